// round 13
// baseline (speedup 1.0000x reference)
#include <cuda_runtime.h>
#include <cuda_fp16.h>
#include <math.h>
#include <stdint.h>

#define Ndim 256
#define Cdim 512
#define Hdim 256
#define NC   (Ndim*Cdim)   // 131072
#define H2   512
#define HU   1024
#define MAXE 520448
#define NB   2033          // MAXE / 256

#if defined(__CUDA_ARCH_FEAT_SM103_ALL) || defined(__CUDA_ARCH_FEAT_SM100_ALL) || \
    (defined(__CUDA_ARCH_SPECIFIC__) && (__CUDA_ARCH_SPECIFIC__ >= 1000))
#define HAS_TC 1
#else
#define HAS_TC 0
#endif

// ---------------- scratch ----------------------------------------------------
__device__ __half g_hin[(size_t)NC*Hdim];
__device__ __half g_PQ [(size_t)NC*HU];
__device__ __half g_Mf [(size_t)MAXE*Hdim];
__device__ __half g_Mr [(size_t)MAXE*Hdim];
__device__ float  g_h2 [(size_t)NC*Hdim];
__device__ __half g_hu [(size_t)NC*Hdim];    // fallback staging only
__device__ __half g_T1 [(size_t)NC*HU];      // fallback staging only
__device__ __half g_wabt[(size_t)HU*Hdim];
__device__ __half g_w2t [(size_t)Hdim*H2];
__device__ __half g_u1t [(size_t)HU*Hdim];
__device__ __half g_u2t [(size_t)Hdim*HU];
__device__ unsigned char g_valid[NC];
__device__ int g_vmode;
__device__ int g_ei[MAXE];
__device__ int g_ej[MAXE];
__device__ int g_posf[4*NC];
__device__ int g_posr[4*NC];
__device__ int g_bcount[2048];
__device__ int g_boffs[2048];
__device__ int g_E;

__device__ __forceinline__ float gelu_exact(float x) {
    return 0.5f * x * (1.0f + erff(x * 0.70710678118654752f));
}
__device__ __forceinline__ void st4h(__half* p, const float* f) {
    uint2 u;
    *(__half2*)&u.x = __float22half2_rn(make_float2(f[0], f[1]));
    *(__half2*)&u.y = __float22half2_rn(make_float2(f[2], f[3]));
    *(uint2*)p = u;
}
__device__ __forceinline__ void ld8h(const __half* p, float* f) {
    uint4 u = *(const uint4*)p;
    float2 a = __half22float2(*(__half2*)&u.x);
    float2 b = __half22float2(*(__half2*)&u.y);
    float2 c = __half22float2(*(__half2*)&u.z);
    float2 d = __half22float2(*(__half2*)&u.w);
    f[0]=a.x; f[1]=a.y; f[2]=b.x; f[3]=b.y; f[4]=c.x; f[5]=c.y; f[6]=d.x; f[7]=d.y;
}
__device__ __forceinline__ void cvt8h(const uint4& u, float* f) {
    float2 a = __half22float2(*(__half2*)&u.x);
    float2 b = __half22float2(*(__half2*)&u.y);
    float2 c = __half22float2(*(__half2*)&u.z);
    float2 d = __half22float2(*(__half2*)&u.w);
    f[0]=a.x; f[1]=a.y; f[2]=b.x; f[3]=b.y; f[4]=c.x; f[5]=c.y; f[6]=d.x; f[7]=d.y;
}
__device__ __forceinline__ uint4 pack8h(const float* f) {
    uint4 u;
    *(__half2*)&u.x = __float22half2_rn(make_float2(f[0], f[1]));
    *(__half2*)&u.y = __float22half2_rn(make_float2(f[2], f[3]));
    *(__half2*)&u.z = __float22half2_rn(make_float2(f[4], f[5]));
    *(__half2*)&u.w = __float22half2_rn(make_float2(f[6], f[7]));
    return u;
}

__device__ __forceinline__ void decode_edge(int g, int& i, int& j, int& oi) {
    int off, Ce, t;
    if (g < 130816)      { off = 1; Ce = 511; t = g;          oi = 0; }
    else if (g < 261376) { off = 2; Ce = 510; t = g - 130816; oi = 1; }
    else if (g < 391424) { off = 4; Ce = 508; t = g - 261376; oi = 2; }
    else                 { off = 8; Ce = 504; t = g - 391424; oi = 3; }
    int n = t / Ce, c = t - n * Ce;
    i = (n << 9) + c; j = i + off;
}

// ---------------- valid dtype detection + normalization ---------------------
__global__ void detect_vmode_kernel(const unsigned char* __restrict__ v) {
    int t = threadIdx.x;
    int nz1 = 0, nz23 = 0;
    #pragma unroll
    for (int k = 0; k < 16; k += 4) {
        int i = t * 16 + k;
        if (v[i+1]) nz1 = 1;
        if (v[i+2] | v[i+3]) nz23 = 1;
    }
    int a1 = __syncthreads_or(nz1);
    int a23 = __syncthreads_or(nz23);
    if (t == 0) g_vmode = a1 ? 0 : (a23 ? 2 : 1);
}
__global__ void conv_valid_kernel(const unsigned char* __restrict__ v) {
    int i = blockIdx.x * 256 + threadIdx.x;
    if (i >= NC) return;
    int mode = g_vmode;
    unsigned char r;
    if (mode == 0)      r = v[i] != 0;
    else if (mode == 1) r = ((const int*)v)[i] != 0;
    else                r = ((const unsigned int*)v)[i] != 0u;
    g_valid[i] = r;
}

__global__ void clear_pos_kernel() {
    int i = blockIdx.x * 256 + threadIdx.x;
    g_posf[i] = -1;
    g_posr[i] = -1;
}

// ---------------- weight transposes (fp16), one launch -----------------------
__global__ void transpose_all_kernel(const float* __restrict__ w1,
                                     const float* __restrict__ w2,
                                     const float* __restrict__ u1,
                                     const float* __restrict__ u2) {
    int idx = blockIdx.x * 256 + threadIdx.x;
    if (idx < 262144) {
        int n = idx >> 8, k = idx & 255;
        float s = (n < 512) ? w1[(size_t)k * 512 + n]
                            : w1[(size_t)(k + 256) * 512 + (n - 512)];
        g_wabt[idx] = __float2half(s);
    } else if (idx < 393216) {
        int t = idx - 262144;
        int n = t >> 9, k = t & 511;
        g_w2t[t] = __float2half(w2[(size_t)k * 256 + n]);
    } else if (idx < 655360) {
        int t = idx - 393216;
        int n = t >> 8, k = t & 255;
        g_u1t[t] = __float2half(u1[(size_t)k * 1024 + n]);
    } else if (idx < 917504) {
        int t = idx - 655360;
        int n = t >> 10, k = t & 1023;
        g_u2t[t] = __float2half(u2[(size_t)k * 256 + n]);
    }
}

// ---------------- LN1 (one-pass stats), warp per row -------------------------
__global__ void ln_kernel(const float* __restrict__ x,
                          const float* __restrict__ w,
                          const float* __restrict__ b,
                          __half* __restrict__ y) {
    int warp = threadIdx.x >> 5, lane = threadIdx.x & 31;
    int row = blockIdx.x * 8 + warp;
    const float* xr = x + (size_t)row * Hdim + lane * 8;
    float4 a = *(const float4*)xr;
    float4 c = *(const float4*)(xr + 4);
    float v[8] = {a.x, a.y, a.z, a.w, c.x, c.y, c.z, c.w};
    float s1 = 0.f, s2 = 0.f;
    #pragma unroll
    for (int k = 0; k < 8; k++) { s1 += v[k]; s2 += v[k]*v[k]; }
    #pragma unroll
    for (int o = 16; o > 0; o >>= 1) {
        s1 += __shfl_xor_sync(0xffffffffu, s1, o);
        s2 += __shfl_xor_sync(0xffffffffu, s2, o);
    }
    float mu = s1 * (1.0f / Hdim);
    float inv = rsqrtf(fmaxf(s2 * (1.0f / Hdim) - mu * mu, 0.f) + 1e-5f);
    const float* wp = w + lane * 8;
    const float* bp = b + lane * 8;
    float o0[4], o1[4];
    #pragma unroll
    for (int k = 0; k < 4; k++) o0[k] = (v[k]   - mu) * inv * wp[k]   + bp[k];
    #pragma unroll
    for (int k = 0; k < 4; k++) o1[k] = (v[4+k] - mu) * inv * wp[4+k] + bp[4+k];
    __half* yr = y + (size_t)row * Hdim + lane * 8;
    st4h(yr, o0); st4h(yr + 4, o1);
}

// ---------------- compaction: count / scan / scatter -------------------------
__global__ void count_kernel() {
    int g = blockIdx.x * 256 + threadIdx.x;
    int i, j, oi; decode_edge(g, i, j, oi);
    int pred = g_valid[i] & g_valid[j];
    unsigned bal = __ballot_sync(0xffffffffu, pred);
    __shared__ int wcnt[8];
    if ((threadIdx.x & 31) == 0) wcnt[threadIdx.x >> 5] = __popc(bal);
    __syncthreads();
    if (threadIdx.x == 0) {
        int s = 0;
        #pragma unroll
        for (int k = 0; k < 8; k++) s += wcnt[k];
        g_bcount[blockIdx.x] = s;
    }
}

__global__ void scan_kernel() {
    __shared__ int part[256];
    int t = threadIdx.x;
    int base = t * 8;
    int loc[8];
    int s = 0;
    #pragma unroll
    for (int k = 0; k < 8; k++) {
        int idx = base + k;
        int v = (idx < NB) ? g_bcount[idx] : 0;
        loc[k] = s; s += v;
    }
    part[t] = s;
    __syncthreads();
    for (int o = 1; o < 256; o <<= 1) {
        int v = part[t];
        int add = (t >= o) ? part[t - o] : 0;
        __syncthreads();
        part[t] = v + add;
        __syncthreads();
    }
    int excl = part[t] - s;
    #pragma unroll
    for (int k = 0; k < 8; k++) {
        int idx = base + k;
        if (idx < 2048) g_boffs[idx] = excl + loc[k];
    }
    __syncthreads();
    if (t == 0) g_E = part[255];
}

__global__ void scatter_kernel() {
    int g = blockIdx.x * 256 + threadIdx.x;
    int lane = threadIdx.x & 31, warp = threadIdx.x >> 5;
    int i, j, oi; decode_edge(g, i, j, oi);
    int pred = g_valid[i] & g_valid[j];
    unsigned bal = __ballot_sync(0xffffffffu, pred);
    __shared__ int wcnt[8], wbase[8];
    if (lane == 0) wcnt[warp] = __popc(bal);
    __syncthreads();
    if (threadIdx.x == 0) {
        int s = 0;
        #pragma unroll
        for (int k = 0; k < 8; k++) { wbase[k] = s; s += wcnt[k]; }
    }
    __syncthreads();
    if (pred) {
        int pos = g_boffs[blockIdx.x] + wbase[warp]
                + __popc(bal & ((1u << lane) - 1u));
        g_ei[pos] = i; g_ej[pos] = j;
        g_posf[oi * NC + i] = pos;
        g_posr[oi * NC + j] = pos;
    }
}

// ============================================================================
// common tcgen05 helpers
// ============================================================================
__device__ __forceinline__ uint32_t smem_u32(const void* p) {
    uint32_t a;
    asm("{ .reg .u64 t; cvta.to.shared.u64 t, %1; cvt.u32.u64 %0, t; }" : "=r"(a) : "l"(p));
    return a;
}
__device__ __forceinline__ void mbar_wait(uint32_t mbar, uint32_t parity) {
    asm volatile(
        "{\n\t.reg .pred P1;\n\t"
        "W_%=:\n\t"
        "mbarrier.try_wait.parity.acquire.cta.shared::cta.b64 P1, [%0], %1, 0x989680;\n\t"
        "@P1 bra.uni D_%=;\n\t"
        "bra.uni W_%=;\n\t"
        "D_%=:\n\t}"
        :: "r"(mbar), "r"(parity) : "memory");
}

#if HAS_TC
__device__ __forceinline__ void mma_f16_ss(uint32_t d_tmem, uint64_t a_desc,
                                           uint64_t b_desc, uint32_t idesc, bool acc) {
    uint32_t en = acc ? 1u : 0u;
    asm volatile(
        "{\n\t.reg .pred p;\n\t"
        "setp.ne.u32 p, %5, 0;\n\t"
        "tcgen05.mma.cta_group::1.kind::f16 [%0], %1, %2, %3, {%4, %4, %4, %4}, p;\n\t"
        "}"
        :: "r"(d_tmem), "l"(a_desc), "l"(b_desc), "r"(idesc), "r"(0u), "r"(en)
        : "memory");
}
#define LDTM_X32(r, addr) \
    asm volatile( \
        "tcgen05.ld.sync.aligned.32x32b.x32.b32 " \
        "{%0, %1, %2, %3, %4, %5, %6, %7, " \
        " %8, %9, %10, %11, %12, %13, %14, %15, " \
        " %16, %17, %18, %19, %20, %21, %22, %23, " \
        " %24, %25, %26, %27, %28, %29, %30, %31}, [%32];" \
        : "=r"((r)[0]),  "=r"((r)[1]),  "=r"((r)[2]),  "=r"((r)[3]), \
          "=r"((r)[4]),  "=r"((r)[5]),  "=r"((r)[6]),  "=r"((r)[7]), \
          "=r"((r)[8]),  "=r"((r)[9]),  "=r"((r)[10]), "=r"((r)[11]), \
          "=r"((r)[12]), "=r"((r)[13]), "=r"((r)[14]), "=r"((r)[15]), \
          "=r"((r)[16]), "=r"((r)[17]), "=r"((r)[18]), "=r"((r)[19]), \
          "=r"((r)[20]), "=r"((r)[21]), "=r"((r)[22]), "=r"((r)[23]), \
          "=r"((r)[24]), "=r"((r)[25]), "=r"((r)[26]), "=r"((r)[27]), \
          "=r"((r)[28]), "=r"((r)[29]), "=r"((r)[30]), "=r"((r)[31]) \
        : "r"(addr))
#endif

static constexpr unsigned long long DESC_BASE =
    (2ull << 61) | (1ull << 46) | (64ull << 32) | (1ull << 16);
#define MMA_IDESC ((1u<<4) | (32u<<17) | (8u<<24))
#define SMEM_DYN  (1024 + 98304 + 64)
#define SMEM_EDGE (1024 + 131072 + 128 + 2048)
#define SMEM_MLP  (1024 + 196608 + 64)

// ============================================================================
// dense tcgen05 f16 GEMM (PQ), 2 CTA/SM, register-prefetched double-buffered.
// ============================================================================
__global__ void __launch_bounds__(256, 2)
mma_gemm_pq(const __half* __restrict__ A, int lda,
            const __half* __restrict__ Bt,
            __half* __restrict__ Cout, int ldc,
            int K) {
    extern __shared__ char dyn[];
    int tid = threadIdx.x;
    int n0 = blockIdx.x * 256;
    int m0 = blockIdx.y * 128;

#if HAS_TC
    uint32_t u0 = smem_u32(dyn);
    uint32_t pad = (1024u - (u0 & 1023u)) & 1023u;
    char* base = dyn + pad;
    uint32_t ub = u0 + pad;

    uint32_t ctrl  = ub + 98304;
    uint32_t mbar0 = ctrl + 8;

    int wid = tid >> 5;
    int lane = tid & 31;

    if (tid == 0) {
        asm volatile("mbarrier.init.shared.b64 [%0], 1;" :: "r"(mbar0)     : "memory");
        asm volatile("mbarrier.init.shared.b64 [%0], 1;" :: "r"(mbar0 + 8) : "memory");
    }
    if (wid == 0) {
        asm volatile("tcgen05.alloc.cta_group::1.sync.aligned.shared::cta.b32 [%0], %1;"
                     :: "r"(ctrl), "r"(256u) : "memory");
        asm volatile("tcgen05.relinquish_alloc_permit.cta_group::1.sync.aligned;");
    }
    __syncthreads();
    uint32_t tmem;
    asm volatile("ld.shared.b32 %0, [%1];" : "=r"(tmem) : "r"(ctrl));

    int rA = tid >> 3, f4 = tid & 7;
    uint32_t soA = (uint32_t)(rA * 128 + f4 * 16);
    soA ^= (soA >> 3) & 0x70u;
    const __half* Abase = A + (size_t)(m0 + rA) * lda + f4 * 8;
    const __half* Bbase = Bt + (size_t)(n0 + rA) * K + f4 * 8;
    size_t strideA = (size_t)32 * lda;
    size_t strideB = (size_t)32 * K;

    uint4 ra[4], rb[8];
    const int NCH = K >> 6;

    #pragma unroll
    for (int i = 0; i < 4; i++) ra[i] = *(const uint4*)(Abase + i * strideA);
    #pragma unroll
    for (int i = 0; i < 8; i++) rb[i] = *(const uint4*)(Bbase + i * strideB);

    #pragma unroll 2
    for (int c = 0; c < NCH; c++) {
        int buf = c & 1;
        if (c >= 2) mbar_wait(mbar0 + 8u * buf, (uint32_t)(((c - 2) >> 1) & 1));
        char* sA = base + buf * 16384;
        char* sB = base + 32768 + buf * 32768;

        #pragma unroll
        for (int i = 0; i < 4; i++)
            *(uint4*)(sA + soA + (uint32_t)(i * 4096)) = ra[i];
        #pragma unroll
        for (int i = 0; i < 8; i++)
            *(uint4*)(sB + soA + (uint32_t)(i * 4096)) = rb[i];

        if (c + 1 < NCH) {
            const __half* An = Abase + (c + 1) * 64;
            const __half* Bn = Bbase + (c + 1) * 64;
            #pragma unroll
            for (int i = 0; i < 4; i++) ra[i] = *(const uint4*)(An + i * strideA);
            #pragma unroll
            for (int i = 0; i < 8; i++) rb[i] = *(const uint4*)(Bn + i * strideB);
        }

        asm volatile("fence.proxy.async.shared::cta;" ::: "memory");
        __syncthreads();

        if (tid == 0) {
            uint32_t aaddr = ub + (uint32_t)(buf * 16384);
            uint32_t baddr = ub + (uint32_t)(32768 + buf * 32768);
            uint64_t adesc = DESC_BASE | (uint64_t)((aaddr >> 4) & 0x3FFFu);
            uint64_t bdesc = DESC_BASE | (uint64_t)((baddr >> 4) & 0x3FFFu);
            #pragma unroll
            for (int s = 0; s < 4; s++) {
                mma_f16_ss(tmem, adesc + 2u * s, bdesc + 2u * s, MMA_IDESC,
                           !(c == 0 && s == 0));
            }
            asm volatile(
                "tcgen05.commit.cta_group::1.mbarrier::arrive::one.shared::cluster.b64 [%0];"
                :: "r"(mbar0 + 8u * buf) : "memory");
        }
    }
    mbar_wait(mbar0 + 8u * ((NCH - 2) & 1), (uint32_t)(((NCH - 2) >> 1) & 1));
    mbar_wait(mbar0 + 8u * ((NCH - 1) & 1), (uint32_t)(((NCH - 1) >> 1) & 1));
    asm volatile("tcgen05.fence::after_thread_sync;" ::: "memory");

    if (wid < 4) {
        int trow = wid * 32 + lane;
        int m = m0 + trow;
        #pragma unroll
        for (int cc = 0; cc < 256; cc += 32) {
            uint32_t r[32];
            LDTM_X32(r, tmem + (uint32_t)cc);
            asm volatile("tcgen05.wait::ld.sync.aligned;" ::: "memory");
            int col0 = n0 + cc;
            #pragma unroll
            for (int j = 0; j < 32; j += 4) {
                float o[4] = {__uint_as_float(r[j]), __uint_as_float(r[j+1]),
                              __uint_as_float(r[j+2]), __uint_as_float(r[j+3])};
                st4h(Cout + (size_t)m * ldc + col0 + j, o);
            }
        }
    }
    __syncthreads();
    if (wid == 0) {
        asm volatile("tcgen05.dealloc.cta_group::1.sync.aligned.b32 %0, %1;"
                     :: "r"(tmem), "r"(256u));
    }

#else  // ---------------- SIMT fallback ----------------------------------------
    float* As = (float*)dyn;
    float* Bs = (float*)(dyn + 8192);

    int tr = tid >> 4, tc = tid & 15;
    int lrow = tid >> 1;
    int lk   = (tid & 1) * 8;

    for (int half = 0; half < 2; half++) {
        int n0h = n0 + half * 128;
        float acc[8][8] = {};
        for (int k0 = 0; k0 < K; k0 += 16) {
            #pragma unroll
            for (int e = 0; e < 8; e++) {
                As[(lk+e)*128 + lrow] = __half2float(A[(size_t)(m0 + lrow) * lda + k0 + lk + e]);
                Bs[(lk+e)*128 + lrow] = __half2float(Bt[(size_t)(n0h + lrow) * K + k0 + lk + e]);
            }
            __syncthreads();
            #pragma unroll
            for (int k = 0; k < 16; k++) {
                float a[8], b[8];
                #pragma unroll
                for (int i = 0; i < 8; i++) a[i] = As[k*128 + tr*8 + i];
                #pragma unroll
                for (int j = 0; j < 8; j++) b[j] = Bs[k*128 + tc*8 + j];
                #pragma unroll
                for (int i = 0; i < 8; i++)
                    #pragma unroll
                    for (int j = 0; j < 8; j++)
                        acc[i][j] += a[i] * b[j];
            }
            __syncthreads();
        }

        int col0 = n0h + tc * 8;
        #pragma unroll
        for (int i = 0; i < 8; i++) {
            int m = m0 + tr * 8 + i;
            for (int j = 0; j < 8; j++)
                Cout[(size_t)m * ldc + col0 + j] = __float2half(acc[i][j]);
        }
        __syncthreads();
    }
#endif
}

// ============================================================================
// fused edge-message kernel (register-prefetched gathers)
// ============================================================================
__global__ void __launch_bounds__(256, 1)
edge_msg_kernel(const float* __restrict__ xyz,
                const float* __restrict__ w1,
                const float* __restrict__ b1,
                const __half* __restrict__ w2t) {
    extern __shared__ char dyn[];
    int tid = threadIdx.x;
    int m0 = blockIdx.x * 128;
    if (m0 >= g_E) return;

#if HAS_TC
    uint32_t u0 = smem_u32(dyn);
    uint32_t pad = (1024u - (u0 & 1023u)) & 1023u;
    char* base = dyn + pad;
    uint32_t ub = u0 + pad;

    uint32_t ctrl  = ub + 131072;
    uint32_t mbar0 = ctrl + 8;
    float* ef = (float*)(base + 131072 + 128);

    int wid = tid >> 5;
    int lane = tid & 31;

    if (tid == 0) {
        asm volatile("mbarrier.init.shared.b64 [%0], 1;" :: "r"(mbar0)     : "memory");
        asm volatile("mbarrier.init.shared.b64 [%0], 1;" :: "r"(mbar0 + 8) : "memory");
    }
    if (wid == 0) {
        asm volatile("tcgen05.alloc.cta_group::1.sync.aligned.shared::cta.b32 [%0], %1;"
                     :: "r"(ctrl), "r"(512u) : "memory");
        asm volatile("tcgen05.relinquish_alloc_permit.cta_group::1.sync.aligned;");
    }
    __syncthreads();
    uint32_t tmem;
    asm volatile("ld.shared.b32 %0, [%1];" : "=r"(tmem) : "r"(ctrl));

    if (tid < 128) {
        int m = m0 + tid;
        int i = g_ei[m], j = g_ej[m];
        float dx = xyz[3*j+0] - xyz[3*i+0];
        float dy = xyz[3*j+1] - xyz[3*i+1];
        float dz = xyz[3*j+2] - xyz[3*i+2];
        float d = fmaxf(sqrtf(dx*dx + dy*dy + dz*dz), 1e-6f);
        float inv = 1.0f / d;
        ef[tid*4+0] = dx*inv; ef[tid*4+1] = dy*inv; ef[tid*4+2] = dz*inv; ef[tid*4+3] = d;
    }
    __syncthreads();

    int r0 = tid >> 3, oct = tid & 7;
    uint32_t so = (uint32_t)(r0 * 128 + oct * 16);
    so ^= (so >> 3) & 0x70u;

    int ei4[4], ej4[4];
    float efr[4][4];
    #pragma unroll
    for (int it = 0; it < 4; it++) {
        int r = r0 + it * 32;
        ei4[it] = g_ei[m0 + r];
        ej4[it] = g_ej[m0 + r];
        efr[it][0] = ef[r*4+0]; efr[it][1] = ef[r*4+1];
        efr[it][2] = ef[r*4+2]; efr[it][3] = ef[r*4+3];
    }

    uint4 gp[16];
    uint4 rbB[8];
    const int NCH = 8;

    {
        int col = oct * 8;
        #pragma unroll
        for (int it = 0; it < 4; it++) {
            gp[it*4+0] = *(const uint4*)(g_PQ + (size_t)ei4[it]*HU + col);
            gp[it*4+1] = *(const uint4*)(g_PQ + (size_t)ei4[it]*HU + 512 + col);
            gp[it*4+2] = *(const uint4*)(g_PQ + (size_t)ej4[it]*HU + col);
            gp[it*4+3] = *(const uint4*)(g_PQ + (size_t)ej4[it]*HU + 512 + col);
        }
        #pragma unroll
        for (int i2 = 0; i2 < 8; i2++) {
            int idx = tid + i2 * 256;
            int rB = idx >> 3, fB = idx & 7;
            rbB[i2] = *(const uint4*)(w2t + (size_t)rB * H2 + fB * 8);
        }
    }

    for (int c = 0; c < NCH; c++) {
        int buf = c & 1;
        if (c >= 2) mbar_wait(mbar0 + 8u * buf, (uint32_t)(((c - 2) >> 1) & 1));
        char* sAf = base + buf * 65536;
        char* sAr = sAf + 16384;
        char* sB  = sAf + 32768;
        int col = (c << 6) + oct * 8;

        #pragma unroll
        for (int i2 = 0; i2 < 8; i2++) {
            int idx = tid + i2 * 256;
            int rB = idx >> 3, fB = idx & 7;
            uint32_t sob = (uint32_t)(rB * 128 + fB * 16);
            sob ^= (sob >> 3) & 0x70u;
            *(uint4*)(sB + sob) = rbB[i2];
        }

        float w0v[8], w1v[8], w2v[8], w3v[8], bbv[8];
        {
            const float* wr0 = w1 + (size_t)(2*Hdim + 0)*H2 + col;
            const float* wr1 = w1 + (size_t)(2*Hdim + 1)*H2 + col;
            const float* wr2 = w1 + (size_t)(2*Hdim + 2)*H2 + col;
            const float* wr3 = w1 + (size_t)(2*Hdim + 3)*H2 + col;
            const float* bbr = b1 + col;
            #pragma unroll
            for (int q = 0; q < 8; q += 4) {
                *(float4*)(w0v+q) = *(const float4*)(wr0+q);
                *(float4*)(w1v+q) = *(const float4*)(wr1+q);
                *(float4*)(w2v+q) = *(const float4*)(wr2+q);
                *(float4*)(w3v+q) = *(const float4*)(wr3+q);
                *(float4*)(bbv+q) = *(const float4*)(bbr+q);
            }
        }

        #pragma unroll
        for (int it = 0; it < 4; it++) {
            float pi[8], qi[8], pj[8], qj[8];
            cvt8h(gp[it*4+0], pi);
            cvt8h(gp[it*4+1], qi);
            cvt8h(gp[it*4+2], pj);
            cvt8h(gp[it*4+3], qj);
            float e0 = efr[it][0], e1 = efr[it][1], e2 = efr[it][2], e3 = efr[it][3];
            float rf[8], rr[8];
            #pragma unroll
            for (int q = 0; q < 8; q++) {
                float eu = e0*w0v[q] + e1*w1v[q] + e2*w2v[q];
                float ed = e3*w3v[q] + bbv[q];
                rf[q] = gelu_exact(pi[q] + qj[q] + eu + ed);
                rr[q] = gelu_exact(pj[q] + qi[q] - eu + ed);
            }
            *(uint4*)(sAf + so + (uint32_t)(it * 4096)) = pack8h(rf);
            *(uint4*)(sAr + so + (uint32_t)(it * 4096)) = pack8h(rr);
        }

        if (c + 1 < NCH) {
            int coln = ((c + 1) << 6) + oct * 8;
            #pragma unroll
            for (int it = 0; it < 4; it++) {
                gp[it*4+0] = *(const uint4*)(g_PQ + (size_t)ei4[it]*HU + coln);
                gp[it*4+1] = *(const uint4*)(g_PQ + (size_t)ei4[it]*HU + 512 + coln);
                gp[it*4+2] = *(const uint4*)(g_PQ + (size_t)ej4[it]*HU + coln);
                gp[it*4+3] = *(const uint4*)(g_PQ + (size_t)ej4[it]*HU + 512 + coln);
            }
            int k0n = (c + 1) << 6;
            #pragma unroll
            for (int i2 = 0; i2 < 8; i2++) {
                int idx = tid + i2 * 256;
                int rB = idx >> 3, fB = idx & 7;
                rbB[i2] = *(const uint4*)(w2t + (size_t)rB * H2 + k0n + fB * 8);
            }
        }

        asm volatile("fence.proxy.async.shared::cta;" ::: "memory");
        __syncthreads();

        if (tid == 0) {
            uint32_t afaddr = ub + (uint32_t)(buf * 65536);
            uint32_t araddr = afaddr + 16384u;
            uint32_t baddr  = afaddr + 32768u;
            uint64_t adescF = DESC_BASE | (uint64_t)((afaddr >> 4) & 0x3FFFu);
            uint64_t adescR = DESC_BASE | (uint64_t)((araddr >> 4) & 0x3FFFu);
            uint64_t bdesc  = DESC_BASE | (uint64_t)((baddr  >> 4) & 0x3FFFu);
            #pragma unroll
            for (int s = 0; s < 4; s++) {
                bool acc = !(c == 0 && s == 0);
                mma_f16_ss(tmem,        adescF + 2u*s, bdesc + 2u*s, MMA_IDESC, acc);
                mma_f16_ss(tmem + 256u, adescR + 2u*s, bdesc + 2u*s, MMA_IDESC, acc);
            }
            asm volatile(
                "tcgen05.commit.cta_group::1.mbarrier::arrive::one.shared::cluster.b64 [%0];"
                :: "r"(mbar0 + 8u * buf) : "memory");
        }
    }
    mbar_wait(mbar0 + 8u * ((NCH - 2) & 1), (uint32_t)(((NCH - 2) >> 1) & 1));
    mbar_wait(mbar0 + 8u * ((NCH - 1) & 1), (uint32_t)(((NCH - 1) >> 1) & 1));
    asm volatile("tcgen05.fence::after_thread_sync;" ::: "memory");

    {
        int dir = wid >> 2;
        int wd  = wid & 3;
        int trow = wd * 32 + lane;
        int m = m0 + trow;
        __half* M = dir ? g_Mr : g_Mf;
        uint32_t dbase = tmem + (uint32_t)(dir * 256);
        #pragma unroll
        for (int cc = 0; cc < 256; cc += 32) {
            uint32_t r[32];
            LDTM_X32(r, dbase + (uint32_t)cc);
            asm volatile("tcgen05.wait::ld.sync.aligned;" ::: "memory");
            #pragma unroll
            for (int q = 0; q < 32; q += 4) {
                float o[4] = {__uint_as_float(r[q]),   __uint_as_float(r[q+1]),
                              __uint_as_float(r[q+2]), __uint_as_float(r[q+3])};
                st4h(M + (size_t)m * Hdim + cc + q, o);
            }
        }
    }
    __syncthreads();
    if (wid == 0) {
        asm volatile("tcgen05.dealloc.cta_group::1.sync.aligned.b32 %0, %1;"
                     :: "r"(tmem), "r"(512u));
    }

#else  // -------- SIMT fallback ------------------------------------------------
    float* As = (float*)dyn;
    float* Bs = (float*)(dyn + 8192);
    float* ef = (float*)(dyn + 16384);

    if (tid < 128) {
        int m = m0 + tid;
        int i = g_ei[m], j = g_ej[m];
        float dx = xyz[3*j+0] - xyz[3*i+0];
        float dy = xyz[3*j+1] - xyz[3*i+1];
        float dz = xyz[3*j+2] - xyz[3*i+2];
        float d = fmaxf(sqrtf(dx*dx + dy*dy + dz*dz), 1e-6f);
        float inv = 1.0f / d;
        ef[tid*4+0] = dx*inv; ef[tid*4+1] = dy*inv; ef[tid*4+2] = dz*inv; ef[tid*4+3] = d;
    }
    __syncthreads();

    int tr = tid >> 4, tc = tid & 15;
    for (int dir = 0; dir < 2; dir++) {
        for (int half = 0; half < 2; half++) {
            int n0h = half * 128;
            float acc[8][8] = {};
            for (int k0 = 0; k0 < H2; k0 += 16) {
                #pragma unroll
                for (int e = 0; e < 8; e++) {
                    int idx = tid * 8 + e;
                    int kk = idx >> 7, rr2 = idx & 127;
                    int m = m0 + rr2;
                    int i = g_ei[m], j = g_ej[m];
                    int colk = k0 + kk;
                    float e0 = ef[rr2*4], e1 = ef[rr2*4+1], e2 = ef[rr2*4+2], e3 = ef[rr2*4+3];
                    float eu = e0*w1[(size_t)(2*Hdim+0)*H2+colk]
                             + e1*w1[(size_t)(2*Hdim+1)*H2+colk]
                             + e2*w1[(size_t)(2*Hdim+2)*H2+colk];
                    float ed = e3*w1[(size_t)(2*Hdim+3)*H2+colk] + b1[colk];
                    float pv, qv;
                    if (dir == 0) {
                        pv = __half2float(g_PQ[(size_t)i*HU + colk]);
                        qv = __half2float(g_PQ[(size_t)j*HU + 512 + colk]);
                        As[kk*128 + rr2] = gelu_exact(pv + qv + eu + ed);
                    } else {
                        pv = __half2float(g_PQ[(size_t)j*HU + colk]);
                        qv = __half2float(g_PQ[(size_t)i*HU + 512 + colk]);
                        As[kk*128 + rr2] = gelu_exact(pv + qv - eu + ed);
                    }
                    Bs[kk*128 + rr2] = __half2float(w2t[(size_t)(n0h + rr2) * H2 + colk]);
                }
                __syncthreads();
                #pragma unroll
                for (int k = 0; k < 16; k++) {
                    float a[8], b[8];
                    #pragma unroll
                    for (int i2 = 0; i2 < 8; i2++) a[i2] = As[k*128 + tr*8 + i2];
                    #pragma unroll
                    for (int j2 = 0; j2 < 8; j2++) b[j2] = Bs[k*128 + tc*8 + j2];
                    #pragma unroll
                    for (int i2 = 0; i2 < 8; i2++)
                        #pragma unroll
                        for (int j2 = 0; j2 < 8; j2++)
                            acc[i2][j2] += a[i2] * b[j2];
                }
                __syncthreads();
            }
            __half* M = dir ? g_Mr : g_Mf;
            int col0 = n0h + tc * 8;
            #pragma unroll
            for (int i2 = 0; i2 < 8; i2++) {
                int m = m0 + tr * 8 + i2;
                for (int j2 = 0; j2 < 8; j2++)
                    M[(size_t)m * Hdim + col0 + j2] = __float2half(acc[i2][j2]);
            }
            __syncthreads();
        }
    }
#endif
}

// ============================================================================
// fused gather + h2 + LN + update-MLP
// ============================================================================
__global__ void __launch_bounds__(256, 1)
gather_mlp_kernel(const float* __restrict__ h,
                  const float* __restrict__ b2,
                  const float* __restrict__ lnw,
                  const float* __restrict__ lnb,
                  const __half* __restrict__ u1t,
                  const __half* __restrict__ u2t,
                  const float* __restrict__ bu1,
                  const float* __restrict__ bu2,
                  float* __restrict__ out) {
    extern __shared__ char dyn[];
    int tid = threadIdx.x;
    int m0 = blockIdx.x * 128;
    int warp = tid >> 5, lane = tid & 31;

#if HAS_TC
    uint32_t u0 = smem_u32(dyn);
    uint32_t pad = (1024u - (u0 & 1023u)) & 1023u;
    char* base = dyn + pad;
    uint32_t ub = u0 + pad;

    uint32_t ctrl  = ub + 196608;
    uint32_t mbar0 = ctrl + 8;

    if (tid == 0) {
        asm volatile("mbarrier.init.shared.b64 [%0], 1;" :: "r"(mbar0)     : "memory");
        asm volatile("mbarrier.init.shared.b64 [%0], 1;" :: "r"(mbar0 + 8) : "memory");
    }
    if (warp == 0) {
        asm volatile("tcgen05.alloc.cta_group::1.sync.aligned.shared::cta.b32 [%0], %1;"
                     :: "r"(ctrl), "r"(512u) : "memory");
        asm volatile("tcgen05.relinquish_alloc_permit.cta_group::1.sync.aligned;");
    }
    __syncthreads();
    uint32_t tmem;
    asm volatile("ld.shared.b32 %0, [%1];" : "=r"(tmem) : "r"(ctrl));

    // prologue: gather + h2 + LN -> sHu, warp per row
    {
        const float* wp = lnw + lane * 8;
        const float* bp = lnb + lane * 8;
        const float* b2p = b2 + lane * 8;
        float wv[8], bv2[8], b2v[8];
        #pragma unroll
        for (int k = 0; k < 8; k += 4) {
            *(float4*)(wv+k)  = *(const float4*)(wp+k);
            *(float4*)(bv2+k) = *(const float4*)(bp+k);
            *(float4*)(b2v+k) = *(const float4*)(b2p+k);
        }
        for (int it = 0; it < 16; it++) {
            int rl = it * 8 + warp;
            int row = m0 + rl;

            int p = -1;
            if (lane < 4)      p = g_posf[lane * NC + row];
            else if (lane < 8) p = g_posr[(lane - 4) * NC + row];

            float acc[8] = {};
            int cnt = 0;
            #pragma unroll
            for (int s = 0; s < 8; s++) {
                int ps = __shfl_sync(0xffffffffu, p, s);
                if (ps >= 0) {
                    cnt++;
                    const __half* Mrow = (s < 4 ? g_Mf : g_Mr)
                                       + (size_t)ps * Hdim + lane * 8;
                    float f[8];
                    ld8h(Mrow, f);
                    #pragma unroll
                    for (int k = 0; k < 8; k++) acc[k] += f[k];
                }
            }
            float cf = (float)cnt;
            const float* hr = h + (size_t)row * Hdim + lane * 8;
            float4 ha = *(const float4*)hr;
            float4 hc = *(const float4*)(hr + 4);
            float hv[8] = {ha.x, ha.y, ha.z, ha.w, hc.x, hc.y, hc.z, hc.w};
            float v[8];
            #pragma unroll
            for (int k = 0; k < 8; k++) v[k] = hv[k] + acc[k] + cf * b2v[k];

            float* h2r = g_h2 + (size_t)row * Hdim + lane * 8;
            float4 o;
            o.x = v[0]; o.y = v[1]; o.z = v[2]; o.w = v[3];
            *(float4*)h2r = o;
            o.x = v[4]; o.y = v[5]; o.z = v[6]; o.w = v[7];
            *(float4*)(h2r + 4) = o;

            float s1 = 0.f, s2 = 0.f;
            #pragma unroll
            for (int k = 0; k < 8; k++) { s1 += v[k]; s2 += v[k]*v[k]; }
            #pragma unroll
            for (int ofs = 16; ofs > 0; ofs >>= 1) {
                s1 += __shfl_xor_sync(0xffffffffu, s1, ofs);
                s2 += __shfl_xor_sync(0xffffffffu, s2, ofs);
            }
            float mu = s1 * (1.0f / Hdim);
            float inv = rsqrtf(fmaxf(s2 * (1.0f / Hdim) - mu * mu, 0.f) + 1e-5f);
            float o8[8];
            #pragma unroll
            for (int k = 0; k < 8; k++) o8[k] = (v[k] - mu) * inv * wv[k] + bv2[k];
            uint32_t sob = (uint32_t)(rl * 128 + (lane & 7) * 16);
            sob ^= (sob >> 3) & 0x70u;
            *(uint4*)(base + (lane >> 3) * 16384 + sob) = pack8h(o8);
        }
    }
    __syncthreads();

    int rB = tid >> 3, fB = tid & 7;
    int trow = (warp & 3) * 32 + lane;
    int colhalf = (warp >> 2) * 128;

    uint32_t D2 = tmem;
    uint32_t D1 = tmem + 256u;

    int cidx = 0;
    for (int p = 0; p < 4; p++) {
        for (int c = 0; c < 4; c++) {
            int buf = cidx & 1;
            if (cidx >= 2) mbar_wait(mbar0 + 8u*buf, (uint32_t)(((cidx-2) >> 1) & 1));
            char* sB = base + 131072 + buf * 32768;
            #pragma unroll
            for (int i2 = 0; i2 < 8; i2++) {
                int rr = rB + i2 * 32;
                uint4 bv = *(const uint4*)(u1t + (size_t)(p*256 + rr) * Hdim + c*64 + fB*8);
                uint32_t sob = (uint32_t)(rr * 128 + fB * 16);
                sob ^= (sob >> 3) & 0x70u;
                *(uint4*)(sB + sob) = bv;
            }
            asm volatile("fence.proxy.async.shared::cta;" ::: "memory");
            __syncthreads();
            if (tid == 0) {
                uint32_t aaddr = ub + (uint32_t)(c * 16384);
                uint32_t baddr = ub + (uint32_t)(131072 + buf * 32768);
                uint64_t adesc = DESC_BASE | (uint64_t)((aaddr >> 4) & 0x3FFFu);
                uint64_t bdesc = DESC_BASE | (uint64_t)((baddr >> 4) & 0x3FFFu);
                #pragma unroll
                for (int s = 0; s < 4; s++)
                    mma_f16_ss(D1, adesc + 2u*s, bdesc + 2u*s, MMA_IDESC, !(c == 0 && s == 0));
                asm volatile(
                    "tcgen05.commit.cta_group::1.mbarrier::arrive::one.shared::cluster.b64 [%0];"
                    :: "r"(mbar0 + 8u*buf) : "memory");
            }
            cidx++;
        }
        mbar_wait(mbar0 + 8u*((cidx-1)&1), (uint32_t)(((cidx-1) >> 1) & 1));
        mbar_wait(mbar0 + 8u*((cidx-2)&1), (uint32_t)(((cidx-2) >> 1) & 1));
        asm volatile("tcgen05.fence::after_thread_sync;" ::: "memory");

        #pragma unroll
        for (int cc2 = 0; cc2 < 4; cc2++) {
            int col = colhalf + cc2 * 32;
            uint32_t r[32];
            LDTM_X32(r, D1 + (uint32_t)col);
            asm volatile("tcgen05.wait::ld.sync.aligned;" ::: "memory");
            #pragma unroll
            for (int q = 0; q < 32; q += 8) {
                int ck = col + q;
                float o[8];
                #pragma unroll
                for (int e = 0; e < 8; e++)
                    o[e] = gelu_exact(__uint_as_float(r[q+e]) + __ldg(&bu1[p*256 + ck + e]));
                uint32_t sob = (uint32_t)(trow * 128 + ((ck >> 3) & 7) * 16);
                sob ^= (sob >> 3) & 0x70u;
                *(uint4*)(base + 65536 + (ck >> 6) * 16384 + sob) = pack8h(o);
            }
        }

        for (int c = 0; c < 4; c++) {
            int buf = cidx & 1;
            mbar_wait(mbar0 + 8u*buf, (uint32_t)(((cidx-2) >> 1) & 1));
            char* sB = base + 131072 + buf * 32768;
            #pragma unroll
            for (int i2 = 0; i2 < 8; i2++) {
                int rr = rB + i2 * 32;
                uint4 bv = *(const uint4*)(u2t + (size_t)rr * HU + p*256 + c*64 + fB*8);
                uint32_t sob = (uint32_t)(rr * 128 + fB * 16);
                sob ^= (sob >> 3) & 0x70u;
                *(uint4*)(sB + sob) = bv;
            }
            asm volatile("fence.proxy.async.shared::cta;" ::: "memory");
            __syncthreads();
            if (tid == 0) {
                uint32_t aaddr = ub + (uint32_t)(65536 + c * 16384);
                uint32_t baddr = ub + (uint32_t)(131072 + buf * 32768);
                uint64_t adesc = DESC_BASE | (uint64_t)((aaddr >> 4) & 0x3FFFu);
                uint64_t bdesc = DESC_BASE | (uint64_t)((baddr >> 4) & 0x3FFFu);
                #pragma unroll
                for (int s = 0; s < 4; s++)
                    mma_f16_ss(D2, adesc + 2u*s, bdesc + 2u*s, MMA_IDESC,
                               !(p == 0 && c == 0 && s == 0));
                asm volatile(
                    "tcgen05.commit.cta_group::1.mbarrier::arrive::one.shared::cluster.b64 [%0];"
                    :: "r"(mbar0 + 8u*buf) : "memory");
            }
            cidx++;
        }
    }
    mbar_wait(mbar0 + 8u*((cidx-1)&1), (uint32_t)(((cidx-1) >> 1) & 1));
    mbar_wait(mbar0 + 8u*((cidx-2)&1), (uint32_t)(((cidx-2) >> 1) & 1));
    asm volatile("tcgen05.fence::after_thread_sync;" ::: "memory");

    {
        int m = m0 + trow;
        float vf = g_valid[m] ? 1.0f : 0.0f;
        #pragma unroll
        for (int cc2 = 0; cc2 < 4; cc2++) {
            int col = colhalf + cc2 * 32;
            uint32_t r[32];
            LDTM_X32(r, D2 + (uint32_t)col);
            asm volatile("tcgen05.wait::ld.sync.aligned;" ::: "memory");
            const float* a2 = g_h2 + (size_t)m * Hdim + col;
            #pragma unroll
            for (int q = 0; q < 32; q += 4) {
                float4 av = *(const float4*)(a2 + q);
                float4 o;
                o.x = (av.x + __uint_as_float(r[q])   + __ldg(&bu2[col+q]))   * vf;
                o.y = (av.y + __uint_as_float(r[q+1]) + __ldg(&bu2[col+q+1])) * vf;
                o.z = (av.z + __uint_as_float(r[q+2]) + __ldg(&bu2[col+q+2])) * vf;
                o.w = (av.w + __uint_as_float(r[q+3]) + __ldg(&bu2[col+q+3])) * vf;
                *(float4*)(out + (size_t)m * Hdim + col + q) = o;
            }
        }
    }
    __syncthreads();
    if (warp == 0) {
        asm volatile("tcgen05.dealloc.cta_group::1.sync.aligned.b32 %0, %1;"
                     :: "r"(tmem), "r"(512u));
    }

#else  // -------- SIMT fallback: gather+LN -> g_hu, then two naive GEMMs -------
    float* As = (float*)dyn;
    float* Bs = (float*)(dyn + 8192);

    for (int it = 0; it < 16; it++) {
        int rl = it * 8 + warp;
        int row = m0 + rl;
        int p = -1;
        if (lane < 4)      p = g_posf[lane * NC + row];
        else if (lane < 8) p = g_posr[(lane - 4) * NC + row];
        float acc[8] = {};
        int cnt = 0;
        #pragma unroll
        for (int s = 0; s < 8; s++) {
            int ps = __shfl_sync(0xffffffffu, p, s);
            if (ps >= 0) {
                cnt++;
                const __half* Mrow = (s < 4 ? g_Mf : g_Mr) + (size_t)ps * Hdim + lane * 8;
                float f[8];
                ld8h(Mrow, f);
                #pragma unroll
                for (int k = 0; k < 8; k++) acc[k] += f[k];
            }
        }
        float cf = (float)cnt;
        const float* hr = h + (size_t)row * Hdim + lane * 8;
        float4 ha = *(const float4*)hr;
        float4 hc = *(const float4*)(hr + 4);
        float hv[8] = {ha.x, ha.y, ha.z, ha.w, hc.x, hc.y, hc.z, hc.w};
        float v[8];
        #pragma unroll
        for (int k = 0; k < 8; k++) v[k] = hv[k] + acc[k] + cf * b2[lane*8+k];
        float* h2r = g_h2 + (size_t)row * Hdim + lane * 8;
        float4 o;
        o.x = v[0]; o.y = v[1]; o.z = v[2]; o.w = v[3];
        *(float4*)h2r = o;
        o.x = v[4]; o.y = v[5]; o.z = v[6]; o.w = v[7];
        *(float4*)(h2r + 4) = o;
        float s1 = 0.f, s2 = 0.f;
        #pragma unroll
        for (int k = 0; k < 8; k++) { s1 += v[k]; s2 += v[k]*v[k]; }
        #pragma unroll
        for (int ofs = 16; ofs > 0; ofs >>= 1) {
            s1 += __shfl_xor_sync(0xffffffffu, s1, ofs);
            s2 += __shfl_xor_sync(0xffffffffu, s2, ofs);
        }
        float mu = s1 * (1.0f / Hdim);
        float inv = rsqrtf(fmaxf(s2 * (1.0f / Hdim) - mu * mu, 0.f) + 1e-5f);
        float o8[8];
        #pragma unroll
        for (int k = 0; k < 8; k++)
            o8[k] = (v[k] - mu) * inv * lnw[lane*8+k] + lnb[lane*8+k];
        st4h(g_hu + (size_t)row * Hdim + lane * 8, o8);
        st4h(g_hu + (size_t)row * Hdim + lane * 8 + 4, o8 + 4);
    }
    __syncthreads();

    int tr = tid >> 4, tc = tid & 15;
    int lrow = tid >> 1;
    int lk   = (tid & 1) * 8;

    for (int half = 0; half < 8; half++) {
        int n0h = half * 128;
        float acc[8][8] = {};
        for (int k0 = 0; k0 < Hdim; k0 += 16) {
            #pragma unroll
            for (int e = 0; e < 8; e++) {
                As[(lk+e)*128 + lrow] = __half2float(g_hu[(size_t)(m0 + lrow) * Hdim + k0 + lk + e]);
                Bs[(lk+e)*128 + lrow] = __half2float(u1t[(size_t)(n0h + lrow) * Hdim + k0 + lk + e]);
            }
            __syncthreads();
            #pragma unroll
            for (int k = 0; k < 16; k++) {
                float a[8], b[8];
                #pragma unroll
                for (int i2 = 0; i2 < 8; i2++) a[i2] = As[k*128 + tr*8 + i2];
                #pragma unroll
                for (int j2 = 0; j2 < 8; j2++) b[j2] = Bs[k*128 + tc*8 + j2];
                #pragma unroll
                for (int i2 = 0; i2 < 8; i2++)
                    #pragma unroll
                    for (int j2 = 0; j2 < 8; j2++)
                        acc[i2][j2] += a[i2] * b[j2];
            }
            __syncthreads();
        }
        int col0 = n0h + tc * 8;
        #pragma unroll
        for (int i2 = 0; i2 < 8; i2++) {
            int m = m0 + tr * 8 + i2;
            for (int j2 = 0; j2 < 8; j2++)
                g_T1[(size_t)m * HU + col0 + j2] =
                    __float2half(gelu_exact(acc[i2][j2] + bu1[col0 + j2]));
        }
        __syncthreads();
    }

    for (int half = 0; half < 2; half++) {
        int n0h = half * 128;
        float acc[8][8] = {};
        for (int k0 = 0; k0 < HU; k0 += 16) {
            #pragma unroll
            for (int e = 0; e < 8; e++) {
                As[(lk+e)*128 + lrow] = __half2float(g_T1[(size_t)(m0 + lrow) * HU + k0 + lk + e]);
                Bs[(lk+e)*128 + lrow] = __half2float(u2t[(size_t)(n0h + lrow) * HU + k0 + lk + e]);
            }
            __syncthreads();
            #pragma unroll
            for (int k = 0; k < 16; k++) {
                float a[8], b[8];
                #pragma unroll
                for (int i2 = 0; i2 < 8; i2++) a[i2] = As[k*128 + tr*8 + i2];
                #pragma unroll
                for (int j2 = 0; j2 < 8; j2++) b[j2] = Bs[k*128 + tc*8 + j2];
                #pragma unroll
                for (int i2 = 0; i2 < 8; i2++)
                    #pragma unroll
                    for (int j2 = 0; j2 < 8; j2++)
                        acc[i2][j2] += a[i2] * b[j2];
            }
            __syncthreads();
        }
        int col0 = n0h + tc * 8;
        #pragma unroll
        for (int i2 = 0; i2 < 8; i2++) {
            int m = m0 + tr * 8 + i2;
            float vf = g_valid[m] ? 1.0f : 0.0f;
            for (int j2 = 0; j2 < 8; j2++)
                out[(size_t)m * Hdim + col0 + j2] =
                    (g_h2[(size_t)m * Hdim + col0 + j2] + acc[i2][j2] + bu2[col0 + j2]) * vf;
        }
        __syncthreads();
    }
#endif
}

// ---------------- launch -----------------------------------------------------
extern "C" void kernel_launch(void* const* d_in, const int* in_sizes, int n_in,
                              void* d_out, int out_size) {
    const float*         h      = (const float*)d_in[0];
    const float*         xyz    = (const float*)d_in[1];
    const unsigned char* validb = (const unsigned char*)d_in[2];
    const float*         ln_n_w = (const float*)d_in[3];
    const float*         ln_n_b = (const float*)d_in[4];
    const float*         w1     = (const float*)d_in[5];
    const float*         b1     = (const float*)d_in[6];
    const float*         w2     = (const float*)d_in[7];
    const float*         b2     = (const float*)d_in[8];
    const float*         ln_u_w = (const float*)d_in[9];
    const float*         ln_u_b = (const float*)d_in[10];
    const float*         u1     = (const float*)d_in[11];
    const float*         bu1    = (const float*)d_in[12];
    const float*         u2     = (const float*)d_in[13];
    const float*         bu2    = (const float*)d_in[14];
    float* out = (float*)d_out;

    __half *pHin, *pPQ, *pWabt, *pW2t, *pU1t, *pU2t;
    cudaGetSymbolAddress((void**)&pHin, g_hin);
    cudaGetSymbolAddress((void**)&pPQ,  g_PQ);
    cudaGetSymbolAddress((void**)&pWabt, g_wabt);
    cudaGetSymbolAddress((void**)&pW2t,  g_w2t);
    cudaGetSymbolAddress((void**)&pU1t,  g_u1t);
    cudaGetSymbolAddress((void**)&pU2t,  g_u2t);

    cudaFuncSetAttribute(mma_gemm_pq, cudaFuncAttributeMaxDynamicSharedMemorySize, SMEM_DYN);
    cudaFuncSetAttribute(edge_msg_kernel, cudaFuncAttributeMaxDynamicSharedMemorySize, SMEM_EDGE);
    cudaFuncSetAttribute(gather_mlp_kernel, cudaFuncAttributeMaxDynamicSharedMemorySize, SMEM_MLP);

    detect_vmode_kernel<<<1, 256>>>(validb);
    conv_valid_kernel<<<(NC + 255) / 256, 256>>>(validb);
    clear_pos_kernel<<<4*NC/256, 256>>>();
    transpose_all_kernel<<<917504/256, 256>>>(w1, w2, u1, u2);
    ln_kernel<<<NC/8, 256>>>(h, ln_n_w, ln_n_b, pHin);
    count_kernel<<<NB, 256>>>();

    // PQ = h_in @ [W1a | W1b]  (2 CTA/SM pipelined GEMM)
    mma_gemm_pq<<<dim3(4, NC/128), 256, SMEM_DYN>>>(pHin, Hdim, pWabt, pPQ, HU, Hdim);

    scan_kernel<<<1, 256>>>();
    scatter_kernel<<<NB, 256>>>();

    edge_msg_kernel<<<MAXE/128, 256, SMEM_EDGE>>>(xyz, w1, b1, pW2t);

    // gather + h2 + LN + update-MLP fused
    gather_mlp_kernel<<<NC/128, 256, SMEM_MLP>>>(h, b2, ln_u_w, ln_u_b,
                                                 pU1t, pU2t, bu1, bu2, out);
    (void)in_sizes; (void)n_in; (void)out_size;
}

// round 14
// speedup vs baseline: 1.0713x; 1.0713x over previous
#include <cuda_runtime.h>
#include <cuda_fp16.h>
#include <math.h>
#include <stdint.h>

#define Ndim 256
#define Cdim 512
#define Hdim 256
#define NC   (Ndim*Cdim)   // 131072
#define H2   512
#define HU   1024
#define MAXE 520448
#define NB   2033          // MAXE / 256

#if defined(__CUDA_ARCH_FEAT_SM103_ALL) || defined(__CUDA_ARCH_FEAT_SM100_ALL) || \
    (defined(__CUDA_ARCH_SPECIFIC__) && (__CUDA_ARCH_SPECIFIC__ >= 1000))
#define HAS_TC 1
#else
#define HAS_TC 0
#endif

// ---------------- scratch ----------------------------------------------------
__device__ __half g_hin[(size_t)NC*Hdim];    // fallback staging only
__device__ __half g_PQ [(size_t)NC*HU];
__device__ __half g_Mf [(size_t)MAXE*Hdim];
__device__ __half g_Mr [(size_t)MAXE*Hdim];
__device__ float  g_h2 [(size_t)NC*Hdim];
__device__ __half g_hu [(size_t)NC*Hdim];
__device__ __half g_T1 [(size_t)NC*HU];      // fallback staging only
__device__ __half g_wabt[(size_t)HU*Hdim];
__device__ __half g_w2t [(size_t)Hdim*H2];
__device__ __half g_u1t [(size_t)HU*Hdim];
__device__ __half g_u2t [(size_t)Hdim*HU];
__device__ unsigned char g_valid[NC];
__device__ int g_vmode;
__device__ int g_ei[MAXE];
__device__ int g_ej[MAXE];
__device__ int g_posf[4*NC];
__device__ int g_posr[4*NC];
__device__ int g_bcount[2048];
__device__ int g_boffs[2048];
__device__ int g_E;

__device__ __forceinline__ float gelu_exact(float x) {
    return 0.5f * x * (1.0f + erff(x * 0.70710678118654752f));
}
__device__ __forceinline__ void st4h(__half* p, const float* f) {
    uint2 u;
    *(__half2*)&u.x = __float22half2_rn(make_float2(f[0], f[1]));
    *(__half2*)&u.y = __float22half2_rn(make_float2(f[2], f[3]));
    *(uint2*)p = u;
}
__device__ __forceinline__ void ld8h(const __half* p, float* f) {
    uint4 u = *(const uint4*)p;
    float2 a = __half22float2(*(__half2*)&u.x);
    float2 b = __half22float2(*(__half2*)&u.y);
    float2 c = __half22float2(*(__half2*)&u.z);
    float2 d = __half22float2(*(__half2*)&u.w);
    f[0]=a.x; f[1]=a.y; f[2]=b.x; f[3]=b.y; f[4]=c.x; f[5]=c.y; f[6]=d.x; f[7]=d.y;
}
__device__ __forceinline__ void cvt8h(const uint4& u, float* f) {
    float2 a = __half22float2(*(__half2*)&u.x);
    float2 b = __half22float2(*(__half2*)&u.y);
    float2 c = __half22float2(*(__half2*)&u.z);
    float2 d = __half22float2(*(__half2*)&u.w);
    f[0]=a.x; f[1]=a.y; f[2]=b.x; f[3]=b.y; f[4]=c.x; f[5]=c.y; f[6]=d.x; f[7]=d.y;
}
__device__ __forceinline__ uint4 pack8h(const float* f) {
    uint4 u;
    *(__half2*)&u.x = __float22half2_rn(make_float2(f[0], f[1]));
    *(__half2*)&u.y = __float22half2_rn(make_float2(f[2], f[3]));
    *(__half2*)&u.z = __float22half2_rn(make_float2(f[4], f[5]));
    *(__half2*)&u.w = __float22half2_rn(make_float2(f[6], f[7]));
    return u;
}

__device__ __forceinline__ void decode_edge(int g, int& i, int& j, int& oi) {
    int off, Ce, t;
    if (g < 130816)      { off = 1; Ce = 511; t = g;          oi = 0; }
    else if (g < 261376) { off = 2; Ce = 510; t = g - 130816; oi = 1; }
    else if (g < 391424) { off = 4; Ce = 508; t = g - 261376; oi = 2; }
    else                 { off = 8; Ce = 504; t = g - 391424; oi = 3; }
    int n = t / Ce, c = t - n * Ce;
    i = (n << 9) + c; j = i + off;
}

// ---------------- valid dtype detection + normalization ---------------------
__global__ void detect_vmode_kernel(const unsigned char* __restrict__ v) {
    int t = threadIdx.x;
    int nz1 = 0, nz23 = 0;
    #pragma unroll
    for (int k = 0; k < 16; k += 4) {
        int i = t * 16 + k;
        if (v[i+1]) nz1 = 1;
        if (v[i+2] | v[i+3]) nz23 = 1;
    }
    int a1 = __syncthreads_or(nz1);
    int a23 = __syncthreads_or(nz23);
    if (t == 0) g_vmode = a1 ? 0 : (a23 ? 2 : 1);
}
__global__ void conv_valid_kernel(const unsigned char* __restrict__ v) {
    int i = blockIdx.x * 256 + threadIdx.x;
    if (i >= NC) return;
    int mode = g_vmode;
    unsigned char r;
    if (mode == 0)      r = v[i] != 0;
    else if (mode == 1) r = ((const int*)v)[i] != 0;
    else                r = ((const unsigned int*)v)[i] != 0u;
    g_valid[i] = r;
}

__global__ void clear_pos_kernel() {
    int i = blockIdx.x * 256 + threadIdx.x;
    g_posf[i] = -1;
    g_posr[i] = -1;
}

// ---------------- weight transposes (fp16), one launch -----------------------
__global__ void transpose_all_kernel(const float* __restrict__ w1,
                                     const float* __restrict__ w2,
                                     const float* __restrict__ u1,
                                     const float* __restrict__ u2) {
    int idx = blockIdx.x * 256 + threadIdx.x;
    if (idx < 262144) {
        int n = idx >> 8, k = idx & 255;
        float s = (n < 512) ? w1[(size_t)k * 512 + n]
                            : w1[(size_t)(k + 256) * 512 + (n - 512)];
        g_wabt[idx] = __float2half(s);
    } else if (idx < 393216) {
        int t = idx - 262144;
        int n = t >> 9, k = t & 511;
        g_w2t[t] = __float2half(w2[(size_t)k * 256 + n]);
    } else if (idx < 655360) {
        int t = idx - 393216;
        int n = t >> 8, k = t & 255;
        g_u1t[t] = __float2half(u1[(size_t)k * 1024 + n]);
    } else if (idx < 917504) {
        int t = idx - 655360;
        int n = t >> 10, k = t & 1023;
        g_u2t[t] = __float2half(u2[(size_t)k * 256 + n]);
    }
}

// ---------------- compaction: count / scan / scatter -------------------------
__global__ void count_kernel() {
    int g = blockIdx.x * 256 + threadIdx.x;
    int i, j, oi; decode_edge(g, i, j, oi);
    int pred = g_valid[i] & g_valid[j];
    unsigned bal = __ballot_sync(0xffffffffu, pred);
    __shared__ int wcnt[8];
    if ((threadIdx.x & 31) == 0) wcnt[threadIdx.x >> 5] = __popc(bal);
    __syncthreads();
    if (threadIdx.x == 0) {
        int s = 0;
        #pragma unroll
        for (int k = 0; k < 8; k++) s += wcnt[k];
        g_bcount[blockIdx.x] = s;
    }
}

__global__ void scan_kernel() {
    __shared__ int part[256];
    int t = threadIdx.x;
    int base = t * 8;
    int loc[8];
    int s = 0;
    #pragma unroll
    for (int k = 0; k < 8; k++) {
        int idx = base + k;
        int v = (idx < NB) ? g_bcount[idx] : 0;
        loc[k] = s; s += v;
    }
    part[t] = s;
    __syncthreads();
    for (int o = 1; o < 256; o <<= 1) {
        int v = part[t];
        int add = (t >= o) ? part[t - o] : 0;
        __syncthreads();
        part[t] = v + add;
        __syncthreads();
    }
    int excl = part[t] - s;
    #pragma unroll
    for (int k = 0; k < 8; k++) {
        int idx = base + k;
        if (idx < 2048) g_boffs[idx] = excl + loc[k];
    }
    __syncthreads();
    if (t == 0) g_E = part[255];
}

__global__ void scatter_kernel() {
    int g = blockIdx.x * 256 + threadIdx.x;
    int lane = threadIdx.x & 31, warp = threadIdx.x >> 5;
    int i, j, oi; decode_edge(g, i, j, oi);
    int pred = g_valid[i] & g_valid[j];
    unsigned bal = __ballot_sync(0xffffffffu, pred);
    __shared__ int wcnt[8], wbase[8];
    if (lane == 0) wcnt[warp] = __popc(bal);
    __syncthreads();
    if (threadIdx.x == 0) {
        int s = 0;
        #pragma unroll
        for (int k = 0; k < 8; k++) { wbase[k] = s; s += wcnt[k]; }
    }
    __syncthreads();
    if (pred) {
        int pos = g_boffs[blockIdx.x] + wbase[warp]
                + __popc(bal & ((1u << lane) - 1u));
        g_ei[pos] = i; g_ej[pos] = j;
        g_posf[oi * NC + i] = pos;
        g_posr[oi * NC + j] = pos;
    }
}

// ---------------- gather messages + h2 residual + LN -> hu -------------------
__global__ void gather_ln_kernel(const float* __restrict__ h,
                                 const float* __restrict__ b2,
                                 const float* __restrict__ w,
                                 const float* __restrict__ b) {
    int warp = threadIdx.x >> 5, lane = threadIdx.x & 31;
    int row = blockIdx.x * 8 + warp;

    int p = -1;
    if (lane < 4)      p = g_posf[lane * NC + row];
    else if (lane < 8) p = g_posr[(lane - 4) * NC + row];

    float acc[8] = {};
    int cnt = 0;
    #pragma unroll
    for (int s = 0; s < 8; s++) {
        int ps = __shfl_sync(0xffffffffu, p, s);
        if (ps >= 0) {
            cnt++;
            const __half* Mrow = (s < 4 ? g_Mf : g_Mr) + (size_t)ps * Hdim + lane * 8;
            float f[8];
            ld8h(Mrow, f);
            #pragma unroll
            for (int k = 0; k < 8; k++) acc[k] += f[k];
        }
    }
    float cf = (float)cnt;
    const float* hr = h + (size_t)row * Hdim + lane * 8;
    const float* b2p = b2 + lane * 8;
    float4 ha = *(const float4*)hr;
    float4 hc = *(const float4*)(hr + 4);
    float hv[8] = {ha.x, ha.y, ha.z, ha.w, hc.x, hc.y, hc.z, hc.w};
    float v[8];
    #pragma unroll
    for (int k = 0; k < 8; k++) v[k] = hv[k] + acc[k] + cf * b2p[k];

    float* h2r = g_h2 + (size_t)row * Hdim + lane * 8;
    float4 o;
    o.x = v[0]; o.y = v[1]; o.z = v[2]; o.w = v[3];
    *(float4*)h2r = o;
    o.x = v[4]; o.y = v[5]; o.z = v[6]; o.w = v[7];
    *(float4*)(h2r + 4) = o;

    float s1 = 0.f, s2 = 0.f;
    #pragma unroll
    for (int k = 0; k < 8; k++) { s1 += v[k]; s2 += v[k]*v[k]; }
    #pragma unroll
    for (int ofs = 16; ofs > 0; ofs >>= 1) {
        s1 += __shfl_xor_sync(0xffffffffu, s1, ofs);
        s2 += __shfl_xor_sync(0xffffffffu, s2, ofs);
    }
    float mu = s1 * (1.0f / Hdim);
    float inv = rsqrtf(fmaxf(s2 * (1.0f / Hdim) - mu * mu, 0.f) + 1e-5f);
    const float* wp = w + lane * 8;
    const float* bp = b + lane * 8;
    float o0[4], o1[4];
    #pragma unroll
    for (int k = 0; k < 4; k++) o0[k] = (v[k]   - mu) * inv * wp[k]   + bp[k];
    #pragma unroll
    for (int k = 0; k < 4; k++) o1[k] = (v[4+k] - mu) * inv * wp[4+k] + bp[4+k];
    __half* yr = g_hu + (size_t)row * Hdim + lane * 8;
    st4h(yr, o0); st4h(yr + 4, o1);
}

// ============================================================================
// common tcgen05 helpers
// ============================================================================
__device__ __forceinline__ uint32_t smem_u32(const void* p) {
    uint32_t a;
    asm("{ .reg .u64 t; cvta.to.shared.u64 t, %1; cvt.u32.u64 %0, t; }" : "=r"(a) : "l"(p));
    return a;
}
__device__ __forceinline__ void mbar_wait(uint32_t mbar, uint32_t parity) {
    asm volatile(
        "{\n\t.reg .pred P1;\n\t"
        "W_%=:\n\t"
        "mbarrier.try_wait.parity.acquire.cta.shared::cta.b64 P1, [%0], %1, 0x989680;\n\t"
        "@P1 bra.uni D_%=;\n\t"
        "bra.uni W_%=;\n\t"
        "D_%=:\n\t}"
        :: "r"(mbar), "r"(parity) : "memory");
}

#if HAS_TC
__device__ __forceinline__ void mma_f16_ss(uint32_t d_tmem, uint64_t a_desc,
                                           uint64_t b_desc, uint32_t idesc, bool acc) {
    uint32_t en = acc ? 1u : 0u;
    asm volatile(
        "{\n\t.reg .pred p;\n\t"
        "setp.ne.u32 p, %5, 0;\n\t"
        "tcgen05.mma.cta_group::1.kind::f16 [%0], %1, %2, %3, {%4, %4, %4, %4}, p;\n\t"
        "}"
        :: "r"(d_tmem), "l"(a_desc), "l"(b_desc), "r"(idesc), "r"(0u), "r"(en)
        : "memory");
}
#define LDTM_X32(r, addr) \
    asm volatile( \
        "tcgen05.ld.sync.aligned.32x32b.x32.b32 " \
        "{%0, %1, %2, %3, %4, %5, %6, %7, " \
        " %8, %9, %10, %11, %12, %13, %14, %15, " \
        " %16, %17, %18, %19, %20, %21, %22, %23, " \
        " %24, %25, %26, %27, %28, %29, %30, %31}, [%32];" \
        : "=r"((r)[0]),  "=r"((r)[1]),  "=r"((r)[2]),  "=r"((r)[3]), \
          "=r"((r)[4]),  "=r"((r)[5]),  "=r"((r)[6]),  "=r"((r)[7]), \
          "=r"((r)[8]),  "=r"((r)[9]),  "=r"((r)[10]), "=r"((r)[11]), \
          "=r"((r)[12]), "=r"((r)[13]), "=r"((r)[14]), "=r"((r)[15]), \
          "=r"((r)[16]), "=r"((r)[17]), "=r"((r)[18]), "=r"((r)[19]), \
          "=r"((r)[20]), "=r"((r)[21]), "=r"((r)[22]), "=r"((r)[23]), \
          "=r"((r)[24]), "=r"((r)[25]), "=r"((r)[26]), "=r"((r)[27]), \
          "=r"((r)[28]), "=r"((r)[29]), "=r"((r)[30]), "=r"((r)[31]) \
        : "r"(addr))
#endif

static constexpr unsigned long long DESC_BASE =
    (2ull << 61) | (1ull << 46) | (64ull << 32) | (1ull << 16);
#define MMA_IDESC ((1u<<4) | (32u<<17) | (8u<<24))
#define SMEM_EDGE (1024 + 131072 + 128 + 2048)
#define SMEM_MLP  (1024 + 196608 + 64)
#define SMEM_PQ   (1024 + 131072 + 64)

// ============================================================================
// fused LN1 + PQ GEMM (from R12): hin = LN(h) into SMEM; PQ = hin @ wabt.
// ============================================================================
__global__ void __launch_bounds__(256, 1)
fused_ln_pq(const float* __restrict__ h,
            const float* __restrict__ lnw,
            const float* __restrict__ lnb,
            const __half* __restrict__ wabt,
            __half* __restrict__ PQ) {
    extern __shared__ char dyn[];
    int tid = threadIdx.x;
    int m0 = blockIdx.x * 128;
    int warp = tid >> 5, lane = tid & 31;

#if HAS_TC
    uint32_t u0 = smem_u32(dyn);
    uint32_t pad = (1024u - (u0 & 1023u)) & 1023u;
    char* base = dyn + pad;
    uint32_t ub = u0 + pad;

    uint32_t ctrl  = ub + 131072;
    uint32_t mbar0 = ctrl + 8;

    if (tid == 0) {
        asm volatile("mbarrier.init.shared.b64 [%0], 1;" :: "r"(mbar0)     : "memory");
        asm volatile("mbarrier.init.shared.b64 [%0], 1;" :: "r"(mbar0 + 8) : "memory");
    }
    if (warp == 0) {
        asm volatile("tcgen05.alloc.cta_group::1.sync.aligned.shared::cta.b32 [%0], %1;"
                     :: "r"(ctrl), "r"(512u) : "memory");
        asm volatile("tcgen05.relinquish_alloc_permit.cta_group::1.sync.aligned;");
    }
    __syncthreads();
    uint32_t tmem;
    asm volatile("ld.shared.b32 %0, [%1];" : "=r"(tmem) : "r"(ctrl));

    {
        const float* wp = lnw + lane * 8;
        const float* bp = lnb + lane * 8;
        float wv[8], bv2[8];
        #pragma unroll
        for (int k = 0; k < 8; k += 4) {
            *(float4*)(wv+k)  = *(const float4*)(wp+k);
            *(float4*)(bv2+k) = *(const float4*)(bp+k);
        }
        for (int it = 0; it < 16; it++) {
            int rl = it * 8 + warp;
            const float* xr = h + (size_t)(m0 + rl) * Hdim + lane * 8;
            float4 a = *(const float4*)xr;
            float4 c = *(const float4*)(xr + 4);
            float v[8] = {a.x, a.y, a.z, a.w, c.x, c.y, c.z, c.w};
            float s1 = 0.f, s2 = 0.f;
            #pragma unroll
            for (int k = 0; k < 8; k++) { s1 += v[k]; s2 += v[k]*v[k]; }
            #pragma unroll
            for (int o = 16; o > 0; o >>= 1) {
                s1 += __shfl_xor_sync(0xffffffffu, s1, o);
                s2 += __shfl_xor_sync(0xffffffffu, s2, o);
            }
            float mu = s1 * (1.0f / Hdim);
            float inv = rsqrtf(fmaxf(s2 * (1.0f / Hdim) - mu * mu, 0.f) + 1e-5f);
            float o8[8];
            #pragma unroll
            for (int k = 0; k < 8; k++) o8[k] = (v[k] - mu) * inv * wv[k] + bv2[k];
            uint32_t sob = (uint32_t)(rl * 128 + (lane & 7) * 16);
            sob ^= (sob >> 3) & 0x70u;
            *(uint4*)(base + (lane >> 3) * 16384 + sob) = pack8h(o8);
        }
    }
    __syncthreads();

    int rB = tid >> 3, fB = tid & 7;
    int trow = (warp & 3) * 32 + lane;
    int colhalf = (warp >> 2) * 128;

    int cidx = 0;
    for (int p = 0; p < 4; p++) {
        uint32_t D = tmem + (uint32_t)((p & 1) * 256);
        for (int c = 0; c < 4; c++) {
            int buf = cidx & 1;
            if (cidx >= 2) mbar_wait(mbar0 + 8u*buf, (uint32_t)(((cidx-2) >> 1) & 1));
            char* sB = base + 65536 + buf * 32768;
            #pragma unroll
            for (int i2 = 0; i2 < 8; i2++) {
                int rr = rB + i2 * 32;
                uint4 bv = *(const uint4*)(wabt + (size_t)(p*256 + rr) * Hdim + c*64 + fB*8);
                uint32_t sob = (uint32_t)(rr * 128 + fB * 16);
                sob ^= (sob >> 3) & 0x70u;
                *(uint4*)(sB + sob) = bv;
            }
            asm volatile("fence.proxy.async.shared::cta;" ::: "memory");
            __syncthreads();
            if (tid == 0) {
                uint32_t aaddr = ub + (uint32_t)(c * 16384);
                uint32_t baddr = ub + (uint32_t)(65536 + buf * 32768);
                uint64_t adesc = DESC_BASE | (uint64_t)((aaddr >> 4) & 0x3FFFu);
                uint64_t bdesc = DESC_BASE | (uint64_t)((baddr >> 4) & 0x3FFFu);
                #pragma unroll
                for (int s = 0; s < 4; s++)
                    mma_f16_ss(D, adesc + 2u*s, bdesc + 2u*s, MMA_IDESC, !(c == 0 && s == 0));
                asm volatile(
                    "tcgen05.commit.cta_group::1.mbarrier::arrive::one.shared::cluster.b64 [%0];"
                    :: "r"(mbar0 + 8u*buf) : "memory");
            }
            cidx++;
        }
        mbar_wait(mbar0 + 8u*((cidx-1)&1), (uint32_t)(((cidx-1) >> 1) & 1));
        mbar_wait(mbar0 + 8u*((cidx-2)&1), (uint32_t)(((cidx-2) >> 1) & 1));
        asm volatile("tcgen05.fence::after_thread_sync;" ::: "memory");

        {
            int m = m0 + trow;
            #pragma unroll
            for (int cc2 = 0; cc2 < 4; cc2++) {
                int col = colhalf + cc2 * 32;
                uint32_t r[32];
                LDTM_X32(r, D + (uint32_t)col);
                asm volatile("tcgen05.wait::ld.sync.aligned;" ::: "memory");
                #pragma unroll
                for (int q = 0; q < 32; q += 4) {
                    float o[4] = {__uint_as_float(r[q]),   __uint_as_float(r[q+1]),
                                  __uint_as_float(r[q+2]), __uint_as_float(r[q+3])};
                    st4h(PQ + (size_t)m * HU + p*256 + col + q, o);
                }
            }
        }
    }
    __syncthreads();
    if (warp == 0) {
        asm volatile("tcgen05.dealloc.cta_group::1.sync.aligned.b32 %0, %1;"
                     :: "r"(tmem), "r"(512u));
    }

#else  // -------- SIMT fallback: LN -> g_hin, then naive GEMM ------------------
    float* As = (float*)dyn;
    float* Bs = (float*)(dyn + 8192);

    for (int it = 0; it < 16; it++) {
        int rl = it * 8 + warp;
        int row = m0 + rl;
        const float* xr = h + (size_t)row * Hdim + lane * 8;
        float4 a = *(const float4*)xr;
        float4 c = *(const float4*)(xr + 4);
        float v[8] = {a.x, a.y, a.z, a.w, c.x, c.y, c.z, c.w};
        float s1 = 0.f, s2 = 0.f;
        #pragma unroll
        for (int k = 0; k < 8; k++) { s1 += v[k]; s2 += v[k]*v[k]; }
        #pragma unroll
        for (int o = 16; o > 0; o >>= 1) {
            s1 += __shfl_xor_sync(0xffffffffu, s1, o);
            s2 += __shfl_xor_sync(0xffffffffu, s2, o);
        }
        float mu = s1 * (1.0f / Hdim);
        float inv = rsqrtf(fmaxf(s2 * (1.0f / Hdim) - mu * mu, 0.f) + 1e-5f);
        float o8[8];
        #pragma unroll
        for (int k = 0; k < 8; k++)
            o8[k] = (v[k] - mu) * inv * lnw[lane*8+k] + lnb[lane*8+k];
        st4h(g_hin + (size_t)row * Hdim + lane * 8, o8);
        st4h(g_hin + (size_t)row * Hdim + lane * 8 + 4, o8 + 4);
    }
    __syncthreads();

    int tr = tid >> 4, tc = tid & 15;
    int lrow = tid >> 1;
    int lk   = (tid & 1) * 8;
    for (int half = 0; half < 8; half++) {
        int n0h = half * 128;
        float acc[8][8] = {};
        for (int k0 = 0; k0 < Hdim; k0 += 16) {
            #pragma unroll
            for (int e = 0; e < 8; e++) {
                As[(lk+e)*128 + lrow] = __half2float(g_hin[(size_t)(m0 + lrow) * Hdim + k0 + lk + e]);
                Bs[(lk+e)*128 + lrow] = __half2float(wabt[(size_t)(n0h + lrow) * Hdim + k0 + lk + e]);
            }
            __syncthreads();
            #pragma unroll
            for (int k = 0; k < 16; k++) {
                float a[8], b[8];
                #pragma unroll
                for (int i2 = 0; i2 < 8; i2++) a[i2] = As[k*128 + tr*8 + i2];
                #pragma unroll
                for (int j2 = 0; j2 < 8; j2++) b[j2] = Bs[k*128 + tc*8 + j2];
                #pragma unroll
                for (int i2 = 0; i2 < 8; i2++)
                    #pragma unroll
                    for (int j2 = 0; j2 < 8; j2++)
                        acc[i2][j2] += a[i2] * b[j2];
            }
            __syncthreads();
        }
        int col0 = n0h + tc * 8;
        #pragma unroll
        for (int i2 = 0; i2 < 8; i2++) {
            int m = m0 + tr * 8 + i2;
            for (int j2 = 0; j2 < 8; j2++)
                PQ[(size_t)m * HU + col0 + j2] = __float2half(acc[i2][j2]);
        }
        __syncthreads();
    }
#endif
}

// ============================================================================
// fused edge-message kernel (register-prefetched gathers)
// ============================================================================
__global__ void __launch_bounds__(256, 1)
edge_msg_kernel(const float* __restrict__ xyz,
                const float* __restrict__ w1,
                const float* __restrict__ b1,
                const __half* __restrict__ w2t) {
    extern __shared__ char dyn[];
    int tid = threadIdx.x;
    int m0 = blockIdx.x * 128;
    if (m0 >= g_E) return;

#if HAS_TC
    uint32_t u0 = smem_u32(dyn);
    uint32_t pad = (1024u - (u0 & 1023u)) & 1023u;
    char* base = dyn + pad;
    uint32_t ub = u0 + pad;

    uint32_t ctrl  = ub + 131072;
    uint32_t mbar0 = ctrl + 8;
    float* ef = (float*)(base + 131072 + 128);

    int wid = tid >> 5;
    int lane = tid & 31;

    if (tid == 0) {
        asm volatile("mbarrier.init.shared.b64 [%0], 1;" :: "r"(mbar0)     : "memory");
        asm volatile("mbarrier.init.shared.b64 [%0], 1;" :: "r"(mbar0 + 8) : "memory");
    }
    if (wid == 0) {
        asm volatile("tcgen05.alloc.cta_group::1.sync.aligned.shared::cta.b32 [%0], %1;"
                     :: "r"(ctrl), "r"(512u) : "memory");
        asm volatile("tcgen05.relinquish_alloc_permit.cta_group::1.sync.aligned;");
    }
    __syncthreads();
    uint32_t tmem;
    asm volatile("ld.shared.b32 %0, [%1];" : "=r"(tmem) : "r"(ctrl));

    if (tid < 128) {
        int m = m0 + tid;
        int i = g_ei[m], j = g_ej[m];
        float dx = xyz[3*j+0] - xyz[3*i+0];
        float dy = xyz[3*j+1] - xyz[3*i+1];
        float dz = xyz[3*j+2] - xyz[3*i+2];
        float d = fmaxf(sqrtf(dx*dx + dy*dy + dz*dz), 1e-6f);
        float inv = 1.0f / d;
        ef[tid*4+0] = dx*inv; ef[tid*4+1] = dy*inv; ef[tid*4+2] = dz*inv; ef[tid*4+3] = d;
    }
    __syncthreads();

    int r0 = tid >> 3, oct = tid & 7;
    uint32_t so = (uint32_t)(r0 * 128 + oct * 16);
    so ^= (so >> 3) & 0x70u;

    int ei4[4], ej4[4];
    float efr[4][4];
    #pragma unroll
    for (int it = 0; it < 4; it++) {
        int r = r0 + it * 32;
        ei4[it] = g_ei[m0 + r];
        ej4[it] = g_ej[m0 + r];
        efr[it][0] = ef[r*4+0]; efr[it][1] = ef[r*4+1];
        efr[it][2] = ef[r*4+2]; efr[it][3] = ef[r*4+3];
    }

    uint4 gp[16];
    uint4 rbB[8];
    const int NCH = 8;

    {
        int col = oct * 8;
        #pragma unroll
        for (int it = 0; it < 4; it++) {
            gp[it*4+0] = *(const uint4*)(g_PQ + (size_t)ei4[it]*HU + col);
            gp[it*4+1] = *(const uint4*)(g_PQ + (size_t)ei4[it]*HU + 512 + col);
            gp[it*4+2] = *(const uint4*)(g_PQ + (size_t)ej4[it]*HU + col);
            gp[it*4+3] = *(const uint4*)(g_PQ + (size_t)ej4[it]*HU + 512 + col);
        }
        #pragma unroll
        for (int i2 = 0; i2 < 8; i2++) {
            int idx = tid + i2 * 256;
            int rB = idx >> 3, fB = idx & 7;
            rbB[i2] = *(const uint4*)(w2t + (size_t)rB * H2 + fB * 8);
        }
    }

    for (int c = 0; c < NCH; c++) {
        int buf = c & 1;
        if (c >= 2) mbar_wait(mbar0 + 8u * buf, (uint32_t)(((c - 2) >> 1) & 1));
        char* sAf = base + buf * 65536;
        char* sAr = sAf + 16384;
        char* sB  = sAf + 32768;
        int col = (c << 6) + oct * 8;

        #pragma unroll
        for (int i2 = 0; i2 < 8; i2++) {
            int idx = tid + i2 * 256;
            int rB = idx >> 3, fB = idx & 7;
            uint32_t sob = (uint32_t)(rB * 128 + fB * 16);
            sob ^= (sob >> 3) & 0x70u;
            *(uint4*)(sB + sob) = rbB[i2];
        }

        float w0v[8], w1v[8], w2v[8], w3v[8], bbv[8];
        {
            const float* wr0 = w1 + (size_t)(2*Hdim + 0)*H2 + col;
            const float* wr1 = w1 + (size_t)(2*Hdim + 1)*H2 + col;
            const float* wr2 = w1 + (size_t)(2*Hdim + 2)*H2 + col;
            const float* wr3 = w1 + (size_t)(2*Hdim + 3)*H2 + col;
            const float* bbr = b1 + col;
            #pragma unroll
            for (int q = 0; q < 8; q += 4) {
                *(float4*)(w0v+q) = *(const float4*)(wr0+q);
                *(float4*)(w1v+q) = *(const float4*)(wr1+q);
                *(float4*)(w2v+q) = *(const float4*)(wr2+q);
                *(float4*)(w3v+q) = *(const float4*)(wr3+q);
                *(float4*)(bbv+q) = *(const float4*)(bbr+q);
            }
        }

        #pragma unroll
        for (int it = 0; it < 4; it++) {
            float pi[8], qi[8], pj[8], qj[8];
            cvt8h(gp[it*4+0], pi);
            cvt8h(gp[it*4+1], qi);
            cvt8h(gp[it*4+2], pj);
            cvt8h(gp[it*4+3], qj);
            float e0 = efr[it][0], e1 = efr[it][1], e2 = efr[it][2], e3 = efr[it][3];
            float rf[8], rr[8];
            #pragma unroll
            for (int q = 0; q < 8; q++) {
                float eu = e0*w0v[q] + e1*w1v[q] + e2*w2v[q];
                float ed = e3*w3v[q] + bbv[q];
                rf[q] = gelu_exact(pi[q] + qj[q] + eu + ed);
                rr[q] = gelu_exact(pj[q] + qi[q] - eu + ed);
            }
            *(uint4*)(sAf + so + (uint32_t)(it * 4096)) = pack8h(rf);
            *(uint4*)(sAr + so + (uint32_t)(it * 4096)) = pack8h(rr);
        }

        if (c + 1 < NCH) {
            int coln = ((c + 1) << 6) + oct * 8;
            #pragma unroll
            for (int it = 0; it < 4; it++) {
                gp[it*4+0] = *(const uint4*)(g_PQ + (size_t)ei4[it]*HU + coln);
                gp[it*4+1] = *(const uint4*)(g_PQ + (size_t)ei4[it]*HU + 512 + coln);
                gp[it*4+2] = *(const uint4*)(g_PQ + (size_t)ej4[it]*HU + coln);
                gp[it*4+3] = *(const uint4*)(g_PQ + (size_t)ej4[it]*HU + 512 + coln);
            }
            int k0n = (c + 1) << 6;
            #pragma unroll
            for (int i2 = 0; i2 < 8; i2++) {
                int idx = tid + i2 * 256;
                int rB = idx >> 3, fB = idx & 7;
                rbB[i2] = *(const uint4*)(w2t + (size_t)rB * H2 + k0n + fB * 8);
            }
        }

        asm volatile("fence.proxy.async.shared::cta;" ::: "memory");
        __syncthreads();

        if (tid == 0) {
            uint32_t afaddr = ub + (uint32_t)(buf * 65536);
            uint32_t araddr = afaddr + 16384u;
            uint32_t baddr  = afaddr + 32768u;
            uint64_t adescF = DESC_BASE | (uint64_t)((afaddr >> 4) & 0x3FFFu);
            uint64_t adescR = DESC_BASE | (uint64_t)((araddr >> 4) & 0x3FFFu);
            uint64_t bdesc  = DESC_BASE | (uint64_t)((baddr  >> 4) & 0x3FFFu);
            #pragma unroll
            for (int s = 0; s < 4; s++) {
                bool acc = !(c == 0 && s == 0);
                mma_f16_ss(tmem,        adescF + 2u*s, bdesc + 2u*s, MMA_IDESC, acc);
                mma_f16_ss(tmem + 256u, adescR + 2u*s, bdesc + 2u*s, MMA_IDESC, acc);
            }
            asm volatile(
                "tcgen05.commit.cta_group::1.mbarrier::arrive::one.shared::cluster.b64 [%0];"
                :: "r"(mbar0 + 8u * buf) : "memory");
        }
    }
    mbar_wait(mbar0 + 8u * ((NCH - 2) & 1), (uint32_t)(((NCH - 2) >> 1) & 1));
    mbar_wait(mbar0 + 8u * ((NCH - 1) & 1), (uint32_t)(((NCH - 1) >> 1) & 1));
    asm volatile("tcgen05.fence::after_thread_sync;" ::: "memory");

    {
        int dir = wid >> 2;
        int wd  = wid & 3;
        int trow = wd * 32 + lane;
        int m = m0 + trow;
        __half* M = dir ? g_Mr : g_Mf;
        uint32_t dbase = tmem + (uint32_t)(dir * 256);
        #pragma unroll
        for (int cc = 0; cc < 256; cc += 32) {
            uint32_t r[32];
            LDTM_X32(r, dbase + (uint32_t)cc);
            asm volatile("tcgen05.wait::ld.sync.aligned;" ::: "memory");
            #pragma unroll
            for (int q = 0; q < 32; q += 4) {
                float o[4] = {__uint_as_float(r[q]),   __uint_as_float(r[q+1]),
                              __uint_as_float(r[q+2]), __uint_as_float(r[q+3])};
                st4h(M + (size_t)m * Hdim + cc + q, o);
            }
        }
    }
    __syncthreads();
    if (wid == 0) {
        asm volatile("tcgen05.dealloc.cta_group::1.sync.aligned.b32 %0, %1;"
                     :: "r"(tmem), "r"(512u));
    }

#else  // -------- SIMT fallback ------------------------------------------------
    float* As = (float*)dyn;
    float* Bs = (float*)(dyn + 8192);
    float* ef = (float*)(dyn + 16384);

    if (tid < 128) {
        int m = m0 + tid;
        int i = g_ei[m], j = g_ej[m];
        float dx = xyz[3*j+0] - xyz[3*i+0];
        float dy = xyz[3*j+1] - xyz[3*i+1];
        float dz = xyz[3*j+2] - xyz[3*i+2];
        float d = fmaxf(sqrtf(dx*dx + dy*dy + dz*dz), 1e-6f);
        float inv = 1.0f / d;
        ef[tid*4+0] = dx*inv; ef[tid*4+1] = dy*inv; ef[tid*4+2] = dz*inv; ef[tid*4+3] = d;
    }
    __syncthreads();

    int tr = tid >> 4, tc = tid & 15;
    for (int dir = 0; dir < 2; dir++) {
        for (int half = 0; half < 2; half++) {
            int n0h = half * 128;
            float acc[8][8] = {};
            for (int k0 = 0; k0 < H2; k0 += 16) {
                #pragma unroll
                for (int e = 0; e < 8; e++) {
                    int idx = tid * 8 + e;
                    int kk = idx >> 7, rr2 = idx & 127;
                    int m = m0 + rr2;
                    int i = g_ei[m], j = g_ej[m];
                    int colk = k0 + kk;
                    float e0 = ef[rr2*4], e1 = ef[rr2*4+1], e2 = ef[rr2*4+2], e3 = ef[rr2*4+3];
                    float eu = e0*w1[(size_t)(2*Hdim+0)*H2+colk]
                             + e1*w1[(size_t)(2*Hdim+1)*H2+colk]
                             + e2*w1[(size_t)(2*Hdim+2)*H2+colk];
                    float ed = e3*w1[(size_t)(2*Hdim+3)*H2+colk] + b1[colk];
                    float pv, qv;
                    if (dir == 0) {
                        pv = __half2float(g_PQ[(size_t)i*HU + colk]);
                        qv = __half2float(g_PQ[(size_t)j*HU + 512 + colk]);
                        As[kk*128 + rr2] = gelu_exact(pv + qv + eu + ed);
                    } else {
                        pv = __half2float(g_PQ[(size_t)j*HU + colk]);
                        qv = __half2float(g_PQ[(size_t)i*HU + 512 + colk]);
                        As[kk*128 + rr2] = gelu_exact(pv + qv - eu + ed);
                    }
                    Bs[kk*128 + rr2] = __half2float(w2t[(size_t)(n0h + rr2) * H2 + colk]);
                }
                __syncthreads();
                #pragma unroll
                for (int k = 0; k < 16; k++) {
                    float a[8], b[8];
                    #pragma unroll
                    for (int i2 = 0; i2 < 8; i2++) a[i2] = As[k*128 + tr*8 + i2];
                    #pragma unroll
                    for (int j2 = 0; j2 < 8; j2++) b[j2] = Bs[k*128 + tc*8 + j2];
                    #pragma unroll
                    for (int i2 = 0; i2 < 8; i2++)
                        #pragma unroll
                        for (int j2 = 0; j2 < 8; j2++)
                            acc[i2][j2] += a[i2] * b[j2];
                }
                __syncthreads();
            }
            __half* M = dir ? g_Mr : g_Mf;
            int col0 = n0h + tc * 8;
            #pragma unroll
            for (int i2 = 0; i2 < 8; i2++) {
                int m = m0 + tr * 8 + i2;
                for (int j2 = 0; j2 < 8; j2++)
                    M[(size_t)m * Hdim + col0 + j2] = __float2half(acc[i2][j2]);
            }
            __syncthreads();
        }
    }
#endif
}

// ============================================================================
// fused update-MLP (from R11): out = (h2 + gelu(hu@u1 + bu1) @ u2 + bu2) * valid
// ============================================================================
__global__ void __launch_bounds__(256, 1)
fused_mlp_kernel(const __half* __restrict__ u1t,
                 const __half* __restrict__ u2t,
                 const float* __restrict__ bu1,
                 const float* __restrict__ bu2,
                 float* __restrict__ out) {
    extern __shared__ char dyn[];
    int tid = threadIdx.x;
    int m0 = blockIdx.x * 128;

#if HAS_TC
    uint32_t u0 = smem_u32(dyn);
    uint32_t pad = (1024u - (u0 & 1023u)) & 1023u;
    char* base = dyn + pad;
    uint32_t ub = u0 + pad;

    uint32_t ctrl  = ub + 196608;
    uint32_t mbar0 = ctrl + 8;

    int wid = tid >> 5;
    int lane = tid & 31;

    if (tid == 0) {
        asm volatile("mbarrier.init.shared.b64 [%0], 1;" :: "r"(mbar0)     : "memory");
        asm volatile("mbarrier.init.shared.b64 [%0], 1;" :: "r"(mbar0 + 8) : "memory");
    }
    if (wid == 0) {
        asm volatile("tcgen05.alloc.cta_group::1.sync.aligned.shared::cta.b32 [%0], %1;"
                     :: "r"(ctrl), "r"(512u) : "memory");
        asm volatile("tcgen05.relinquish_alloc_permit.cta_group::1.sync.aligned;");
    }
    __syncthreads();
    uint32_t tmem;
    asm volatile("ld.shared.b32 %0, [%1];" : "=r"(tmem) : "r"(ctrl));

    #pragma unroll
    for (int i2 = 0; i2 < 16; i2++) {
        int g = tid + i2 * 256;
        int r = g >> 5;
        int f = g & 31;
        uint4 v = *(const uint4*)(g_hu + (size_t)(m0 + r) * Hdim + f * 8);
        uint32_t sob = (uint32_t)(r * 128 + (f & 7) * 16);
        sob ^= (sob >> 3) & 0x70u;
        *(uint4*)(base + (f >> 3) * 16384 + sob) = v;
    }

    int rB = tid >> 3, fB = tid & 7;
    int trow = (wid & 3) * 32 + lane;
    int colhalf = (wid >> 2) * 128;

    uint32_t D2 = tmem;
    uint32_t D1 = tmem + 256u;

    int cidx = 0;
    for (int p = 0; p < 4; p++) {
        for (int c = 0; c < 4; c++) {
            int buf = cidx & 1;
            if (cidx >= 2) mbar_wait(mbar0 + 8u*buf, (uint32_t)(((cidx-2) >> 1) & 1));
            char* sB = base + 131072 + buf * 32768;
            #pragma unroll
            for (int i2 = 0; i2 < 8; i2++) {
                int rr = rB + i2 * 32;
                uint4 bv = *(const uint4*)(u1t + (size_t)(p*256 + rr) * Hdim + c*64 + fB*8);
                uint32_t sob = (uint32_t)(rr * 128 + fB * 16);
                sob ^= (sob >> 3) & 0x70u;
                *(uint4*)(sB + sob) = bv;
            }
            asm volatile("fence.proxy.async.shared::cta;" ::: "memory");
            __syncthreads();
            if (tid == 0) {
                uint32_t aaddr = ub + (uint32_t)(c * 16384);
                uint32_t baddr = ub + (uint32_t)(131072 + buf * 32768);
                uint64_t adesc = DESC_BASE | (uint64_t)((aaddr >> 4) & 0x3FFFu);
                uint64_t bdesc = DESC_BASE | (uint64_t)((baddr >> 4) & 0x3FFFu);
                #pragma unroll
                for (int s = 0; s < 4; s++)
                    mma_f16_ss(D1, adesc + 2u*s, bdesc + 2u*s, MMA_IDESC, !(c == 0 && s == 0));
                asm volatile(
                    "tcgen05.commit.cta_group::1.mbarrier::arrive::one.shared::cluster.b64 [%0];"
                    :: "r"(mbar0 + 8u*buf) : "memory");
            }
            cidx++;
        }
        mbar_wait(mbar0 + 8u*((cidx-1)&1), (uint32_t)(((cidx-1) >> 1) & 1));
        mbar_wait(mbar0 + 8u*((cidx-2)&1), (uint32_t)(((cidx-2) >> 1) & 1));
        asm volatile("tcgen05.fence::after_thread_sync;" ::: "memory");

        #pragma unroll
        for (int cc2 = 0; cc2 < 4; cc2++) {
            int col = colhalf + cc2 * 32;
            uint32_t r[32];
            LDTM_X32(r, D1 + (uint32_t)col);
            asm volatile("tcgen05.wait::ld.sync.aligned;" ::: "memory");
            #pragma unroll
            for (int q = 0; q < 32; q += 8) {
                int ck = col + q;
                float o[8];
                #pragma unroll
                for (int e = 0; e < 8; e++)
                    o[e] = gelu_exact(__uint_as_float(r[q+e]) + __ldg(&bu1[p*256 + ck + e]));
                uint32_t sob = (uint32_t)(trow * 128 + ((ck >> 3) & 7) * 16);
                sob ^= (sob >> 3) & 0x70u;
                *(uint4*)(base + 65536 + (ck >> 6) * 16384 + sob) = pack8h(o);
            }
        }

        for (int c = 0; c < 4; c++) {
            int buf = cidx & 1;
            mbar_wait(mbar0 + 8u*buf, (uint32_t)(((cidx-2) >> 1) & 1));
            char* sB = base + 131072 + buf * 32768;
            #pragma unroll
            for (int i2 = 0; i2 < 8; i2++) {
                int rr = rB + i2 * 32;
                uint4 bv = *(const uint4*)(u2t + (size_t)rr * HU + p*256 + c*64 + fB*8);
                uint32_t sob = (uint32_t)(rr * 128 + fB * 16);
                sob ^= (sob >> 3) & 0x70u;
                *(uint4*)(sB + sob) = bv;
            }
            asm volatile("fence.proxy.async.shared::cta;" ::: "memory");
            __syncthreads();
            if (tid == 0) {
                uint32_t aaddr = ub + (uint32_t)(65536 + c * 16384);
                uint32_t baddr = ub + (uint32_t)(131072 + buf * 32768);
                uint64_t adesc = DESC_BASE | (uint64_t)((aaddr >> 4) & 0x3FFFu);
                uint64_t bdesc = DESC_BASE | (uint64_t)((baddr >> 4) & 0x3FFFu);
                #pragma unroll
                for (int s = 0; s < 4; s++)
                    mma_f16_ss(D2, adesc + 2u*s, bdesc + 2u*s, MMA_IDESC,
                               !(p == 0 && c == 0 && s == 0));
                asm volatile(
                    "tcgen05.commit.cta_group::1.mbarrier::arrive::one.shared::cluster.b64 [%0];"
                    :: "r"(mbar0 + 8u*buf) : "memory");
            }
            cidx++;
        }
    }
    mbar_wait(mbar0 + 8u*((cidx-1)&1), (uint32_t)(((cidx-1) >> 1) & 1));
    mbar_wait(mbar0 + 8u*((cidx-2)&1), (uint32_t)(((cidx-2) >> 1) & 1));
    asm volatile("tcgen05.fence::after_thread_sync;" ::: "memory");

    {
        int m = m0 + trow;
        float vf = g_valid[m] ? 1.0f : 0.0f;
        #pragma unroll
        for (int cc2 = 0; cc2 < 4; cc2++) {
            int col = colhalf + cc2 * 32;
            uint32_t r[32];
            LDTM_X32(r, D2 + (uint32_t)col);
            asm volatile("tcgen05.wait::ld.sync.aligned;" ::: "memory");
            const float* a2 = g_h2 + (size_t)m * Hdim + col;
            #pragma unroll
            for (int q = 0; q < 32; q += 4) {
                float4 av = *(const float4*)(a2 + q);
                float4 o;
                o.x = (av.x + __uint_as_float(r[q])   + __ldg(&bu2[col+q]))   * vf;
                o.y = (av.y + __uint_as_float(r[q+1]) + __ldg(&bu2[col+q+1])) * vf;
                o.z = (av.z + __uint_as_float(r[q+2]) + __ldg(&bu2[col+q+2])) * vf;
                o.w = (av.w + __uint_as_float(r[q+3]) + __ldg(&bu2[col+q+3])) * vf;
                *(float4*)(out + (size_t)m * Hdim + col + q) = o;
            }
        }
    }
    __syncthreads();
    if (wid == 0) {
        asm volatile("tcgen05.dealloc.cta_group::1.sync.aligned.b32 %0, %1;"
                     :: "r"(tmem), "r"(512u));
    }

#else  // -------- SIMT fallback: two naive GEMMs staged via g_T1 --------------
    float* As = (float*)dyn;
    float* Bs = (float*)(dyn + 8192);
    int tr = tid >> 4, tc = tid & 15;
    int lrow = tid >> 1;
    int lk   = (tid & 1) * 8;

    for (int half = 0; half < 8; half++) {
        int n0h = half * 128;
        float acc[8][8] = {};
        for (int k0 = 0; k0 < Hdim; k0 += 16) {
            #pragma unroll
            for (int e = 0; e < 8; e++) {
                As[(lk+e)*128 + lrow] = __half2float(g_hu[(size_t)(m0 + lrow) * Hdim + k0 + lk + e]);
                Bs[(lk+e)*128 + lrow] = __half2float(u1t[(size_t)(n0h + lrow) * Hdim + k0 + lk + e]);
            }
            __syncthreads();
            #pragma unroll
            for (int k = 0; k < 16; k++) {
                float a[8], b[8];
                #pragma unroll
                for (int i2 = 0; i2 < 8; i2++) a[i2] = As[k*128 + tr*8 + i2];
                #pragma unroll
                for (int j2 = 0; j2 < 8; j2++) b[j2] = Bs[k*128 + tc*8 + j2];
                #pragma unroll
                for (int i2 = 0; i2 < 8; i2++)
                    #pragma unroll
                    for (int j2 = 0; j2 < 8; j2++)
                        acc[i2][j2] += a[i2] * b[j2];
            }
            __syncthreads();
        }
        int col0 = n0h + tc * 8;
        #pragma unroll
        for (int i2 = 0; i2 < 8; i2++) {
            int m = m0 + tr * 8 + i2;
            for (int j2 = 0; j2 < 8; j2++)
                g_T1[(size_t)m * HU + col0 + j2] =
                    __float2half(gelu_exact(acc[i2][j2] + bu1[col0 + j2]));
        }
        __syncthreads();
    }

    for (int half = 0; half < 2; half++) {
        int n0h = half * 128;
        float acc[8][8] = {};
        for (int k0 = 0; k0 < HU; k0 += 16) {
            #pragma unroll
            for (int e = 0; e < 8; e++) {
                As[(lk+e)*128 + lrow] = __half2float(g_T1[(size_t)(m0 + lrow) * HU + k0 + lk + e]);
                Bs[(lk+e)*128 + lrow] = __half2float(u2t[(size_t)(n0h + lrow) * HU + k0 + lk + e]);
            }
            __syncthreads();
            #pragma unroll
            for (int k = 0; k < 16; k++) {
                float a[8], b[8];
                #pragma unroll
                for (int i2 = 0; i2 < 8; i2++) a[i2] = As[k*128 + tr*8 + i2];
                #pragma unroll
                for (int j2 = 0; j2 < 8; j2++) b[j2] = Bs[k*128 + tc*8 + j2];
                #pragma unroll
                for (int i2 = 0; i2 < 8; i2++)
                    #pragma unroll
                    for (int j2 = 0; j2 < 8; j2++)
                        acc[i2][j2] += a[i2] * b[j2];
            }
            __syncthreads();
        }
        int col0 = n0h + tc * 8;
        #pragma unroll
        for (int i2 = 0; i2 < 8; i2++) {
            int m = m0 + tr * 8 + i2;
            float vf = g_valid[m] ? 1.0f : 0.0f;
            for (int j2 = 0; j2 < 8; j2++)
                out[(size_t)m * Hdim + col0 + j2] =
                    (g_h2[(size_t)m * Hdim + col0 + j2] + acc[i2][j2] + bu2[col0 + j2]) * vf;
        }
        __syncthreads();
    }
#endif
}

// ---------------- launch -----------------------------------------------------
extern "C" void kernel_launch(void* const* d_in, const int* in_sizes, int n_in,
                              void* d_out, int out_size) {
    const float*         h      = (const float*)d_in[0];
    const float*         xyz    = (const float*)d_in[1];
    const unsigned char* validb = (const unsigned char*)d_in[2];
    const float*         ln_n_w = (const float*)d_in[3];
    const float*         ln_n_b = (const float*)d_in[4];
    const float*         w1     = (const float*)d_in[5];
    const float*         b1     = (const float*)d_in[6];
    const float*         w2     = (const float*)d_in[7];
    const float*         b2     = (const float*)d_in[8];
    const float*         ln_u_w = (const float*)d_in[9];
    const float*         ln_u_b = (const float*)d_in[10];
    const float*         u1     = (const float*)d_in[11];
    const float*         bu1    = (const float*)d_in[12];
    const float*         u2     = (const float*)d_in[13];
    const float*         bu2    = (const float*)d_in[14];
    float* out = (float*)d_out;

    __half *pPQ, *pWabt, *pW2t, *pU1t, *pU2t;
    cudaGetSymbolAddress((void**)&pPQ,  g_PQ);
    cudaGetSymbolAddress((void**)&pWabt, g_wabt);
    cudaGetSymbolAddress((void**)&pW2t,  g_w2t);
    cudaGetSymbolAddress((void**)&pU1t,  g_u1t);
    cudaGetSymbolAddress((void**)&pU2t,  g_u2t);

    cudaFuncSetAttribute(fused_ln_pq, cudaFuncAttributeMaxDynamicSharedMemorySize, SMEM_PQ);
    cudaFuncSetAttribute(edge_msg_kernel, cudaFuncAttributeMaxDynamicSharedMemorySize, SMEM_EDGE);
    cudaFuncSetAttribute(fused_mlp_kernel, cudaFuncAttributeMaxDynamicSharedMemorySize, SMEM_MLP);

    detect_vmode_kernel<<<1, 256>>>(validb);
    conv_valid_kernel<<<(NC + 255) / 256, 256>>>(validb);
    clear_pos_kernel<<<4*NC/256, 256>>>();
    transpose_all_kernel<<<917504/256, 256>>>(w1, w2, u1, u2);
    count_kernel<<<NB, 256>>>();

    // LN1 + PQ GEMM fused
    fused_ln_pq<<<NC/128, 256, SMEM_PQ>>>(h, ln_n_w, ln_n_b, pWabt, pPQ);

    scan_kernel<<<1, 256>>>();
    scatter_kernel<<<NB, 256>>>();

    edge_msg_kernel<<<MAXE/128, 256, SMEM_EDGE>>>(xyz, w1, b1, pW2t);

    // gather + h2 + LN -> hu (separate launch; overlaps edge tail across SMs)
    gather_ln_kernel<<<NC/8, 256>>>(h, b2, ln_u_w, ln_u_b);

    // fused update MLP
    fused_mlp_kernel<<<NC/128, 256, SMEM_MLP>>>(pU1t, pU2t, bu1, bu2, out);
    (void)in_sizes; (void)n_in; (void)out_size;
}

// round 15
// speedup vs baseline: 1.0965x; 1.0236x over previous
#include <cuda_runtime.h>
#include <cuda_fp16.h>
#include <math.h>
#include <stdint.h>

#define Ndim 256
#define Cdim 512
#define Hdim 256
#define NC   (Ndim*Cdim)   // 131072
#define H2   512
#define HU   1024
#define MAXE 520448
#define NB   2033          // MAXE / 256

#if defined(__CUDA_ARCH_FEAT_SM103_ALL) || defined(__CUDA_ARCH_FEAT_SM100_ALL) || \
    (defined(__CUDA_ARCH_SPECIFIC__) && (__CUDA_ARCH_SPECIFIC__ >= 1000))
#define HAS_TC 1
#else
#define HAS_TC 0
#endif

// ---------------- scratch ----------------------------------------------------
__device__ __half g_hin[(size_t)NC*Hdim];    // fallback staging only
__device__ __half g_PQ [(size_t)NC*HU];
__device__ __half g_Mf [(size_t)MAXE*Hdim];
__device__ __half g_Mr [(size_t)MAXE*Hdim];
__device__ float  g_h2 [(size_t)NC*Hdim];
__device__ __half g_hu [(size_t)NC*Hdim];
__device__ __half g_T1 [(size_t)NC*HU];      // fallback staging only
__device__ __half g_wabt[(size_t)HU*Hdim];
__device__ __half g_w2t [(size_t)Hdim*H2];
__device__ __half g_u1t [(size_t)HU*Hdim];
__device__ __half g_u2t [(size_t)Hdim*HU];
__device__ unsigned char g_valid[NC];
__device__ int g_vmode;
__device__ int g_ei[MAXE];
__device__ int g_ej[MAXE];
__device__ int g_posf[4*NC];
__device__ int g_posr[4*NC];
__device__ int g_bcount[2048];
__device__ int g_boffs[2048];
__device__ int g_E;

__device__ __forceinline__ float gelu_exact(float x) {
    return 0.5f * x * (1.0f + erff(x * 0.70710678118654752f));
}
__device__ __forceinline__ void st4h(__half* p, const float* f) {
    uint2 u;
    *(__half2*)&u.x = __float22half2_rn(make_float2(f[0], f[1]));
    *(__half2*)&u.y = __float22half2_rn(make_float2(f[2], f[3]));
    *(uint2*)p = u;
}
__device__ __forceinline__ void ld8h(const __half* p, float* f) {
    uint4 u = *(const uint4*)p;
    float2 a = __half22float2(*(__half2*)&u.x);
    float2 b = __half22float2(*(__half2*)&u.y);
    float2 c = __half22float2(*(__half2*)&u.z);
    float2 d = __half22float2(*(__half2*)&u.w);
    f[0]=a.x; f[1]=a.y; f[2]=b.x; f[3]=b.y; f[4]=c.x; f[5]=c.y; f[6]=d.x; f[7]=d.y;
}
__device__ __forceinline__ void cvt8h(const uint4& u, float* f) {
    float2 a = __half22float2(*(__half2*)&u.x);
    float2 b = __half22float2(*(__half2*)&u.y);
    float2 c = __half22float2(*(__half2*)&u.z);
    float2 d = __half22float2(*(__half2*)&u.w);
    f[0]=a.x; f[1]=a.y; f[2]=b.x; f[3]=b.y; f[4]=c.x; f[5]=c.y; f[6]=d.x; f[7]=d.y;
}
__device__ __forceinline__ uint4 pack8h(const float* f) {
    uint4 u;
    *(__half2*)&u.x = __float22half2_rn(make_float2(f[0], f[1]));
    *(__half2*)&u.y = __float22half2_rn(make_float2(f[2], f[3]));
    *(__half2*)&u.z = __float22half2_rn(make_float2(f[4], f[5]));
    *(__half2*)&u.w = __float22half2_rn(make_float2(f[6], f[7]));
    return u;
}

__device__ __forceinline__ void decode_edge(int g, int& i, int& j, int& oi) {
    int off, Ce, t;
    if (g < 130816)      { off = 1; Ce = 511; t = g;          oi = 0; }
    else if (g < 261376) { off = 2; Ce = 510; t = g - 130816; oi = 1; }
    else if (g < 391424) { off = 4; Ce = 508; t = g - 261376; oi = 2; }
    else                 { off = 8; Ce = 504; t = g - 391424; oi = 3; }
    int n = t / Ce, c = t - n * Ce;
    i = (n << 9) + c; j = i + off;
}

// ---------------- valid dtype detection + normalization ---------------------
__global__ void detect_vmode_kernel(const unsigned char* __restrict__ v) {
    int t = threadIdx.x;
    int nz1 = 0, nz23 = 0;
    #pragma unroll
    for (int k = 0; k < 16; k += 4) {
        int i = t * 16 + k;
        if (v[i+1]) nz1 = 1;
        if (v[i+2] | v[i+3]) nz23 = 1;
    }
    int a1 = __syncthreads_or(nz1);
    int a23 = __syncthreads_or(nz23);
    if (t == 0) g_vmode = a1 ? 0 : (a23 ? 2 : 1);
}
// conv valid + clear pos tables in one launch (grid 4*NC/256)
__global__ void conv_clear_kernel(const unsigned char* __restrict__ v) {
    int i = blockIdx.x * 256 + threadIdx.x;
    g_posf[i] = -1;
    g_posr[i] = -1;
    if (i < NC) {
        int mode = g_vmode;
        unsigned char r;
        if (mode == 0)      r = v[i] != 0;
        else if (mode == 1) r = ((const int*)v)[i] != 0;
        else                r = ((const unsigned int*)v)[i] != 0u;
        g_valid[i] = r;
    }
}

// ---------------- weight transposes (fp16), one launch -----------------------
__global__ void transpose_all_kernel(const float* __restrict__ w1,
                                     const float* __restrict__ w2,
                                     const float* __restrict__ u1,
                                     const float* __restrict__ u2) {
    int idx = blockIdx.x * 256 + threadIdx.x;
    if (idx < 262144) {
        int n = idx >> 8, k = idx & 255;
        float s = (n < 512) ? w1[(size_t)k * 512 + n]
                            : w1[(size_t)(k + 256) * 512 + (n - 512)];
        g_wabt[idx] = __float2half(s);
    } else if (idx < 393216) {
        int t = idx - 262144;
        int n = t >> 9, k = t & 511;
        g_w2t[t] = __float2half(w2[(size_t)k * 256 + n]);
    } else if (idx < 655360) {
        int t = idx - 393216;
        int n = t >> 8, k = t & 255;
        g_u1t[t] = __float2half(u1[(size_t)k * 1024 + n]);
    } else if (idx < 917504) {
        int t = idx - 655360;
        int n = t >> 10, k = t & 1023;
        g_u2t[t] = __float2half(u2[(size_t)k * 256 + n]);
    }
}

// ---------------- compaction: count / scan / scatter -------------------------
__global__ void count_kernel() {
    int g = blockIdx.x * 256 + threadIdx.x;
    int i, j, oi; decode_edge(g, i, j, oi);
    int pred = g_valid[i] & g_valid[j];
    unsigned bal = __ballot_sync(0xffffffffu, pred);
    __shared__ int wcnt[8];
    if ((threadIdx.x & 31) == 0) wcnt[threadIdx.x >> 5] = __popc(bal);
    __syncthreads();
    if (threadIdx.x == 0) {
        int s = 0;
        #pragma unroll
        for (int k = 0; k < 8; k++) s += wcnt[k];
        g_bcount[blockIdx.x] = s;
    }
}

__global__ void scan_kernel() {
    __shared__ int part[256];
    int t = threadIdx.x;
    int base = t * 8;
    int loc[8];
    int s = 0;
    #pragma unroll
    for (int k = 0; k < 8; k++) {
        int idx = base + k;
        int v = (idx < NB) ? g_bcount[idx] : 0;
        loc[k] = s; s += v;
    }
    part[t] = s;
    __syncthreads();
    for (int o = 1; o < 256; o <<= 1) {
        int v = part[t];
        int add = (t >= o) ? part[t - o] : 0;
        __syncthreads();
        part[t] = v + add;
        __syncthreads();
    }
    int excl = part[t] - s;
    #pragma unroll
    for (int k = 0; k < 8; k++) {
        int idx = base + k;
        if (idx < 2048) g_boffs[idx] = excl + loc[k];
    }
    __syncthreads();
    if (t == 0) g_E = part[255];
}

__global__ void scatter_kernel() {
    int g = blockIdx.x * 256 + threadIdx.x;
    int lane = threadIdx.x & 31, warp = threadIdx.x >> 5;
    int i, j, oi; decode_edge(g, i, j, oi);
    int pred = g_valid[i] & g_valid[j];
    unsigned bal = __ballot_sync(0xffffffffu, pred);
    __shared__ int wcnt[8], wbase[8];
    if (lane == 0) wcnt[warp] = __popc(bal);
    __syncthreads();
    if (threadIdx.x == 0) {
        int s = 0;
        #pragma unroll
        for (int k = 0; k < 8; k++) { wbase[k] = s; s += wcnt[k]; }
    }
    __syncthreads();
    if (pred) {
        int pos = g_boffs[blockIdx.x] + wbase[warp]
                + __popc(bal & ((1u << lane) - 1u));
        g_ei[pos] = i; g_ej[pos] = j;
        g_posf[oi * NC + i] = pos;
        g_posr[oi * NC + j] = pos;
    }
}

// ---------------- gather messages + h2 residual + LN -> hu -------------------
__global__ void gather_ln_kernel(const float* __restrict__ h,
                                 const float* __restrict__ b2,
                                 const float* __restrict__ w,
                                 const float* __restrict__ b) {
    int warp = threadIdx.x >> 5, lane = threadIdx.x & 31;
    int row = blockIdx.x * 8 + warp;

    int p = -1;
    if (lane < 4)      p = g_posf[lane * NC + row];
    else if (lane < 8) p = g_posr[(lane - 4) * NC + row];

    float acc[8] = {};
    int cnt = 0;
    #pragma unroll
    for (int s = 0; s < 8; s++) {
        int ps = __shfl_sync(0xffffffffu, p, s);
        if (ps >= 0) {
            cnt++;
            const __half* Mrow = (s < 4 ? g_Mf : g_Mr) + (size_t)ps * Hdim + lane * 8;
            float f[8];
            ld8h(Mrow, f);
            #pragma unroll
            for (int k = 0; k < 8; k++) acc[k] += f[k];
        }
    }
    float cf = (float)cnt;
    const float* hr = h + (size_t)row * Hdim + lane * 8;
    const float* b2p = b2 + lane * 8;
    float4 ha = *(const float4*)hr;
    float4 hc = *(const float4*)(hr + 4);
    float hv[8] = {ha.x, ha.y, ha.z, ha.w, hc.x, hc.y, hc.z, hc.w};
    float v[8];
    #pragma unroll
    for (int k = 0; k < 8; k++) v[k] = hv[k] + acc[k] + cf * b2p[k];

    float* h2r = g_h2 + (size_t)row * Hdim + lane * 8;
    float4 o;
    o.x = v[0]; o.y = v[1]; o.z = v[2]; o.w = v[3];
    *(float4*)h2r = o;
    o.x = v[4]; o.y = v[5]; o.z = v[6]; o.w = v[7];
    *(float4*)(h2r + 4) = o;

    float s1 = 0.f, s2 = 0.f;
    #pragma unroll
    for (int k = 0; k < 8; k++) { s1 += v[k]; s2 += v[k]*v[k]; }
    #pragma unroll
    for (int ofs = 16; ofs > 0; ofs >>= 1) {
        s1 += __shfl_xor_sync(0xffffffffu, s1, ofs);
        s2 += __shfl_xor_sync(0xffffffffu, s2, ofs);
    }
    float mu = s1 * (1.0f / Hdim);
    float inv = rsqrtf(fmaxf(s2 * (1.0f / Hdim) - mu * mu, 0.f) + 1e-5f);
    const float* wp = w + lane * 8;
    const float* bp = b + lane * 8;
    float o0[4], o1[4];
    #pragma unroll
    for (int k = 0; k < 4; k++) o0[k] = (v[k]   - mu) * inv * wp[k]   + bp[k];
    #pragma unroll
    for (int k = 0; k < 4; k++) o1[k] = (v[4+k] - mu) * inv * wp[4+k] + bp[4+k];
    __half* yr = g_hu + (size_t)row * Hdim + lane * 8;
    st4h(yr, o0); st4h(yr + 4, o1);
}

// ============================================================================
// common tcgen05 helpers
// ============================================================================
__device__ __forceinline__ uint32_t smem_u32(const void* p) {
    uint32_t a;
    asm("{ .reg .u64 t; cvta.to.shared.u64 t, %1; cvt.u32.u64 %0, t; }" : "=r"(a) : "l"(p));
    return a;
}
__device__ __forceinline__ void mbar_wait(uint32_t mbar, uint32_t parity) {
    asm volatile(
        "{\n\t.reg .pred P1;\n\t"
        "W_%=:\n\t"
        "mbarrier.try_wait.parity.acquire.cta.shared::cta.b64 P1, [%0], %1, 0x989680;\n\t"
        "@P1 bra.uni D_%=;\n\t"
        "bra.uni W_%=;\n\t"
        "D_%=:\n\t}"
        :: "r"(mbar), "r"(parity) : "memory");
}

#if HAS_TC
__device__ __forceinline__ void mma_f16_ss(uint32_t d_tmem, uint64_t a_desc,
                                           uint64_t b_desc, uint32_t idesc, bool acc) {
    uint32_t en = acc ? 1u : 0u;
    asm volatile(
        "{\n\t.reg .pred p;\n\t"
        "setp.ne.u32 p, %5, 0;\n\t"
        "tcgen05.mma.cta_group::1.kind::f16 [%0], %1, %2, %3, {%4, %4, %4, %4}, p;\n\t"
        "}"
        :: "r"(d_tmem), "l"(a_desc), "l"(b_desc), "r"(idesc), "r"(0u), "r"(en)
        : "memory");
}
#define LDTM_X32(r, addr) \
    asm volatile( \
        "tcgen05.ld.sync.aligned.32x32b.x32.b32 " \
        "{%0, %1, %2, %3, %4, %5, %6, %7, " \
        " %8, %9, %10, %11, %12, %13, %14, %15, " \
        " %16, %17, %18, %19, %20, %21, %22, %23, " \
        " %24, %25, %26, %27, %28, %29, %30, %31}, [%32];" \
        : "=r"((r)[0]),  "=r"((r)[1]),  "=r"((r)[2]),  "=r"((r)[3]), \
          "=r"((r)[4]),  "=r"((r)[5]),  "=r"((r)[6]),  "=r"((r)[7]), \
          "=r"((r)[8]),  "=r"((r)[9]),  "=r"((r)[10]), "=r"((r)[11]), \
          "=r"((r)[12]), "=r"((r)[13]), "=r"((r)[14]), "=r"((r)[15]), \
          "=r"((r)[16]), "=r"((r)[17]), "=r"((r)[18]), "=r"((r)[19]), \
          "=r"((r)[20]), "=r"((r)[21]), "=r"((r)[22]), "=r"((r)[23]), \
          "=r"((r)[24]), "=r"((r)[25]), "=r"((r)[26]), "=r"((r)[27]), \
          "=r"((r)[28]), "=r"((r)[29]), "=r"((r)[30]), "=r"((r)[31]) \
        : "r"(addr))
#endif

static constexpr unsigned long long DESC_BASE =
    (2ull << 61) | (1ull << 46) | (64ull << 32) | (1ull << 16);
#define MMA_IDESC ((1u<<4) | (32u<<17) | (8u<<24))
#define SMEM_EDGE (1024 + 131072 + 128 + 2048)
#define SMEM_MLP  (1024 + 196608 + 64)
#define SMEM_PQ   (1024 + 131072 + 64)

// ============================================================================
// fused LN1 + PQ GEMM, B register-prefetched.
// ============================================================================
__global__ void __launch_bounds__(256, 1)
fused_ln_pq(const float* __restrict__ h,
            const float* __restrict__ lnw,
            const float* __restrict__ lnb,
            const __half* __restrict__ wabt,
            __half* __restrict__ PQ) {
    extern __shared__ char dyn[];
    int tid = threadIdx.x;
    int m0 = blockIdx.x * 128;
    int warp = tid >> 5, lane = tid & 31;

#if HAS_TC
    uint32_t u0 = smem_u32(dyn);
    uint32_t pad = (1024u - (u0 & 1023u)) & 1023u;
    char* base = dyn + pad;
    uint32_t ub = u0 + pad;

    uint32_t ctrl  = ub + 131072;
    uint32_t mbar0 = ctrl + 8;

    if (tid == 0) {
        asm volatile("mbarrier.init.shared.b64 [%0], 1;" :: "r"(mbar0)     : "memory");
        asm volatile("mbarrier.init.shared.b64 [%0], 1;" :: "r"(mbar0 + 8) : "memory");
    }
    if (warp == 0) {
        asm volatile("tcgen05.alloc.cta_group::1.sync.aligned.shared::cta.b32 [%0], %1;"
                     :: "r"(ctrl), "r"(512u) : "memory");
        asm volatile("tcgen05.relinquish_alloc_permit.cta_group::1.sync.aligned;");
    }
    __syncthreads();
    uint32_t tmem;
    asm volatile("ld.shared.b32 %0, [%1];" : "=r"(tmem) : "r"(ctrl));

    int rB = tid >> 3, fB = tid & 7;

    // prefetch B chunk 0 while LN prologue runs
    uint4 rbB[8];
    {
        const __half* src = wabt + (size_t)rB * Hdim + fB * 8;
        #pragma unroll
        for (int i = 0; i < 8; i++)
            rbB[i] = *(const uint4*)(src + (size_t)(i * 32) * Hdim);
    }

    {
        const float* wp = lnw + lane * 8;
        const float* bp = lnb + lane * 8;
        float wv[8], bv2[8];
        #pragma unroll
        for (int k = 0; k < 8; k += 4) {
            *(float4*)(wv+k)  = *(const float4*)(wp+k);
            *(float4*)(bv2+k) = *(const float4*)(bp+k);
        }
        for (int it = 0; it < 16; it++) {
            int rl = it * 8 + warp;
            const float* xr = h + (size_t)(m0 + rl) * Hdim + lane * 8;
            float4 a = *(const float4*)xr;
            float4 c = *(const float4*)(xr + 4);
            float v[8] = {a.x, a.y, a.z, a.w, c.x, c.y, c.z, c.w};
            float s1 = 0.f, s2 = 0.f;
            #pragma unroll
            for (int k = 0; k < 8; k++) { s1 += v[k]; s2 += v[k]*v[k]; }
            #pragma unroll
            for (int o = 16; o > 0; o >>= 1) {
                s1 += __shfl_xor_sync(0xffffffffu, s1, o);
                s2 += __shfl_xor_sync(0xffffffffu, s2, o);
            }
            float mu = s1 * (1.0f / Hdim);
            float inv = rsqrtf(fmaxf(s2 * (1.0f / Hdim) - mu * mu, 0.f) + 1e-5f);
            float o8[8];
            #pragma unroll
            for (int k = 0; k < 8; k++) o8[k] = (v[k] - mu) * inv * wv[k] + bv2[k];
            uint32_t sob = (uint32_t)(rl * 128 + (lane & 7) * 16);
            sob ^= (sob >> 3) & 0x70u;
            *(uint4*)(base + (lane >> 3) * 16384 + sob) = pack8h(o8);
        }
    }
    __syncthreads();

    int trow = (warp & 3) * 32 + lane;
    int colhalf = (warp >> 2) * 128;

    int cidx = 0;
    for (int p = 0; p < 4; p++) {
        uint32_t D = tmem + (uint32_t)((p & 1) * 256);
        for (int c = 0; c < 4; c++) {
            int buf = cidx & 1;
            if (cidx >= 2) mbar_wait(mbar0 + 8u*buf, (uint32_t)(((cidx-2) >> 1) & 1));
            char* sB = base + 65536 + buf * 32768;
            #pragma unroll
            for (int i2 = 0; i2 < 8; i2++) {
                int rr = rB + i2 * 32;
                uint32_t sob = (uint32_t)(rr * 128 + fB * 16);
                sob ^= (sob >> 3) & 0x70u;
                *(uint4*)(sB + sob) = rbB[i2];
            }
            // prefetch next chunk's B
            if (cidx + 1 < 16) {
                int nidx = cidx + 1;
                int np = nidx >> 2, nc = nidx & 3;
                const __half* src = wabt + (size_t)(np*256 + rB) * Hdim + nc*64 + fB*8;
                #pragma unroll
                for (int i = 0; i < 8; i++)
                    rbB[i] = *(const uint4*)(src + (size_t)(i * 32) * Hdim);
            }
            asm volatile("fence.proxy.async.shared::cta;" ::: "memory");
            __syncthreads();
            if (tid == 0) {
                uint32_t aaddr = ub + (uint32_t)(c * 16384);
                uint32_t baddr = ub + (uint32_t)(65536 + buf * 32768);
                uint64_t adesc = DESC_BASE | (uint64_t)((aaddr >> 4) & 0x3FFFu);
                uint64_t bdesc = DESC_BASE | (uint64_t)((baddr >> 4) & 0x3FFFu);
                #pragma unroll
                for (int s = 0; s < 4; s++)
                    mma_f16_ss(D, adesc + 2u*s, bdesc + 2u*s, MMA_IDESC, !(c == 0 && s == 0));
                asm volatile(
                    "tcgen05.commit.cta_group::1.mbarrier::arrive::one.shared::cluster.b64 [%0];"
                    :: "r"(mbar0 + 8u*buf) : "memory");
            }
            cidx++;
        }
        mbar_wait(mbar0 + 8u*((cidx-1)&1), (uint32_t)(((cidx-1) >> 1) & 1));
        mbar_wait(mbar0 + 8u*((cidx-2)&1), (uint32_t)(((cidx-2) >> 1) & 1));
        asm volatile("tcgen05.fence::after_thread_sync;" ::: "memory");

        {
            int m = m0 + trow;
            #pragma unroll
            for (int cc2 = 0; cc2 < 4; cc2++) {
                int col = colhalf + cc2 * 32;
                uint32_t r[32];
                LDTM_X32(r, D + (uint32_t)col);
                asm volatile("tcgen05.wait::ld.sync.aligned;" ::: "memory");
                #pragma unroll
                for (int q = 0; q < 32; q += 4) {
                    float o[4] = {__uint_as_float(r[q]),   __uint_as_float(r[q+1]),
                                  __uint_as_float(r[q+2]), __uint_as_float(r[q+3])};
                    st4h(PQ + (size_t)m * HU + p*256 + col + q, o);
                }
            }
        }
    }
    __syncthreads();
    if (warp == 0) {
        asm volatile("tcgen05.dealloc.cta_group::1.sync.aligned.b32 %0, %1;"
                     :: "r"(tmem), "r"(512u));
    }

#else  // -------- SIMT fallback: LN -> g_hin, then naive GEMM ------------------
    float* As = (float*)dyn;
    float* Bs = (float*)(dyn + 8192);

    for (int it = 0; it < 16; it++) {
        int rl = it * 8 + warp;
        int row = m0 + rl;
        const float* xr = h + (size_t)row * Hdim + lane * 8;
        float4 a = *(const float4*)xr;
        float4 c = *(const float4*)(xr + 4);
        float v[8] = {a.x, a.y, a.z, a.w, c.x, c.y, c.z, c.w};
        float s1 = 0.f, s2 = 0.f;
        #pragma unroll
        for (int k = 0; k < 8; k++) { s1 += v[k]; s2 += v[k]*v[k]; }
        #pragma unroll
        for (int o = 16; o > 0; o >>= 1) {
            s1 += __shfl_xor_sync(0xffffffffu, s1, o);
            s2 += __shfl_xor_sync(0xffffffffu, s2, o);
        }
        float mu = s1 * (1.0f / Hdim);
        float inv = rsqrtf(fmaxf(s2 * (1.0f / Hdim) - mu * mu, 0.f) + 1e-5f);
        float o8[8];
        #pragma unroll
        for (int k = 0; k < 8; k++)
            o8[k] = (v[k] - mu) * inv * lnw[lane*8+k] + lnb[lane*8+k];
        st4h(g_hin + (size_t)row * Hdim + lane * 8, o8);
        st4h(g_hin + (size_t)row * Hdim + lane * 8 + 4, o8 + 4);
    }
    __syncthreads();

    int tr = tid >> 4, tc = tid & 15;
    int lrow = tid >> 1;
    int lk   = (tid & 1) * 8;
    for (int half = 0; half < 8; half++) {
        int n0h = half * 128;
        float acc[8][8] = {};
        for (int k0 = 0; k0 < Hdim; k0 += 16) {
            #pragma unroll
            for (int e = 0; e < 8; e++) {
                As[(lk+e)*128 + lrow] = __half2float(g_hin[(size_t)(m0 + lrow) * Hdim + k0 + lk + e]);
                Bs[(lk+e)*128 + lrow] = __half2float(wabt[(size_t)(n0h + lrow) * Hdim + k0 + lk + e]);
            }
            __syncthreads();
            #pragma unroll
            for (int k = 0; k < 16; k++) {
                float a[8], b[8];
                #pragma unroll
                for (int i2 = 0; i2 < 8; i2++) a[i2] = As[k*128 + tr*8 + i2];
                #pragma unroll
                for (int j2 = 0; j2 < 8; j2++) b[j2] = Bs[k*128 + tc*8 + j2];
                #pragma unroll
                for (int i2 = 0; i2 < 8; i2++)
                    #pragma unroll
                    for (int j2 = 0; j2 < 8; j2++)
                        acc[i2][j2] += a[i2] * b[j2];
            }
            __syncthreads();
        }
        int col0 = n0h + tc * 8;
        #pragma unroll
        for (int i2 = 0; i2 < 8; i2++) {
            int m = m0 + tr * 8 + i2;
            for (int j2 = 0; j2 < 8; j2++)
                PQ[(size_t)m * HU + col0 + j2] = __float2half(acc[i2][j2]);
        }
        __syncthreads();
    }
#endif
}

// ============================================================================
// fused edge-message kernel (register-prefetched gathers)
// ============================================================================
__global__ void __launch_bounds__(256, 1)
edge_msg_kernel(const float* __restrict__ xyz,
                const float* __restrict__ w1,
                const float* __restrict__ b1,
                const __half* __restrict__ w2t) {
    extern __shared__ char dyn[];
    int tid = threadIdx.x;
    int m0 = blockIdx.x * 128;
    if (m0 >= g_E) return;

#if HAS_TC
    uint32_t u0 = smem_u32(dyn);
    uint32_t pad = (1024u - (u0 & 1023u)) & 1023u;
    char* base = dyn + pad;
    uint32_t ub = u0 + pad;

    uint32_t ctrl  = ub + 131072;
    uint32_t mbar0 = ctrl + 8;
    float* ef = (float*)(base + 131072 + 128);

    int wid = tid >> 5;
    int lane = tid & 31;

    if (tid == 0) {
        asm volatile("mbarrier.init.shared.b64 [%0], 1;" :: "r"(mbar0)     : "memory");
        asm volatile("mbarrier.init.shared.b64 [%0], 1;" :: "r"(mbar0 + 8) : "memory");
    }
    if (wid == 0) {
        asm volatile("tcgen05.alloc.cta_group::1.sync.aligned.shared::cta.b32 [%0], %1;"
                     :: "r"(ctrl), "r"(512u) : "memory");
        asm volatile("tcgen05.relinquish_alloc_permit.cta_group::1.sync.aligned;");
    }
    __syncthreads();
    uint32_t tmem;
    asm volatile("ld.shared.b32 %0, [%1];" : "=r"(tmem) : "r"(ctrl));

    if (tid < 128) {
        int m = m0 + tid;
        int i = g_ei[m], j = g_ej[m];
        float dx = xyz[3*j+0] - xyz[3*i+0];
        float dy = xyz[3*j+1] - xyz[3*i+1];
        float dz = xyz[3*j+2] - xyz[3*i+2];
        float d = fmaxf(sqrtf(dx*dx + dy*dy + dz*dz), 1e-6f);
        float inv = 1.0f / d;
        ef[tid*4+0] = dx*inv; ef[tid*4+1] = dy*inv; ef[tid*4+2] = dz*inv; ef[tid*4+3] = d;
    }
    __syncthreads();

    int r0 = tid >> 3, oct = tid & 7;
    uint32_t so = (uint32_t)(r0 * 128 + oct * 16);
    so ^= (so >> 3) & 0x70u;

    int ei4[4], ej4[4];
    float efr[4][4];
    #pragma unroll
    for (int it = 0; it < 4; it++) {
        int r = r0 + it * 32;
        ei4[it] = g_ei[m0 + r];
        ej4[it] = g_ej[m0 + r];
        efr[it][0] = ef[r*4+0]; efr[it][1] = ef[r*4+1];
        efr[it][2] = ef[r*4+2]; efr[it][3] = ef[r*4+3];
    }

    uint4 gp[16];
    uint4 rbB[8];
    const int NCH = 8;

    {
        int col = oct * 8;
        #pragma unroll
        for (int it = 0; it < 4; it++) {
            gp[it*4+0] = *(const uint4*)(g_PQ + (size_t)ei4[it]*HU + col);
            gp[it*4+1] = *(const uint4*)(g_PQ + (size_t)ei4[it]*HU + 512 + col);
            gp[it*4+2] = *(const uint4*)(g_PQ + (size_t)ej4[it]*HU + col);
            gp[it*4+3] = *(const uint4*)(g_PQ + (size_t)ej4[it]*HU + 512 + col);
        }
        #pragma unroll
        for (int i2 = 0; i2 < 8; i2++) {
            int idx = tid + i2 * 256;
            int rB = idx >> 3, fB = idx & 7;
            rbB[i2] = *(const uint4*)(w2t + (size_t)rB * H2 + fB * 8);
        }
    }

    for (int c = 0; c < NCH; c++) {
        int buf = c & 1;
        if (c >= 2) mbar_wait(mbar0 + 8u * buf, (uint32_t)(((c - 2) >> 1) & 1));
        char* sAf = base + buf * 65536;
        char* sAr = sAf + 16384;
        char* sB  = sAf + 32768;
        int col = (c << 6) + oct * 8;

        #pragma unroll
        for (int i2 = 0; i2 < 8; i2++) {
            int idx = tid + i2 * 256;
            int rB = idx >> 3, fB = idx & 7;
            uint32_t sob = (uint32_t)(rB * 128 + fB * 16);
            sob ^= (sob >> 3) & 0x70u;
            *(uint4*)(sB + sob) = rbB[i2];
        }

        float w0v[8], w1v[8], w2v[8], w3v[8], bbv[8];
        {
            const float* wr0 = w1 + (size_t)(2*Hdim + 0)*H2 + col;
            const float* wr1 = w1 + (size_t)(2*Hdim + 1)*H2 + col;
            const float* wr2 = w1 + (size_t)(2*Hdim + 2)*H2 + col;
            const float* wr3 = w1 + (size_t)(2*Hdim + 3)*H2 + col;
            const float* bbr = b1 + col;
            #pragma unroll
            for (int q = 0; q < 8; q += 4) {
                *(float4*)(w0v+q) = *(const float4*)(wr0+q);
                *(float4*)(w1v+q) = *(const float4*)(wr1+q);
                *(float4*)(w2v+q) = *(const float4*)(wr2+q);
                *(float4*)(w3v+q) = *(const float4*)(wr3+q);
                *(float4*)(bbv+q) = *(const float4*)(bbr+q);
            }
        }

        #pragma unroll
        for (int it = 0; it < 4; it++) {
            float pi[8], qi[8], pj[8], qj[8];
            cvt8h(gp[it*4+0], pi);
            cvt8h(gp[it*4+1], qi);
            cvt8h(gp[it*4+2], pj);
            cvt8h(gp[it*4+3], qj);
            float e0 = efr[it][0], e1 = efr[it][1], e2 = efr[it][2], e3 = efr[it][3];
            float rf[8], rr[8];
            #pragma unroll
            for (int q = 0; q < 8; q++) {
                float eu = e0*w0v[q] + e1*w1v[q] + e2*w2v[q];
                float ed = e3*w3v[q] + bbv[q];
                rf[q] = gelu_exact(pi[q] + qj[q] + eu + ed);
                rr[q] = gelu_exact(pj[q] + qi[q] - eu + ed);
            }
            *(uint4*)(sAf + so + (uint32_t)(it * 4096)) = pack8h(rf);
            *(uint4*)(sAr + so + (uint32_t)(it * 4096)) = pack8h(rr);
        }

        if (c + 1 < NCH) {
            int coln = ((c + 1) << 6) + oct * 8;
            #pragma unroll
            for (int it = 0; it < 4; it++) {
                gp[it*4+0] = *(const uint4*)(g_PQ + (size_t)ei4[it]*HU + coln);
                gp[it*4+1] = *(const uint4*)(g_PQ + (size_t)ei4[it]*HU + 512 + coln);
                gp[it*4+2] = *(const uint4*)(g_PQ + (size_t)ej4[it]*HU + coln);
                gp[it*4+3] = *(const uint4*)(g_PQ + (size_t)ej4[it]*HU + 512 + coln);
            }
            int k0n = (c + 1) << 6;
            #pragma unroll
            for (int i2 = 0; i2 < 8; i2++) {
                int idx = tid + i2 * 256;
                int rB = idx >> 3, fB = idx & 7;
                rbB[i2] = *(const uint4*)(w2t + (size_t)rB * H2 + k0n + fB * 8);
            }
        }

        asm volatile("fence.proxy.async.shared::cta;" ::: "memory");
        __syncthreads();

        if (tid == 0) {
            uint32_t afaddr = ub + (uint32_t)(buf * 65536);
            uint32_t araddr = afaddr + 16384u;
            uint32_t baddr  = afaddr + 32768u;
            uint64_t adescF = DESC_BASE | (uint64_t)((afaddr >> 4) & 0x3FFFu);
            uint64_t adescR = DESC_BASE | (uint64_t)((araddr >> 4) & 0x3FFFu);
            uint64_t bdesc  = DESC_BASE | (uint64_t)((baddr  >> 4) & 0x3FFFu);
            #pragma unroll
            for (int s = 0; s < 4; s++) {
                bool acc = !(c == 0 && s == 0);
                mma_f16_ss(tmem,        adescF + 2u*s, bdesc + 2u*s, MMA_IDESC, acc);
                mma_f16_ss(tmem + 256u, adescR + 2u*s, bdesc + 2u*s, MMA_IDESC, acc);
            }
            asm volatile(
                "tcgen05.commit.cta_group::1.mbarrier::arrive::one.shared::cluster.b64 [%0];"
                :: "r"(mbar0 + 8u * buf) : "memory");
        }
    }
    mbar_wait(mbar0 + 8u * ((NCH - 2) & 1), (uint32_t)(((NCH - 2) >> 1) & 1));
    mbar_wait(mbar0 + 8u * ((NCH - 1) & 1), (uint32_t)(((NCH - 1) >> 1) & 1));
    asm volatile("tcgen05.fence::after_thread_sync;" ::: "memory");

    {
        int dir = wid >> 2;
        int wd  = wid & 3;
        int trow = wd * 32 + lane;
        int m = m0 + trow;
        __half* M = dir ? g_Mr : g_Mf;
        uint32_t dbase = tmem + (uint32_t)(dir * 256);
        #pragma unroll
        for (int cc = 0; cc < 256; cc += 32) {
            uint32_t r[32];
            LDTM_X32(r, dbase + (uint32_t)cc);
            asm volatile("tcgen05.wait::ld.sync.aligned;" ::: "memory");
            #pragma unroll
            for (int q = 0; q < 32; q += 4) {
                float o[4] = {__uint_as_float(r[q]),   __uint_as_float(r[q+1]),
                              __uint_as_float(r[q+2]), __uint_as_float(r[q+3])};
                st4h(M + (size_t)m * Hdim + cc + q, o);
            }
        }
    }
    __syncthreads();
    if (wid == 0) {
        asm volatile("tcgen05.dealloc.cta_group::1.sync.aligned.b32 %0, %1;"
                     :: "r"(tmem), "r"(512u));
    }

#else  // -------- SIMT fallback ------------------------------------------------
    float* As = (float*)dyn;
    float* Bs = (float*)(dyn + 8192);
    float* ef = (float*)(dyn + 16384);

    if (tid < 128) {
        int m = m0 + tid;
        int i = g_ei[m], j = g_ej[m];
        float dx = xyz[3*j+0] - xyz[3*i+0];
        float dy = xyz[3*j+1] - xyz[3*i+1];
        float dz = xyz[3*j+2] - xyz[3*i+2];
        float d = fmaxf(sqrtf(dx*dx + dy*dy + dz*dz), 1e-6f);
        float inv = 1.0f / d;
        ef[tid*4+0] = dx*inv; ef[tid*4+1] = dy*inv; ef[tid*4+2] = dz*inv; ef[tid*4+3] = d;
    }
    __syncthreads();

    int tr = tid >> 4, tc = tid & 15;
    for (int dir = 0; dir < 2; dir++) {
        for (int half = 0; half < 2; half++) {
            int n0h = half * 128;
            float acc[8][8] = {};
            for (int k0 = 0; k0 < H2; k0 += 16) {
                #pragma unroll
                for (int e = 0; e < 8; e++) {
                    int idx = tid * 8 + e;
                    int kk = idx >> 7, rr2 = idx & 127;
                    int m = m0 + rr2;
                    int i = g_ei[m], j = g_ej[m];
                    int colk = k0 + kk;
                    float e0 = ef[rr2*4], e1 = ef[rr2*4+1], e2 = ef[rr2*4+2], e3 = ef[rr2*4+3];
                    float eu = e0*w1[(size_t)(2*Hdim+0)*H2+colk]
                             + e1*w1[(size_t)(2*Hdim+1)*H2+colk]
                             + e2*w1[(size_t)(2*Hdim+2)*H2+colk];
                    float ed = e3*w1[(size_t)(2*Hdim+3)*H2+colk] + b1[colk];
                    float pv, qv;
                    if (dir == 0) {
                        pv = __half2float(g_PQ[(size_t)i*HU + colk]);
                        qv = __half2float(g_PQ[(size_t)j*HU + 512 + colk]);
                        As[kk*128 + rr2] = gelu_exact(pv + qv + eu + ed);
                    } else {
                        pv = __half2float(g_PQ[(size_t)j*HU + colk]);
                        qv = __half2float(g_PQ[(size_t)i*HU + 512 + colk]);
                        As[kk*128 + rr2] = gelu_exact(pv + qv - eu + ed);
                    }
                    Bs[kk*128 + rr2] = __half2float(w2t[(size_t)(n0h + rr2) * H2 + colk]);
                }
                __syncthreads();
                #pragma unroll
                for (int k = 0; k < 16; k++) {
                    float a[8], b[8];
                    #pragma unroll
                    for (int i2 = 0; i2 < 8; i2++) a[i2] = As[k*128 + tr*8 + i2];
                    #pragma unroll
                    for (int j2 = 0; j2 < 8; j2++) b[j2] = Bs[k*128 + tc*8 + j2];
                    #pragma unroll
                    for (int i2 = 0; i2 < 8; i2++)
                        #pragma unroll
                        for (int j2 = 0; j2 < 8; j2++)
                            acc[i2][j2] += a[i2] * b[j2];
                }
                __syncthreads();
            }
            __half* M = dir ? g_Mr : g_Mf;
            int col0 = n0h + tc * 8;
            #pragma unroll
            for (int i2 = 0; i2 < 8; i2++) {
                int m = m0 + tr * 8 + i2;
                for (int j2 = 0; j2 < 8; j2++)
                    M[(size_t)m * Hdim + col0 + j2] = __float2half(acc[i2][j2]);
            }
            __syncthreads();
        }
    }
#endif
}

// ============================================================================
// fused update-MLP, B register-prefetched across GEMM1/epilogue/GEMM2.
// ============================================================================
#if HAS_TC
__device__ __forceinline__ void mlp_prefetch_B(int idx, int rB, int fB,
                                               const __half* __restrict__ u1t,
                                               const __half* __restrict__ u2t,
                                               uint4* rb) {
    int p = idx >> 3, sub = idx & 7;
    if (sub < 4) {
        const __half* src = u1t + (size_t)(p*256 + rB) * Hdim + sub*64 + fB*8;
        #pragma unroll
        for (int i = 0; i < 8; i++)
            rb[i] = *(const uint4*)(src + (size_t)(i * 32) * Hdim);
    } else {
        const __half* src = u2t + (size_t)rB * HU + p*256 + (sub-4)*64 + fB*8;
        #pragma unroll
        for (int i = 0; i < 8; i++)
            rb[i] = *(const uint4*)(src + (size_t)(i * 32) * HU);
    }
}
#endif

__global__ void __launch_bounds__(256, 1)
fused_mlp_kernel(const __half* __restrict__ u1t,
                 const __half* __restrict__ u2t,
                 const float* __restrict__ bu1,
                 const float* __restrict__ bu2,
                 float* __restrict__ out) {
    extern __shared__ char dyn[];
    int tid = threadIdx.x;
    int m0 = blockIdx.x * 128;

#if HAS_TC
    uint32_t u0 = smem_u32(dyn);
    uint32_t pad = (1024u - (u0 & 1023u)) & 1023u;
    char* base = dyn + pad;
    uint32_t ub = u0 + pad;

    uint32_t ctrl  = ub + 196608;
    uint32_t mbar0 = ctrl + 8;

    int wid = tid >> 5;
    int lane = tid & 31;

    if (tid == 0) {
        asm volatile("mbarrier.init.shared.b64 [%0], 1;" :: "r"(mbar0)     : "memory");
        asm volatile("mbarrier.init.shared.b64 [%0], 1;" :: "r"(mbar0 + 8) : "memory");
    }
    if (wid == 0) {
        asm volatile("tcgen05.alloc.cta_group::1.sync.aligned.shared::cta.b32 [%0], %1;"
                     :: "r"(ctrl), "r"(512u) : "memory");
        asm volatile("tcgen05.relinquish_alloc_permit.cta_group::1.sync.aligned;");
    }
    __syncthreads();
    uint32_t tmem;
    asm volatile("ld.shared.b32 %0, [%1];" : "=r"(tmem) : "r"(ctrl));

    int rB = tid >> 3, fB = tid & 7;

    // prefetch B idx 0 while hu tile loads
    uint4 rbB[8];
    mlp_prefetch_B(0, rB, fB, u1t, u2t, rbB);

    #pragma unroll
    for (int i2 = 0; i2 < 16; i2++) {
        int g = tid + i2 * 256;
        int r = g >> 5;
        int f = g & 31;
        uint4 v = *(const uint4*)(g_hu + (size_t)(m0 + r) * Hdim + f * 8);
        uint32_t sob = (uint32_t)(r * 128 + (f & 7) * 16);
        sob ^= (sob >> 3) & 0x70u;
        *(uint4*)(base + (f >> 3) * 16384 + sob) = v;
    }

    int trow = (wid & 3) * 32 + lane;
    int colhalf = (wid >> 2) * 128;

    uint32_t D2 = tmem;
    uint32_t D1 = tmem + 256u;

    int cidx = 0;
    for (int p = 0; p < 4; p++) {
        for (int c = 0; c < 4; c++) {
            int buf = cidx & 1;
            if (cidx >= 2) mbar_wait(mbar0 + 8u*buf, (uint32_t)(((cidx-2) >> 1) & 1));
            char* sB = base + 131072 + buf * 32768;
            #pragma unroll
            for (int i2 = 0; i2 < 8; i2++) {
                int rr = rB + i2 * 32;
                uint32_t sob = (uint32_t)(rr * 128 + fB * 16);
                sob ^= (sob >> 3) & 0x70u;
                *(uint4*)(sB + sob) = rbB[i2];
            }
            if (cidx + 1 < 32)
                mlp_prefetch_B(cidx + 1, rB, fB, u1t, u2t, rbB);
            asm volatile("fence.proxy.async.shared::cta;" ::: "memory");
            __syncthreads();
            if (tid == 0) {
                uint32_t aaddr = ub + (uint32_t)(c * 16384);
                uint32_t baddr = ub + (uint32_t)(131072 + buf * 32768);
                uint64_t adesc = DESC_BASE | (uint64_t)((aaddr >> 4) & 0x3FFFu);
                uint64_t bdesc = DESC_BASE | (uint64_t)((baddr >> 4) & 0x3FFFu);
                #pragma unroll
                for (int s = 0; s < 4; s++)
                    mma_f16_ss(D1, adesc + 2u*s, bdesc + 2u*s, MMA_IDESC, !(c == 0 && s == 0));
                asm volatile(
                    "tcgen05.commit.cta_group::1.mbarrier::arrive::one.shared::cluster.b64 [%0];"
                    :: "r"(mbar0 + 8u*buf) : "memory");
            }
            cidx++;
        }
        mbar_wait(mbar0 + 8u*((cidx-1)&1), (uint32_t)(((cidx-1) >> 1) & 1));
        mbar_wait(mbar0 + 8u*((cidx-2)&1), (uint32_t)(((cidx-2) >> 1) & 1));
        asm volatile("tcgen05.fence::after_thread_sync;" ::: "memory");

        #pragma unroll
        for (int cc2 = 0; cc2 < 4; cc2++) {
            int col = colhalf + cc2 * 32;
            uint32_t r[32];
            LDTM_X32(r, D1 + (uint32_t)col);
            asm volatile("tcgen05.wait::ld.sync.aligned;" ::: "memory");
            #pragma unroll
            for (int q = 0; q < 32; q += 8) {
                int ck = col + q;
                float o[8];
                #pragma unroll
                for (int e = 0; e < 8; e++)
                    o[e] = gelu_exact(__uint_as_float(r[q+e]) + __ldg(&bu1[p*256 + ck + e]));
                uint32_t sob = (uint32_t)(trow * 128 + ((ck >> 3) & 7) * 16);
                sob ^= (sob >> 3) & 0x70u;
                *(uint4*)(base + 65536 + (ck >> 6) * 16384 + sob) = pack8h(o);
            }
        }

        for (int c = 0; c < 4; c++) {
            int buf = cidx & 1;
            mbar_wait(mbar0 + 8u*buf, (uint32_t)(((cidx-2) >> 1) & 1));
            char* sB = base + 131072 + buf * 32768;
            #pragma unroll
            for (int i2 = 0; i2 < 8; i2++) {
                int rr = rB + i2 * 32;
                uint32_t sob = (uint32_t)(rr * 128 + fB * 16);
                sob ^= (sob >> 3) & 0x70u;
                *(uint4*)(sB + sob) = rbB[i2];
            }
            if (cidx + 1 < 32)
                mlp_prefetch_B(cidx + 1, rB, fB, u1t, u2t, rbB);
            asm volatile("fence.proxy.async.shared::cta;" ::: "memory");
            __syncthreads();
            if (tid == 0) {
                uint32_t aaddr = ub + (uint32_t)(65536 + c * 16384);
                uint32_t baddr = ub + (uint32_t)(131072 + buf * 32768);
                uint64_t adesc = DESC_BASE | (uint64_t)((aaddr >> 4) & 0x3FFFu);
                uint64_t bdesc = DESC_BASE | (uint64_t)((baddr >> 4) & 0x3FFFu);
                #pragma unroll
                for (int s = 0; s < 4; s++)
                    mma_f16_ss(D2, adesc + 2u*s, bdesc + 2u*s, MMA_IDESC,
                               !(p == 0 && c == 0 && s == 0));
                asm volatile(
                    "tcgen05.commit.cta_group::1.mbarrier::arrive::one.shared::cluster.b64 [%0];"
                    :: "r"(mbar0 + 8u*buf) : "memory");
            }
            cidx++;
        }
    }
    mbar_wait(mbar0 + 8u*((cidx-1)&1), (uint32_t)(((cidx-1) >> 1) & 1));
    mbar_wait(mbar0 + 8u*((cidx-2)&1), (uint32_t)(((cidx-2) >> 1) & 1));
    asm volatile("tcgen05.fence::after_thread_sync;" ::: "memory");

    {
        int m = m0 + trow;
        float vf = g_valid[m] ? 1.0f : 0.0f;
        #pragma unroll
        for (int cc2 = 0; cc2 < 4; cc2++) {
            int col = colhalf + cc2 * 32;
            uint32_t r[32];
            LDTM_X32(r, D2 + (uint32_t)col);
            asm volatile("tcgen05.wait::ld.sync.aligned;" ::: "memory");
            const float* a2 = g_h2 + (size_t)m * Hdim + col;
            #pragma unroll
            for (int q = 0; q < 32; q += 4) {
                float4 av = *(const float4*)(a2 + q);
                float4 o;
                o.x = (av.x + __uint_as_float(r[q])   + __ldg(&bu2[col+q]))   * vf;
                o.y = (av.y + __uint_as_float(r[q+1]) + __ldg(&bu2[col+q+1])) * vf;
                o.z = (av.z + __uint_as_float(r[q+2]) + __ldg(&bu2[col+q+2])) * vf;
                o.w = (av.w + __uint_as_float(r[q+3]) + __ldg(&bu2[col+q+3])) * vf;
                *(float4*)(out + (size_t)m * Hdim + col + q) = o;
            }
        }
    }
    __syncthreads();
    if (wid == 0) {
        asm volatile("tcgen05.dealloc.cta_group::1.sync.aligned.b32 %0, %1;"
                     :: "r"(tmem), "r"(512u));
    }

#else  // -------- SIMT fallback: two naive GEMMs staged via g_T1 --------------
    float* As = (float*)dyn;
    float* Bs = (float*)(dyn + 8192);
    int tr = tid >> 4, tc = tid & 15;
    int lrow = tid >> 1;
    int lk   = (tid & 1) * 8;

    for (int half = 0; half < 8; half++) {
        int n0h = half * 128;
        float acc[8][8] = {};
        for (int k0 = 0; k0 < Hdim; k0 += 16) {
            #pragma unroll
            for (int e = 0; e < 8; e++) {
                As[(lk+e)*128 + lrow] = __half2float(g_hu[(size_t)(m0 + lrow) * Hdim + k0 + lk + e]);
                Bs[(lk+e)*128 + lrow] = __half2float(u1t[(size_t)(n0h + lrow) * Hdim + k0 + lk + e]);
            }
            __syncthreads();
            #pragma unroll
            for (int k = 0; k < 16; k++) {
                float a[8], b[8];
                #pragma unroll
                for (int i2 = 0; i2 < 8; i2++) a[i2] = As[k*128 + tr*8 + i2];
                #pragma unroll
                for (int j2 = 0; j2 < 8; j2++) b[j2] = Bs[k*128 + tc*8 + j2];
                #pragma unroll
                for (int i2 = 0; i2 < 8; i2++)
                    #pragma unroll
                    for (int j2 = 0; j2 < 8; j2++)
                        acc[i2][j2] += a[i2] * b[j2];
            }
            __syncthreads();
        }
        int col0 = n0h + tc * 8;
        #pragma unroll
        for (int i2 = 0; i2 < 8; i2++) {
            int m = m0 + tr * 8 + i2;
            for (int j2 = 0; j2 < 8; j2++)
                g_T1[(size_t)m * HU + col0 + j2] =
                    __float2half(gelu_exact(acc[i2][j2] + bu1[col0 + j2]));
        }
        __syncthreads();
    }

    for (int half = 0; half < 2; half++) {
        int n0h = half * 128;
        float acc[8][8] = {};
        for (int k0 = 0; k0 < HU; k0 += 16) {
            #pragma unroll
            for (int e = 0; e < 8; e++) {
                As[(lk+e)*128 + lrow] = __half2float(g_T1[(size_t)(m0 + lrow) * HU + k0 + lk + e]);
                Bs[(lk+e)*128 + lrow] = __half2float(u2t[(size_t)(n0h + lrow) * HU + k0 + lk + e]);
            }
            __syncthreads();
            #pragma unroll
            for (int k = 0; k < 16; k++) {
                float a[8], b[8];
                #pragma unroll
                for (int i2 = 0; i2 < 8; i2++) a[i2] = As[k*128 + tr*8 + i2];
                #pragma unroll
                for (int j2 = 0; j2 < 8; j2++) b[j2] = Bs[k*128 + tc*8 + j2];
                #pragma unroll
                for (int i2 = 0; i2 < 8; i2++)
                    #pragma unroll
                    for (int j2 = 0; j2 < 8; j2++)
                        acc[i2][j2] += a[i2] * b[j2];
            }
            __syncthreads();
        }
        int col0 = n0h + tc * 8;
        #pragma unroll
        for (int i2 = 0; i2 < 8; i2++) {
            int m = m0 + tr * 8 + i2;
            float vf = g_valid[m] ? 1.0f : 0.0f;
            for (int j2 = 0; j2 < 8; j2++)
                out[(size_t)m * Hdim + col0 + j2] =
                    (g_h2[(size_t)m * Hdim + col0 + j2] + acc[i2][j2] + bu2[col0 + j2]) * vf;
        }
        __syncthreads();
    }
#endif
}

// ---------------- launch -----------------------------------------------------
extern "C" void kernel_launch(void* const* d_in, const int* in_sizes, int n_in,
                              void* d_out, int out_size) {
    const float*         h      = (const float*)d_in[0];
    const float*         xyz    = (const float*)d_in[1];
    const unsigned char* validb = (const unsigned char*)d_in[2];
    const float*         ln_n_w = (const float*)d_in[3];
    const float*         ln_n_b = (const float*)d_in[4];
    const float*         w1     = (const float*)d_in[5];
    const float*         b1     = (const float*)d_in[6];
    const float*         w2     = (const float*)d_in[7];
    const float*         b2     = (const float*)d_in[8];
    const float*         ln_u_w = (const float*)d_in[9];
    const float*         ln_u_b = (const float*)d_in[10];
    const float*         u1     = (const float*)d_in[11];
    const float*         bu1    = (const float*)d_in[12];
    const float*         u2     = (const float*)d_in[13];
    const float*         bu2    = (const float*)d_in[14];
    float* out = (float*)d_out;

    __half *pPQ, *pWabt, *pW2t, *pU1t, *pU2t;
    cudaGetSymbolAddress((void**)&pPQ,  g_PQ);
    cudaGetSymbolAddress((void**)&pWabt, g_wabt);
    cudaGetSymbolAddress((void**)&pW2t,  g_w2t);
    cudaGetSymbolAddress((void**)&pU1t,  g_u1t);
    cudaGetSymbolAddress((void**)&pU2t,  g_u2t);

    cudaFuncSetAttribute(fused_ln_pq, cudaFuncAttributeMaxDynamicSharedMemorySize, SMEM_PQ);
    cudaFuncSetAttribute(edge_msg_kernel, cudaFuncAttributeMaxDynamicSharedMemorySize, SMEM_EDGE);
    cudaFuncSetAttribute(fused_mlp_kernel, cudaFuncAttributeMaxDynamicSharedMemorySize, SMEM_MLP);

    detect_vmode_kernel<<<1, 256>>>(validb);
    conv_clear_kernel<<<4*NC/256, 256>>>(validb);
    transpose_all_kernel<<<917504/256, 256>>>(w1, w2, u1, u2);
    count_kernel<<<NB, 256>>>();

    // LN1 + PQ GEMM fused
    fused_ln_pq<<<NC/128, 256, SMEM_PQ>>>(h, ln_n_w, ln_n_b, pWabt, pPQ);

    scan_kernel<<<1, 256>>>();
    scatter_kernel<<<NB, 256>>>();

    edge_msg_kernel<<<MAXE/128, 256, SMEM_EDGE>>>(xyz, w1, b1, pW2t);

    gather_ln_kernel<<<NC/8, 256>>>(h, b2, ln_u_w, ln_u_b);

    fused_mlp_kernel<<<NC/128, 256, SMEM_MLP>>>(pU1t, pU2t, bu1, bu2, out);
    (void)in_sizes; (void)n_in; (void)out_size;
}

// round 16
// speedup vs baseline: 1.3289x; 1.2120x over previous
#include <cuda_runtime.h>
#include <cuda_fp16.h>
#include <math.h>
#include <stdint.h>

#define Ndim 256
#define Cdim 512
#define Hdim 256
#define NC   (Ndim*Cdim)   // 131072
#define H2   512
#define HU   1024
#define MAXE 520448
#define NB   2033          // MAXE / 256

#if defined(__CUDA_ARCH_FEAT_SM103_ALL) || defined(__CUDA_ARCH_FEAT_SM100_ALL) || \
    (defined(__CUDA_ARCH_SPECIFIC__) && (__CUDA_ARCH_SPECIFIC__ >= 1000))
#define HAS_TC 1
#else
#define HAS_TC 0
#endif

// ---------------- scratch ----------------------------------------------------
__device__ __half g_hin[(size_t)NC*Hdim];    // fallback staging only
__device__ __half g_PQ [(size_t)NC*HU];
__device__ __half g_Mf [(size_t)MAXE*Hdim];
__device__ __half g_Mr [(size_t)MAXE*Hdim];
__device__ float  g_h2 [(size_t)NC*Hdim];
__device__ __half g_hu [(size_t)NC*Hdim];
__device__ __half g_T1 [(size_t)NC*HU];      // fallback staging only
__device__ __half g_wabt[(size_t)HU*Hdim];
__device__ __half g_w2t [(size_t)Hdim*H2];
__device__ __half g_u1t [(size_t)HU*Hdim];
__device__ __half g_u2t [(size_t)Hdim*HU];
__device__ unsigned char g_valid[NC];
__device__ int g_vmode;
__device__ int g_ei[MAXE];
__device__ int g_ej[MAXE];
__device__ int g_posf[4*NC];
__device__ int g_posr[4*NC];
__device__ int g_bcount[2048];
__device__ int g_boffs[2048];
__device__ int g_E;

// fast GELU: tanh form + tanh.approx.f32 (sm_75+ MUFU).
// |tanh-form - exact| <= ~3e-4 abs; tanh.approx rel err ~2^-10.9 — both at/below
// the fp16 rounding these values already receive.
__device__ __forceinline__ float gelu_fast(float x) {
    float t = 0.7978845608028654f * fmaf(0.044715f * x, x * x, x);
    float th;
    asm("tanh.approx.f32 %0, %1;" : "=f"(th) : "f"(t));
    return 0.5f * x * (1.0f + th);
}
__device__ __forceinline__ void st4h(__half* p, const float* f) {
    uint2 u;
    *(__half2*)&u.x = __float22half2_rn(make_float2(f[0], f[1]));
    *(__half2*)&u.y = __float22half2_rn(make_float2(f[2], f[3]));
    *(uint2*)p = u;
}
__device__ __forceinline__ void ld8h(const __half* p, float* f) {
    uint4 u = *(const uint4*)p;
    float2 a = __half22float2(*(__half2*)&u.x);
    float2 b = __half22float2(*(__half2*)&u.y);
    float2 c = __half22float2(*(__half2*)&u.z);
    float2 d = __half22float2(*(__half2*)&u.w);
    f[0]=a.x; f[1]=a.y; f[2]=b.x; f[3]=b.y; f[4]=c.x; f[5]=c.y; f[6]=d.x; f[7]=d.y;
}
__device__ __forceinline__ void cvt8h(const uint4& u, float* f) {
    float2 a = __half22float2(*(__half2*)&u.x);
    float2 b = __half22float2(*(__half2*)&u.y);
    float2 c = __half22float2(*(__half2*)&u.z);
    float2 d = __half22float2(*(__half2*)&u.w);
    f[0]=a.x; f[1]=a.y; f[2]=b.x; f[3]=b.y; f[4]=c.x; f[5]=c.y; f[6]=d.x; f[7]=d.y;
}
__device__ __forceinline__ uint4 pack8h(const float* f) {
    uint4 u;
    *(__half2*)&u.x = __float22half2_rn(make_float2(f[0], f[1]));
    *(__half2*)&u.y = __float22half2_rn(make_float2(f[2], f[3]));
    *(__half2*)&u.z = __float22half2_rn(make_float2(f[4], f[5]));
    *(__half2*)&u.w = __float22half2_rn(make_float2(f[6], f[7]));
    return u;
}

__device__ __forceinline__ void decode_edge(int g, int& i, int& j, int& oi) {
    int off, Ce, t;
    if (g < 130816)      { off = 1; Ce = 511; t = g;          oi = 0; }
    else if (g < 261376) { off = 2; Ce = 510; t = g - 130816; oi = 1; }
    else if (g < 391424) { off = 4; Ce = 508; t = g - 261376; oi = 2; }
    else                 { off = 8; Ce = 504; t = g - 391424; oi = 3; }
    int n = t / Ce, c = t - n * Ce;
    i = (n << 9) + c; j = i + off;
}

// ---------------- valid dtype detection + normalization ---------------------
__global__ void detect_vmode_kernel(const unsigned char* __restrict__ v) {
    int t = threadIdx.x;
    int nz1 = 0, nz23 = 0;
    #pragma unroll
    for (int k = 0; k < 16; k += 4) {
        int i = t * 16 + k;
        if (v[i+1]) nz1 = 1;
        if (v[i+2] | v[i+3]) nz23 = 1;
    }
    int a1 = __syncthreads_or(nz1);
    int a23 = __syncthreads_or(nz23);
    if (t == 0) g_vmode = a1 ? 0 : (a23 ? 2 : 1);
}
__global__ void conv_clear_kernel(const unsigned char* __restrict__ v) {
    int i = blockIdx.x * 256 + threadIdx.x;
    g_posf[i] = -1;
    g_posr[i] = -1;
    if (i < NC) {
        int mode = g_vmode;
        unsigned char r;
        if (mode == 0)      r = v[i] != 0;
        else if (mode == 1) r = ((const int*)v)[i] != 0;
        else                r = ((const unsigned int*)v)[i] != 0u;
        g_valid[i] = r;
    }
}

// ---------------- weight transposes (fp16), one launch -----------------------
__global__ void transpose_all_kernel(const float* __restrict__ w1,
                                     const float* __restrict__ w2,
                                     const float* __restrict__ u1,
                                     const float* __restrict__ u2) {
    int idx = blockIdx.x * 256 + threadIdx.x;
    if (idx < 262144) {
        int n = idx >> 8, k = idx & 255;
        float s = (n < 512) ? w1[(size_t)k * 512 + n]
                            : w1[(size_t)(k + 256) * 512 + (n - 512)];
        g_wabt[idx] = __float2half(s);
    } else if (idx < 393216) {
        int t = idx - 262144;
        int n = t >> 9, k = t & 511;
        g_w2t[t] = __float2half(w2[(size_t)k * 256 + n]);
    } else if (idx < 655360) {
        int t = idx - 393216;
        int n = t >> 8, k = t & 255;
        g_u1t[t] = __float2half(u1[(size_t)k * 1024 + n]);
    } else if (idx < 917504) {
        int t = idx - 655360;
        int n = t >> 10, k = t & 1023;
        g_u2t[t] = __float2half(u2[(size_t)k * 256 + n]);
    }
}

// ---------------- compaction: count / scan / scatter -------------------------
__global__ void count_kernel() {
    int g = blockIdx.x * 256 + threadIdx.x;
    int i, j, oi; decode_edge(g, i, j, oi);
    int pred = g_valid[i] & g_valid[j];
    unsigned bal = __ballot_sync(0xffffffffu, pred);
    __shared__ int wcnt[8];
    if ((threadIdx.x & 31) == 0) wcnt[threadIdx.x >> 5] = __popc(bal);
    __syncthreads();
    if (threadIdx.x == 0) {
        int s = 0;
        #pragma unroll
        for (int k = 0; k < 8; k++) s += wcnt[k];
        g_bcount[blockIdx.x] = s;
    }
}

__global__ void scan_kernel() {
    __shared__ int part[256];
    int t = threadIdx.x;
    int base = t * 8;
    int loc[8];
    int s = 0;
    #pragma unroll
    for (int k = 0; k < 8; k++) {
        int idx = base + k;
        int v = (idx < NB) ? g_bcount[idx] : 0;
        loc[k] = s; s += v;
    }
    part[t] = s;
    __syncthreads();
    for (int o = 1; o < 256; o <<= 1) {
        int v = part[t];
        int add = (t >= o) ? part[t - o] : 0;
        __syncthreads();
        part[t] = v + add;
        __syncthreads();
    }
    int excl = part[t] - s;
    #pragma unroll
    for (int k = 0; k < 8; k++) {
        int idx = base + k;
        if (idx < 2048) g_boffs[idx] = excl + loc[k];
    }
    __syncthreads();
    if (t == 0) g_E = part[255];
}

__global__ void scatter_kernel() {
    int g = blockIdx.x * 256 + threadIdx.x;
    int lane = threadIdx.x & 31, warp = threadIdx.x >> 5;
    int i, j, oi; decode_edge(g, i, j, oi);
    int pred = g_valid[i] & g_valid[j];
    unsigned bal = __ballot_sync(0xffffffffu, pred);
    __shared__ int wcnt[8], wbase[8];
    if (lane == 0) wcnt[warp] = __popc(bal);
    __syncthreads();
    if (threadIdx.x == 0) {
        int s = 0;
        #pragma unroll
        for (int k = 0; k < 8; k++) { wbase[k] = s; s += wcnt[k]; }
    }
    __syncthreads();
    if (pred) {
        int pos = g_boffs[blockIdx.x] + wbase[warp]
                + __popc(bal & ((1u << lane) - 1u));
        g_ei[pos] = i; g_ej[pos] = j;
        g_posf[oi * NC + i] = pos;
        g_posr[oi * NC + j] = pos;
    }
}

// ---------------- gather messages + h2 residual + LN -> hu -------------------
__global__ void gather_ln_kernel(const float* __restrict__ h,
                                 const float* __restrict__ b2,
                                 const float* __restrict__ w,
                                 const float* __restrict__ b) {
    int warp = threadIdx.x >> 5, lane = threadIdx.x & 31;
    int row = blockIdx.x * 8 + warp;

    int p = -1;
    if (lane < 4)      p = g_posf[lane * NC + row];
    else if (lane < 8) p = g_posr[(lane - 4) * NC + row];

    float acc[8] = {};
    int cnt = 0;
    #pragma unroll
    for (int s = 0; s < 8; s++) {
        int ps = __shfl_sync(0xffffffffu, p, s);
        if (ps >= 0) {
            cnt++;
            const __half* Mrow = (s < 4 ? g_Mf : g_Mr) + (size_t)ps * Hdim + lane * 8;
            float f[8];
            ld8h(Mrow, f);
            #pragma unroll
            for (int k = 0; k < 8; k++) acc[k] += f[k];
        }
    }
    float cf = (float)cnt;
    const float* hr = h + (size_t)row * Hdim + lane * 8;
    const float* b2p = b2 + lane * 8;
    float4 ha = *(const float4*)hr;
    float4 hc = *(const float4*)(hr + 4);
    float hv[8] = {ha.x, ha.y, ha.z, ha.w, hc.x, hc.y, hc.z, hc.w};
    float v[8];
    #pragma unroll
    for (int k = 0; k < 8; k++) v[k] = hv[k] + acc[k] + cf * b2p[k];

    float* h2r = g_h2 + (size_t)row * Hdim + lane * 8;
    float4 o;
    o.x = v[0]; o.y = v[1]; o.z = v[2]; o.w = v[3];
    *(float4*)h2r = o;
    o.x = v[4]; o.y = v[5]; o.z = v[6]; o.w = v[7];
    *(float4*)(h2r + 4) = o;

    float s1 = 0.f, s2 = 0.f;
    #pragma unroll
    for (int k = 0; k < 8; k++) { s1 += v[k]; s2 += v[k]*v[k]; }
    #pragma unroll
    for (int ofs = 16; ofs > 0; ofs >>= 1) {
        s1 += __shfl_xor_sync(0xffffffffu, s1, ofs);
        s2 += __shfl_xor_sync(0xffffffffu, s2, ofs);
    }
    float mu = s1 * (1.0f / Hdim);
    float inv = rsqrtf(fmaxf(s2 * (1.0f / Hdim) - mu * mu, 0.f) + 1e-5f);
    const float* wp = w + lane * 8;
    const float* bp = b + lane * 8;
    float o0[4], o1[4];
    #pragma unroll
    for (int k = 0; k < 4; k++) o0[k] = (v[k]   - mu) * inv * wp[k]   + bp[k];
    #pragma unroll
    for (int k = 0; k < 4; k++) o1[k] = (v[4+k] - mu) * inv * wp[4+k] + bp[4+k];
    __half* yr = g_hu + (size_t)row * Hdim + lane * 8;
    st4h(yr, o0); st4h(yr + 4, o1);
}

// ============================================================================
// common tcgen05 helpers
// ============================================================================
__device__ __forceinline__ uint32_t smem_u32(const void* p) {
    uint32_t a;
    asm("{ .reg .u64 t; cvta.to.shared.u64 t, %1; cvt.u32.u64 %0, t; }" : "=r"(a) : "l"(p));
    return a;
}
__device__ __forceinline__ void mbar_wait(uint32_t mbar, uint32_t parity) {
    asm volatile(
        "{\n\t.reg .pred P1;\n\t"
        "W_%=:\n\t"
        "mbarrier.try_wait.parity.acquire.cta.shared::cta.b64 P1, [%0], %1, 0x989680;\n\t"
        "@P1 bra.uni D_%=;\n\t"
        "bra.uni W_%=;\n\t"
        "D_%=:\n\t}"
        :: "r"(mbar), "r"(parity) : "memory");
}

#if HAS_TC
__device__ __forceinline__ void mma_f16_ss(uint32_t d_tmem, uint64_t a_desc,
                                           uint64_t b_desc, uint32_t idesc, bool acc) {
    uint32_t en = acc ? 1u : 0u;
    asm volatile(
        "{\n\t.reg .pred p;\n\t"
        "setp.ne.u32 p, %5, 0;\n\t"
        "tcgen05.mma.cta_group::1.kind::f16 [%0], %1, %2, %3, {%4, %4, %4, %4}, p;\n\t"
        "}"
        :: "r"(d_tmem), "l"(a_desc), "l"(b_desc), "r"(idesc), "r"(0u), "r"(en)
        : "memory");
}
#define LDTM_X32(r, addr) \
    asm volatile( \
        "tcgen05.ld.sync.aligned.32x32b.x32.b32 " \
        "{%0, %1, %2, %3, %4, %5, %6, %7, " \
        " %8, %9, %10, %11, %12, %13, %14, %15, " \
        " %16, %17, %18, %19, %20, %21, %22, %23, " \
        " %24, %25, %26, %27, %28, %29, %30, %31}, [%32];" \
        : "=r"((r)[0]),  "=r"((r)[1]),  "=r"((r)[2]),  "=r"((r)[3]), \
          "=r"((r)[4]),  "=r"((r)[5]),  "=r"((r)[6]),  "=r"((r)[7]), \
          "=r"((r)[8]),  "=r"((r)[9]),  "=r"((r)[10]), "=r"((r)[11]), \
          "=r"((r)[12]), "=r"((r)[13]), "=r"((r)[14]), "=r"((r)[15]), \
          "=r"((r)[16]), "=r"((r)[17]), "=r"((r)[18]), "=r"((r)[19]), \
          "=r"((r)[20]), "=r"((r)[21]), "=r"((r)[22]), "=r"((r)[23]), \
          "=r"((r)[24]), "=r"((r)[25]), "=r"((r)[26]), "=r"((r)[27]), \
          "=r"((r)[28]), "=r"((r)[29]), "=r"((r)[30]), "=r"((r)[31]) \
        : "r"(addr))
#endif

static constexpr unsigned long long DESC_BASE =
    (2ull << 61) | (1ull << 46) | (64ull << 32) | (1ull << 16);
#define MMA_IDESC ((1u<<4) | (32u<<17) | (8u<<24))
#define SMEM_EDGE (1024 + 131072 + 128 + 2048)
#define SMEM_MLP  (1024 + 196608 + 64)
#define SMEM_PQ   (1024 + 131072 + 64)

// ============================================================================
// fused LN1 + PQ GEMM, B register-prefetched.
// ============================================================================
__global__ void __launch_bounds__(256, 1)
fused_ln_pq(const float* __restrict__ h,
            const float* __restrict__ lnw,
            const float* __restrict__ lnb,
            const __half* __restrict__ wabt,
            __half* __restrict__ PQ) {
    extern __shared__ char dyn[];
    int tid = threadIdx.x;
    int m0 = blockIdx.x * 128;
    int warp = tid >> 5, lane = tid & 31;

#if HAS_TC
    uint32_t u0 = smem_u32(dyn);
    uint32_t pad = (1024u - (u0 & 1023u)) & 1023u;
    char* base = dyn + pad;
    uint32_t ub = u0 + pad;

    uint32_t ctrl  = ub + 131072;
    uint32_t mbar0 = ctrl + 8;

    if (tid == 0) {
        asm volatile("mbarrier.init.shared.b64 [%0], 1;" :: "r"(mbar0)     : "memory");
        asm volatile("mbarrier.init.shared.b64 [%0], 1;" :: "r"(mbar0 + 8) : "memory");
    }
    if (warp == 0) {
        asm volatile("tcgen05.alloc.cta_group::1.sync.aligned.shared::cta.b32 [%0], %1;"
                     :: "r"(ctrl), "r"(512u) : "memory");
        asm volatile("tcgen05.relinquish_alloc_permit.cta_group::1.sync.aligned;");
    }
    __syncthreads();
    uint32_t tmem;
    asm volatile("ld.shared.b32 %0, [%1];" : "=r"(tmem) : "r"(ctrl));

    int rB = tid >> 3, fB = tid & 7;

    uint4 rbB[8];
    {
        const __half* src = wabt + (size_t)rB * Hdim + fB * 8;
        #pragma unroll
        for (int i = 0; i < 8; i++)
            rbB[i] = *(const uint4*)(src + (size_t)(i * 32) * Hdim);
    }

    {
        const float* wp = lnw + lane * 8;
        const float* bp = lnb + lane * 8;
        float wv[8], bv2[8];
        #pragma unroll
        for (int k = 0; k < 8; k += 4) {
            *(float4*)(wv+k)  = *(const float4*)(wp+k);
            *(float4*)(bv2+k) = *(const float4*)(bp+k);
        }
        for (int it = 0; it < 16; it++) {
            int rl = it * 8 + warp;
            const float* xr = h + (size_t)(m0 + rl) * Hdim + lane * 8;
            float4 a = *(const float4*)xr;
            float4 c = *(const float4*)(xr + 4);
            float v[8] = {a.x, a.y, a.z, a.w, c.x, c.y, c.z, c.w};
            float s1 = 0.f, s2 = 0.f;
            #pragma unroll
            for (int k = 0; k < 8; k++) { s1 += v[k]; s2 += v[k]*v[k]; }
            #pragma unroll
            for (int o = 16; o > 0; o >>= 1) {
                s1 += __shfl_xor_sync(0xffffffffu, s1, o);
                s2 += __shfl_xor_sync(0xffffffffu, s2, o);
            }
            float mu = s1 * (1.0f / Hdim);
            float inv = rsqrtf(fmaxf(s2 * (1.0f / Hdim) - mu * mu, 0.f) + 1e-5f);
            float o8[8];
            #pragma unroll
            for (int k = 0; k < 8; k++) o8[k] = (v[k] - mu) * inv * wv[k] + bv2[k];
            uint32_t sob = (uint32_t)(rl * 128 + (lane & 7) * 16);
            sob ^= (sob >> 3) & 0x70u;
            *(uint4*)(base + (lane >> 3) * 16384 + sob) = pack8h(o8);
        }
    }
    __syncthreads();

    int trow = (warp & 3) * 32 + lane;
    int colhalf = (warp >> 2) * 128;

    int cidx = 0;
    for (int p = 0; p < 4; p++) {
        uint32_t D = tmem + (uint32_t)((p & 1) * 256);
        for (int c = 0; c < 4; c++) {
            int buf = cidx & 1;
            if (cidx >= 2) mbar_wait(mbar0 + 8u*buf, (uint32_t)(((cidx-2) >> 1) & 1));
            char* sB = base + 65536 + buf * 32768;
            #pragma unroll
            for (int i2 = 0; i2 < 8; i2++) {
                int rr = rB + i2 * 32;
                uint32_t sob = (uint32_t)(rr * 128 + fB * 16);
                sob ^= (sob >> 3) & 0x70u;
                *(uint4*)(sB + sob) = rbB[i2];
            }
            if (cidx + 1 < 16) {
                int nidx = cidx + 1;
                int np = nidx >> 2, nc = nidx & 3;
                const __half* src = wabt + (size_t)(np*256 + rB) * Hdim + nc*64 + fB*8;
                #pragma unroll
                for (int i = 0; i < 8; i++)
                    rbB[i] = *(const uint4*)(src + (size_t)(i * 32) * Hdim);
            }
            asm volatile("fence.proxy.async.shared::cta;" ::: "memory");
            __syncthreads();
            if (tid == 0) {
                uint32_t aaddr = ub + (uint32_t)(c * 16384);
                uint32_t baddr = ub + (uint32_t)(65536 + buf * 32768);
                uint64_t adesc = DESC_BASE | (uint64_t)((aaddr >> 4) & 0x3FFFu);
                uint64_t bdesc = DESC_BASE | (uint64_t)((baddr >> 4) & 0x3FFFu);
                #pragma unroll
                for (int s = 0; s < 4; s++)
                    mma_f16_ss(D, adesc + 2u*s, bdesc + 2u*s, MMA_IDESC, !(c == 0 && s == 0));
                asm volatile(
                    "tcgen05.commit.cta_group::1.mbarrier::arrive::one.shared::cluster.b64 [%0];"
                    :: "r"(mbar0 + 8u*buf) : "memory");
            }
            cidx++;
        }
        mbar_wait(mbar0 + 8u*((cidx-1)&1), (uint32_t)(((cidx-1) >> 1) & 1));
        mbar_wait(mbar0 + 8u*((cidx-2)&1), (uint32_t)(((cidx-2) >> 1) & 1));
        asm volatile("tcgen05.fence::after_thread_sync;" ::: "memory");

        {
            int m = m0 + trow;
            #pragma unroll
            for (int cc2 = 0; cc2 < 4; cc2++) {
                int col = colhalf + cc2 * 32;
                uint32_t r[32];
                LDTM_X32(r, D + (uint32_t)col);
                asm volatile("tcgen05.wait::ld.sync.aligned;" ::: "memory");
                #pragma unroll
                for (int q = 0; q < 32; q += 4) {
                    float o[4] = {__uint_as_float(r[q]),   __uint_as_float(r[q+1]),
                                  __uint_as_float(r[q+2]), __uint_as_float(r[q+3])};
                    st4h(PQ + (size_t)m * HU + p*256 + col + q, o);
                }
            }
        }
    }
    __syncthreads();
    if (warp == 0) {
        asm volatile("tcgen05.dealloc.cta_group::1.sync.aligned.b32 %0, %1;"
                     :: "r"(tmem), "r"(512u));
    }

#else  // -------- SIMT fallback: LN -> g_hin, then naive GEMM ------------------
    float* As = (float*)dyn;
    float* Bs = (float*)(dyn + 8192);

    for (int it = 0; it < 16; it++) {
        int rl = it * 8 + warp;
        int row = m0 + rl;
        const float* xr = h + (size_t)row * Hdim + lane * 8;
        float4 a = *(const float4*)xr;
        float4 c = *(const float4*)(xr + 4);
        float v[8] = {a.x, a.y, a.z, a.w, c.x, c.y, c.z, c.w};
        float s1 = 0.f, s2 = 0.f;
        #pragma unroll
        for (int k = 0; k < 8; k++) { s1 += v[k]; s2 += v[k]*v[k]; }
        #pragma unroll
        for (int o = 16; o > 0; o >>= 1) {
            s1 += __shfl_xor_sync(0xffffffffu, s1, o);
            s2 += __shfl_xor_sync(0xffffffffu, s2, o);
        }
        float mu = s1 * (1.0f / Hdim);
        float inv = rsqrtf(fmaxf(s2 * (1.0f / Hdim) - mu * mu, 0.f) + 1e-5f);
        float o8[8];
        #pragma unroll
        for (int k = 0; k < 8; k++)
            o8[k] = (v[k] - mu) * inv * lnw[lane*8+k] + lnb[lane*8+k];
        st4h(g_hin + (size_t)row * Hdim + lane * 8, o8);
        st4h(g_hin + (size_t)row * Hdim + lane * 8 + 4, o8 + 4);
    }
    __syncthreads();

    int tr = tid >> 4, tc = tid & 15;
    int lrow = tid >> 1;
    int lk   = (tid & 1) * 8;
    for (int half = 0; half < 8; half++) {
        int n0h = half * 128;
        float acc[8][8] = {};
        for (int k0 = 0; k0 < Hdim; k0 += 16) {
            #pragma unroll
            for (int e = 0; e < 8; e++) {
                As[(lk+e)*128 + lrow] = __half2float(g_hin[(size_t)(m0 + lrow) * Hdim + k0 + lk + e]);
                Bs[(lk+e)*128 + lrow] = __half2float(wabt[(size_t)(n0h + lrow) * Hdim + k0 + lk + e]);
            }
            __syncthreads();
            #pragma unroll
            for (int k = 0; k < 16; k++) {
                float a[8], b[8];
                #pragma unroll
                for (int i2 = 0; i2 < 8; i2++) a[i2] = As[k*128 + tr*8 + i2];
                #pragma unroll
                for (int j2 = 0; j2 < 8; j2++) b[j2] = Bs[k*128 + tc*8 + j2];
                #pragma unroll
                for (int i2 = 0; i2 < 8; i2++)
                    #pragma unroll
                    for (int j2 = 0; j2 < 8; j2++)
                        acc[i2][j2] += a[i2] * b[j2];
            }
            __syncthreads();
        }
        int col0 = n0h + tc * 8;
        #pragma unroll
        for (int i2 = 0; i2 < 8; i2++) {
            int m = m0 + tr * 8 + i2;
            for (int j2 = 0; j2 < 8; j2++)
                PQ[(size_t)m * HU + col0 + j2] = __float2half(acc[i2][j2]);
        }
        __syncthreads();
    }
#endif
}

// ============================================================================
// fused edge-message kernel (register-prefetched gathers, fast gelu)
// ============================================================================
__global__ void __launch_bounds__(256, 1)
edge_msg_kernel(const float* __restrict__ xyz,
                const float* __restrict__ w1,
                const float* __restrict__ b1,
                const __half* __restrict__ w2t) {
    extern __shared__ char dyn[];
    int tid = threadIdx.x;
    int m0 = blockIdx.x * 128;
    if (m0 >= g_E) return;

#if HAS_TC
    uint32_t u0 = smem_u32(dyn);
    uint32_t pad = (1024u - (u0 & 1023u)) & 1023u;
    char* base = dyn + pad;
    uint32_t ub = u0 + pad;

    uint32_t ctrl  = ub + 131072;
    uint32_t mbar0 = ctrl + 8;
    float* ef = (float*)(base + 131072 + 128);

    int wid = tid >> 5;
    int lane = tid & 31;

    if (tid == 0) {
        asm volatile("mbarrier.init.shared.b64 [%0], 1;" :: "r"(mbar0)     : "memory");
        asm volatile("mbarrier.init.shared.b64 [%0], 1;" :: "r"(mbar0 + 8) : "memory");
    }
    if (wid == 0) {
        asm volatile("tcgen05.alloc.cta_group::1.sync.aligned.shared::cta.b32 [%0], %1;"
                     :: "r"(ctrl), "r"(512u) : "memory");
        asm volatile("tcgen05.relinquish_alloc_permit.cta_group::1.sync.aligned;");
    }
    __syncthreads();
    uint32_t tmem;
    asm volatile("ld.shared.b32 %0, [%1];" : "=r"(tmem) : "r"(ctrl));

    if (tid < 128) {
        int m = m0 + tid;
        int i = g_ei[m], j = g_ej[m];
        float dx = xyz[3*j+0] - xyz[3*i+0];
        float dy = xyz[3*j+1] - xyz[3*i+1];
        float dz = xyz[3*j+2] - xyz[3*i+2];
        float d = fmaxf(sqrtf(dx*dx + dy*dy + dz*dz), 1e-6f);
        float inv = 1.0f / d;
        ef[tid*4+0] = dx*inv; ef[tid*4+1] = dy*inv; ef[tid*4+2] = dz*inv; ef[tid*4+3] = d;
    }
    __syncthreads();

    int r0 = tid >> 3, oct = tid & 7;
    uint32_t so = (uint32_t)(r0 * 128 + oct * 16);
    so ^= (so >> 3) & 0x70u;

    int ei4[4], ej4[4];
    float efr[4][4];
    #pragma unroll
    for (int it = 0; it < 4; it++) {
        int r = r0 + it * 32;
        ei4[it] = g_ei[m0 + r];
        ej4[it] = g_ej[m0 + r];
        efr[it][0] = ef[r*4+0]; efr[it][1] = ef[r*4+1];
        efr[it][2] = ef[r*4+2]; efr[it][3] = ef[r*4+3];
    }

    uint4 gp[16];
    uint4 rbB[8];
    const int NCH = 8;

    {
        int col = oct * 8;
        #pragma unroll
        for (int it = 0; it < 4; it++) {
            gp[it*4+0] = *(const uint4*)(g_PQ + (size_t)ei4[it]*HU + col);
            gp[it*4+1] = *(const uint4*)(g_PQ + (size_t)ei4[it]*HU + 512 + col);
            gp[it*4+2] = *(const uint4*)(g_PQ + (size_t)ej4[it]*HU + col);
            gp[it*4+3] = *(const uint4*)(g_PQ + (size_t)ej4[it]*HU + 512 + col);
        }
        #pragma unroll
        for (int i2 = 0; i2 < 8; i2++) {
            int idx = tid + i2 * 256;
            int rB = idx >> 3, fB = idx & 7;
            rbB[i2] = *(const uint4*)(w2t + (size_t)rB * H2 + fB * 8);
        }
    }

    for (int c = 0; c < NCH; c++) {
        int buf = c & 1;
        if (c >= 2) mbar_wait(mbar0 + 8u * buf, (uint32_t)(((c - 2) >> 1) & 1));
        char* sAf = base + buf * 65536;
        char* sAr = sAf + 16384;
        char* sB  = sAf + 32768;
        int col = (c << 6) + oct * 8;

        #pragma unroll
        for (int i2 = 0; i2 < 8; i2++) {
            int idx = tid + i2 * 256;
            int rB = idx >> 3, fB = idx & 7;
            uint32_t sob = (uint32_t)(rB * 128 + fB * 16);
            sob ^= (sob >> 3) & 0x70u;
            *(uint4*)(sB + sob) = rbB[i2];
        }

        float w0v[8], w1v[8], w2v[8], w3v[8], bbv[8];
        {
            const float* wr0 = w1 + (size_t)(2*Hdim + 0)*H2 + col;
            const float* wr1 = w1 + (size_t)(2*Hdim + 1)*H2 + col;
            const float* wr2 = w1 + (size_t)(2*Hdim + 2)*H2 + col;
            const float* wr3 = w1 + (size_t)(2*Hdim + 3)*H2 + col;
            const float* bbr = b1 + col;
            #pragma unroll
            for (int q = 0; q < 8; q += 4) {
                *(float4*)(w0v+q) = *(const float4*)(wr0+q);
                *(float4*)(w1v+q) = *(const float4*)(wr1+q);
                *(float4*)(w2v+q) = *(const float4*)(wr2+q);
                *(float4*)(w3v+q) = *(const float4*)(wr3+q);
                *(float4*)(bbv+q) = *(const float4*)(bbr+q);
            }
        }

        #pragma unroll
        for (int it = 0; it < 4; it++) {
            float pi[8], qi[8], pj[8], qj[8];
            cvt8h(gp[it*4+0], pi);
            cvt8h(gp[it*4+1], qi);
            cvt8h(gp[it*4+2], pj);
            cvt8h(gp[it*4+3], qj);
            float e0 = efr[it][0], e1 = efr[it][1], e2 = efr[it][2], e3 = efr[it][3];
            float rf[8], rr[8];
            #pragma unroll
            for (int q = 0; q < 8; q++) {
                float eu = e0*w0v[q] + e1*w1v[q] + e2*w2v[q];
                float ed = e3*w3v[q] + bbv[q];
                rf[q] = gelu_fast(pi[q] + qj[q] + eu + ed);
                rr[q] = gelu_fast(pj[q] + qi[q] - eu + ed);
            }
            *(uint4*)(sAf + so + (uint32_t)(it * 4096)) = pack8h(rf);
            *(uint4*)(sAr + so + (uint32_t)(it * 4096)) = pack8h(rr);
        }

        if (c + 1 < NCH) {
            int coln = ((c + 1) << 6) + oct * 8;
            #pragma unroll
            for (int it = 0; it < 4; it++) {
                gp[it*4+0] = *(const uint4*)(g_PQ + (size_t)ei4[it]*HU + coln);
                gp[it*4+1] = *(const uint4*)(g_PQ + (size_t)ei4[it]*HU + 512 + coln);
                gp[it*4+2] = *(const uint4*)(g_PQ + (size_t)ej4[it]*HU + coln);
                gp[it*4+3] = *(const uint4*)(g_PQ + (size_t)ej4[it]*HU + 512 + coln);
            }
            int k0n = (c + 1) << 6;
            #pragma unroll
            for (int i2 = 0; i2 < 8; i2++) {
                int idx = tid + i2 * 256;
                int rB = idx >> 3, fB = idx & 7;
                rbB[i2] = *(const uint4*)(w2t + (size_t)rB * H2 + k0n + fB * 8);
            }
        }

        asm volatile("fence.proxy.async.shared::cta;" ::: "memory");
        __syncthreads();

        if (tid == 0) {
            uint32_t afaddr = ub + (uint32_t)(buf * 65536);
            uint32_t araddr = afaddr + 16384u;
            uint32_t baddr  = afaddr + 32768u;
            uint64_t adescF = DESC_BASE | (uint64_t)((afaddr >> 4) & 0x3FFFu);
            uint64_t adescR = DESC_BASE | (uint64_t)((araddr >> 4) & 0x3FFFu);
            uint64_t bdesc  = DESC_BASE | (uint64_t)((baddr  >> 4) & 0x3FFFu);
            #pragma unroll
            for (int s = 0; s < 4; s++) {
                bool acc = !(c == 0 && s == 0);
                mma_f16_ss(tmem,        adescF + 2u*s, bdesc + 2u*s, MMA_IDESC, acc);
                mma_f16_ss(tmem + 256u, adescR + 2u*s, bdesc + 2u*s, MMA_IDESC, acc);
            }
            asm volatile(
                "tcgen05.commit.cta_group::1.mbarrier::arrive::one.shared::cluster.b64 [%0];"
                :: "r"(mbar0 + 8u * buf) : "memory");
        }
    }
    mbar_wait(mbar0 + 8u * ((NCH - 2) & 1), (uint32_t)(((NCH - 2) >> 1) & 1));
    mbar_wait(mbar0 + 8u * ((NCH - 1) & 1), (uint32_t)(((NCH - 1) >> 1) & 1));
    asm volatile("tcgen05.fence::after_thread_sync;" ::: "memory");

    {
        int dir = wid >> 2;
        int wd  = wid & 3;
        int trow = wd * 32 + lane;
        int m = m0 + trow;
        __half* M = dir ? g_Mr : g_Mf;
        uint32_t dbase = tmem + (uint32_t)(dir * 256);
        #pragma unroll
        for (int cc = 0; cc < 256; cc += 32) {
            uint32_t r[32];
            LDTM_X32(r, dbase + (uint32_t)cc);
            asm volatile("tcgen05.wait::ld.sync.aligned;" ::: "memory");
            #pragma unroll
            for (int q = 0; q < 32; q += 4) {
                float o[4] = {__uint_as_float(r[q]),   __uint_as_float(r[q+1]),
                              __uint_as_float(r[q+2]), __uint_as_float(r[q+3])};
                st4h(M + (size_t)m * Hdim + cc + q, o);
            }
        }
    }
    __syncthreads();
    if (wid == 0) {
        asm volatile("tcgen05.dealloc.cta_group::1.sync.aligned.b32 %0, %1;"
                     :: "r"(tmem), "r"(512u));
    }

#else  // -------- SIMT fallback ------------------------------------------------
    float* As = (float*)dyn;
    float* Bs = (float*)(dyn + 8192);
    float* ef = (float*)(dyn + 16384);

    if (tid < 128) {
        int m = m0 + tid;
        int i = g_ei[m], j = g_ej[m];
        float dx = xyz[3*j+0] - xyz[3*i+0];
        float dy = xyz[3*j+1] - xyz[3*i+1];
        float dz = xyz[3*j+2] - xyz[3*i+2];
        float d = fmaxf(sqrtf(dx*dx + dy*dy + dz*dz), 1e-6f);
        float inv = 1.0f / d;
        ef[tid*4+0] = dx*inv; ef[tid*4+1] = dy*inv; ef[tid*4+2] = dz*inv; ef[tid*4+3] = d;
    }
    __syncthreads();

    int tr = tid >> 4, tc = tid & 15;
    for (int dir = 0; dir < 2; dir++) {
        for (int half = 0; half < 2; half++) {
            int n0h = half * 128;
            float acc[8][8] = {};
            for (int k0 = 0; k0 < H2; k0 += 16) {
                #pragma unroll
                for (int e = 0; e < 8; e++) {
                    int idx = tid * 8 + e;
                    int kk = idx >> 7, rr2 = idx & 127;
                    int m = m0 + rr2;
                    int i = g_ei[m], j = g_ej[m];
                    int colk = k0 + kk;
                    float e0 = ef[rr2*4], e1 = ef[rr2*4+1], e2 = ef[rr2*4+2], e3 = ef[rr2*4+3];
                    float eu = e0*w1[(size_t)(2*Hdim+0)*H2+colk]
                             + e1*w1[(size_t)(2*Hdim+1)*H2+colk]
                             + e2*w1[(size_t)(2*Hdim+2)*H2+colk];
                    float ed = e3*w1[(size_t)(2*Hdim+3)*H2+colk] + b1[colk];
                    float pv, qv;
                    if (dir == 0) {
                        pv = __half2float(g_PQ[(size_t)i*HU + colk]);
                        qv = __half2float(g_PQ[(size_t)j*HU + 512 + colk]);
                        As[kk*128 + rr2] = gelu_fast(pv + qv + eu + ed);
                    } else {
                        pv = __half2float(g_PQ[(size_t)j*HU + colk]);
                        qv = __half2float(g_PQ[(size_t)i*HU + 512 + colk]);
                        As[kk*128 + rr2] = gelu_fast(pv + qv - eu + ed);
                    }
                    Bs[kk*128 + rr2] = __half2float(w2t[(size_t)(n0h + rr2) * H2 + colk]);
                }
                __syncthreads();
                #pragma unroll
                for (int k = 0; k < 16; k++) {
                    float a[8], b[8];
                    #pragma unroll
                    for (int i2 = 0; i2 < 8; i2++) a[i2] = As[k*128 + tr*8 + i2];
                    #pragma unroll
                    for (int j2 = 0; j2 < 8; j2++) b[j2] = Bs[k*128 + tc*8 + j2];
                    #pragma unroll
                    for (int i2 = 0; i2 < 8; i2++)
                        #pragma unroll
                        for (int j2 = 0; j2 < 8; j2++)
                            acc[i2][j2] += a[i2] * b[j2];
                }
                __syncthreads();
            }
            __half* M = dir ? g_Mr : g_Mf;
            int col0 = n0h + tc * 8;
            #pragma unroll
            for (int i2 = 0; i2 < 8; i2++) {
                int m = m0 + tr * 8 + i2;
                for (int j2 = 0; j2 < 8; j2++)
                    M[(size_t)m * Hdim + col0 + j2] = __float2half(acc[i2][j2]);
            }
            __syncthreads();
        }
    }
#endif
}

// ============================================================================
// fused update-MLP, B register-prefetched, fast gelu epilogue.
// ============================================================================
#if HAS_TC
__device__ __forceinline__ void mlp_prefetch_B(int idx, int rB, int fB,
                                               const __half* __restrict__ u1t,
                                               const __half* __restrict__ u2t,
                                               uint4* rb) {
    int p = idx >> 3, sub = idx & 7;
    if (sub < 4) {
        const __half* src = u1t + (size_t)(p*256 + rB) * Hdim + sub*64 + fB*8;
        #pragma unroll
        for (int i = 0; i < 8; i++)
            rb[i] = *(const uint4*)(src + (size_t)(i * 32) * Hdim);
    } else {
        const __half* src = u2t + (size_t)rB * HU + p*256 + (sub-4)*64 + fB*8;
        #pragma unroll
        for (int i = 0; i < 8; i++)
            rb[i] = *(const uint4*)(src + (size_t)(i * 32) * HU);
    }
}
#endif

__global__ void __launch_bounds__(256, 1)
fused_mlp_kernel(const __half* __restrict__ u1t,
                 const __half* __restrict__ u2t,
                 const float* __restrict__ bu1,
                 const float* __restrict__ bu2,
                 float* __restrict__ out) {
    extern __shared__ char dyn[];
    int tid = threadIdx.x;
    int m0 = blockIdx.x * 128;

#if HAS_TC
    uint32_t u0 = smem_u32(dyn);
    uint32_t pad = (1024u - (u0 & 1023u)) & 1023u;
    char* base = dyn + pad;
    uint32_t ub = u0 + pad;

    uint32_t ctrl  = ub + 196608;
    uint32_t mbar0 = ctrl + 8;

    int wid = tid >> 5;
    int lane = tid & 31;

    if (tid == 0) {
        asm volatile("mbarrier.init.shared.b64 [%0], 1;" :: "r"(mbar0)     : "memory");
        asm volatile("mbarrier.init.shared.b64 [%0], 1;" :: "r"(mbar0 + 8) : "memory");
    }
    if (wid == 0) {
        asm volatile("tcgen05.alloc.cta_group::1.sync.aligned.shared::cta.b32 [%0], %1;"
                     :: "r"(ctrl), "r"(512u) : "memory");
        asm volatile("tcgen05.relinquish_alloc_permit.cta_group::1.sync.aligned;");
    }
    __syncthreads();
    uint32_t tmem;
    asm volatile("ld.shared.b32 %0, [%1];" : "=r"(tmem) : "r"(ctrl));

    int rB = tid >> 3, fB = tid & 7;

    uint4 rbB[8];
    mlp_prefetch_B(0, rB, fB, u1t, u2t, rbB);

    #pragma unroll
    for (int i2 = 0; i2 < 16; i2++) {
        int g = tid + i2 * 256;
        int r = g >> 5;
        int f = g & 31;
        uint4 v = *(const uint4*)(g_hu + (size_t)(m0 + r) * Hdim + f * 8);
        uint32_t sob = (uint32_t)(r * 128 + (f & 7) * 16);
        sob ^= (sob >> 3) & 0x70u;
        *(uint4*)(base + (f >> 3) * 16384 + sob) = v;
    }

    int trow = (wid & 3) * 32 + lane;
    int colhalf = (wid >> 2) * 128;

    uint32_t D2 = tmem;
    uint32_t D1 = tmem + 256u;

    int cidx = 0;
    for (int p = 0; p < 4; p++) {
        for (int c = 0; c < 4; c++) {
            int buf = cidx & 1;
            if (cidx >= 2) mbar_wait(mbar0 + 8u*buf, (uint32_t)(((cidx-2) >> 1) & 1));
            char* sB = base + 131072 + buf * 32768;
            #pragma unroll
            for (int i2 = 0; i2 < 8; i2++) {
                int rr = rB + i2 * 32;
                uint32_t sob = (uint32_t)(rr * 128 + fB * 16);
                sob ^= (sob >> 3) & 0x70u;
                *(uint4*)(sB + sob) = rbB[i2];
            }
            if (cidx + 1 < 32)
                mlp_prefetch_B(cidx + 1, rB, fB, u1t, u2t, rbB);
            asm volatile("fence.proxy.async.shared::cta;" ::: "memory");
            __syncthreads();
            if (tid == 0) {
                uint32_t aaddr = ub + (uint32_t)(c * 16384);
                uint32_t baddr = ub + (uint32_t)(131072 + buf * 32768);
                uint64_t adesc = DESC_BASE | (uint64_t)((aaddr >> 4) & 0x3FFFu);
                uint64_t bdesc = DESC_BASE | (uint64_t)((baddr >> 4) & 0x3FFFu);
                #pragma unroll
                for (int s = 0; s < 4; s++)
                    mma_f16_ss(D1, adesc + 2u*s, bdesc + 2u*s, MMA_IDESC, !(c == 0 && s == 0));
                asm volatile(
                    "tcgen05.commit.cta_group::1.mbarrier::arrive::one.shared::cluster.b64 [%0];"
                    :: "r"(mbar0 + 8u*buf) : "memory");
            }
            cidx++;
        }
        mbar_wait(mbar0 + 8u*((cidx-1)&1), (uint32_t)(((cidx-1) >> 1) & 1));
        mbar_wait(mbar0 + 8u*((cidx-2)&1), (uint32_t)(((cidx-2) >> 1) & 1));
        asm volatile("tcgen05.fence::after_thread_sync;" ::: "memory");

        #pragma unroll
        for (int cc2 = 0; cc2 < 4; cc2++) {
            int col = colhalf + cc2 * 32;
            uint32_t r[32];
            LDTM_X32(r, D1 + (uint32_t)col);
            asm volatile("tcgen05.wait::ld.sync.aligned;" ::: "memory");
            #pragma unroll
            for (int q = 0; q < 32; q += 8) {
                int ck = col + q;
                float o[8];
                #pragma unroll
                for (int e = 0; e < 8; e++)
                    o[e] = gelu_fast(__uint_as_float(r[q+e]) + __ldg(&bu1[p*256 + ck + e]));
                uint32_t sob = (uint32_t)(trow * 128 + ((ck >> 3) & 7) * 16);
                sob ^= (sob >> 3) & 0x70u;
                *(uint4*)(base + 65536 + (ck >> 6) * 16384 + sob) = pack8h(o);
            }
        }

        for (int c = 0; c < 4; c++) {
            int buf = cidx & 1;
            mbar_wait(mbar0 + 8u*buf, (uint32_t)(((cidx-2) >> 1) & 1));
            char* sB = base + 131072 + buf * 32768;
            #pragma unroll
            for (int i2 = 0; i2 < 8; i2++) {
                int rr = rB + i2 * 32;
                uint32_t sob = (uint32_t)(rr * 128 + fB * 16);
                sob ^= (sob >> 3) & 0x70u;
                *(uint4*)(sB + sob) = rbB[i2];
            }
            if (cidx + 1 < 32)
                mlp_prefetch_B(cidx + 1, rB, fB, u1t, u2t, rbB);
            asm volatile("fence.proxy.async.shared::cta;" ::: "memory");
            __syncthreads();
            if (tid == 0) {
                uint32_t aaddr = ub + (uint32_t)(65536 + c * 16384);
                uint32_t baddr = ub + (uint32_t)(131072 + buf * 32768);
                uint64_t adesc = DESC_BASE | (uint64_t)((aaddr >> 4) & 0x3FFFu);
                uint64_t bdesc = DESC_BASE | (uint64_t)((baddr >> 4) & 0x3FFFu);
                #pragma unroll
                for (int s = 0; s < 4; s++)
                    mma_f16_ss(D2, adesc + 2u*s, bdesc + 2u*s, MMA_IDESC,
                               !(p == 0 && c == 0 && s == 0));
                asm volatile(
                    "tcgen05.commit.cta_group::1.mbarrier::arrive::one.shared::cluster.b64 [%0];"
                    :: "r"(mbar0 + 8u*buf) : "memory");
            }
            cidx++;
        }
    }
    mbar_wait(mbar0 + 8u*((cidx-1)&1), (uint32_t)(((cidx-1) >> 1) & 1));
    mbar_wait(mbar0 + 8u*((cidx-2)&1), (uint32_t)(((cidx-2) >> 1) & 1));
    asm volatile("tcgen05.fence::after_thread_sync;" ::: "memory");

    {
        int m = m0 + trow;
        float vf = g_valid[m] ? 1.0f : 0.0f;
        #pragma unroll
        for (int cc2 = 0; cc2 < 4; cc2++) {
            int col = colhalf + cc2 * 32;
            uint32_t r[32];
            LDTM_X32(r, D2 + (uint32_t)col);
            asm volatile("tcgen05.wait::ld.sync.aligned;" ::: "memory");
            const float* a2 = g_h2 + (size_t)m * Hdim + col;
            #pragma unroll
            for (int q = 0; q < 32; q += 4) {
                float4 av = *(const float4*)(a2 + q);
                float4 o;
                o.x = (av.x + __uint_as_float(r[q])   + __ldg(&bu2[col+q]))   * vf;
                o.y = (av.y + __uint_as_float(r[q+1]) + __ldg(&bu2[col+q+1])) * vf;
                o.z = (av.z + __uint_as_float(r[q+2]) + __ldg(&bu2[col+q+2])) * vf;
                o.w = (av.w + __uint_as_float(r[q+3]) + __ldg(&bu2[col+q+3])) * vf;
                *(float4*)(out + (size_t)m * Hdim + col + q) = o;
            }
        }
    }
    __syncthreads();
    if (wid == 0) {
        asm volatile("tcgen05.dealloc.cta_group::1.sync.aligned.b32 %0, %1;"
                     :: "r"(tmem), "r"(512u));
    }

#else  // -------- SIMT fallback: two naive GEMMs staged via g_T1 --------------
    float* As = (float*)dyn;
    float* Bs = (float*)(dyn + 8192);
    int tr = tid >> 4, tc = tid & 15;
    int lrow = tid >> 1;
    int lk   = (tid & 1) * 8;

    for (int half = 0; half < 8; half++) {
        int n0h = half * 128;
        float acc[8][8] = {};
        for (int k0 = 0; k0 < Hdim; k0 += 16) {
            #pragma unroll
            for (int e = 0; e < 8; e++) {
                As[(lk+e)*128 + lrow] = __half2float(g_hu[(size_t)(m0 + lrow) * Hdim + k0 + lk + e]);
                Bs[(lk+e)*128 + lrow] = __half2float(u1t[(size_t)(n0h + lrow) * Hdim + k0 + lk + e]);
            }
            __syncthreads();
            #pragma unroll
            for (int k = 0; k < 16; k++) {
                float a[8], b[8];
                #pragma unroll
                for (int i2 = 0; i2 < 8; i2++) a[i2] = As[k*128 + tr*8 + i2];
                #pragma unroll
                for (int j2 = 0; j2 < 8; j2++) b[j2] = Bs[k*128 + tc*8 + j2];
                #pragma unroll
                for (int i2 = 0; i2 < 8; i2++)
                    #pragma unroll
                    for (int j2 = 0; j2 < 8; j2++)
                        acc[i2][j2] += a[i2] * b[j2];
            }
            __syncthreads();
        }
        int col0 = n0h + tc * 8;
        #pragma unroll
        for (int i2 = 0; i2 < 8; i2++) {
            int m = m0 + tr * 8 + i2;
            for (int j2 = 0; j2 < 8; j2++)
                g_T1[(size_t)m * HU + col0 + j2] =
                    __float2half(gelu_fast(acc[i2][j2] + bu1[col0 + j2]));
        }
        __syncthreads();
    }

    for (int half = 0; half < 2; half++) {
        int n0h = half * 128;
        float acc[8][8] = {};
        for (int k0 = 0; k0 < HU; k0 += 16) {
            #pragma unroll
            for (int e = 0; e < 8; e++) {
                As[(lk+e)*128 + lrow] = __half2float(g_T1[(size_t)(m0 + lrow) * HU + k0 + lk + e]);
                Bs[(lk+e)*128 + lrow] = __half2float(u2t[(size_t)(n0h + lrow) * HU + k0 + lk + e]);
            }
            __syncthreads();
            #pragma unroll
            for (int k = 0; k < 16; k++) {
                float a[8], b[8];
                #pragma unroll
                for (int i2 = 0; i2 < 8; i2++) a[i2] = As[k*128 + tr*8 + i2];
                #pragma unroll
                for (int j2 = 0; j2 < 8; j2++) b[j2] = Bs[k*128 + tc*8 + j2];
                #pragma unroll
                for (int i2 = 0; i2 < 8; i2++)
                    #pragma unroll
                    for (int j2 = 0; j2 < 8; j2++)
                        acc[i2][j2] += a[i2] * b[j2];
            }
            __syncthreads();
        }
        int col0 = n0h + tc * 8;
        #pragma unroll
        for (int i2 = 0; i2 < 8; i2++) {
            int m = m0 + tr * 8 + i2;
            float vf = g_valid[m] ? 1.0f : 0.0f;
            for (int j2 = 0; j2 < 8; j2++)
                out[(size_t)m * Hdim + col0 + j2] =
                    (g_h2[(size_t)m * Hdim + col0 + j2] + acc[i2][j2] + bu2[col0 + j2]) * vf;
        }
        __syncthreads();
    }
#endif
}

// ---------------- launch -----------------------------------------------------
extern "C" void kernel_launch(void* const* d_in, const int* in_sizes, int n_in,
                              void* d_out, int out_size) {
    const float*         h      = (const float*)d_in[0];
    const float*         xyz    = (const float*)d_in[1];
    const unsigned char* validb = (const unsigned char*)d_in[2];
    const float*         ln_n_w = (const float*)d_in[3];
    const float*         ln_n_b = (const float*)d_in[4];
    const float*         w1     = (const float*)d_in[5];
    const float*         b1     = (const float*)d_in[6];
    const float*         w2     = (const float*)d_in[7];
    const float*         b2     = (const float*)d_in[8];
    const float*         ln_u_w = (const float*)d_in[9];
    const float*         ln_u_b = (const float*)d_in[10];
    const float*         u1     = (const float*)d_in[11];
    const float*         bu1    = (const float*)d_in[12];
    const float*         u2     = (const float*)d_in[13];
    const float*         bu2    = (const float*)d_in[14];
    float* out = (float*)d_out;

    __half *pPQ, *pWabt, *pW2t, *pU1t, *pU2t;
    cudaGetSymbolAddress((void**)&pPQ,  g_PQ);
    cudaGetSymbolAddress((void**)&pWabt, g_wabt);
    cudaGetSymbolAddress((void**)&pW2t,  g_w2t);
    cudaGetSymbolAddress((void**)&pU1t,  g_u1t);
    cudaGetSymbolAddress((void**)&pU2t,  g_u2t);

    cudaFuncSetAttribute(fused_ln_pq, cudaFuncAttributeMaxDynamicSharedMemorySize, SMEM_PQ);
    cudaFuncSetAttribute(edge_msg_kernel, cudaFuncAttributeMaxDynamicSharedMemorySize, SMEM_EDGE);
    cudaFuncSetAttribute(fused_mlp_kernel, cudaFuncAttributeMaxDynamicSharedMemorySize, SMEM_MLP);

    detect_vmode_kernel<<<1, 256>>>(validb);
    conv_clear_kernel<<<4*NC/256, 256>>>(validb);
    transpose_all_kernel<<<917504/256, 256>>>(w1, w2, u1, u2);
    count_kernel<<<NB, 256>>>();

    fused_ln_pq<<<NC/128, 256, SMEM_PQ>>>(h, ln_n_w, ln_n_b, pWabt, pPQ);

    scan_kernel<<<1, 256>>>();
    scatter_kernel<<<NB, 256>>>();

    edge_msg_kernel<<<MAXE/128, 256, SMEM_EDGE>>>(xyz, w1, b1, pW2t);

    gather_ln_kernel<<<NC/8, 256>>>(h, b2, ln_u_w, ln_u_b);

    fused_mlp_kernel<<<NC/128, 256, SMEM_MLP>>>(pU1t, pU2t, bu1, bu2, out);
    (void)in_sizes; (void)n_in; (void)out_size;
}

// round 17
// speedup vs baseline: 1.3429x; 1.0105x over previous
#include <cuda_runtime.h>
#include <cuda_fp16.h>
#include <math.h>
#include <stdint.h>

#define Ndim 256
#define Cdim 512
#define Hdim 256
#define NC   (Ndim*Cdim)   // 131072
#define H2   512
#define HU   1024
#define MAXE 520448
#define NB   2033          // MAXE / 256

#if defined(__CUDA_ARCH_FEAT_SM103_ALL) || defined(__CUDA_ARCH_FEAT_SM100_ALL) || \
    (defined(__CUDA_ARCH_SPECIFIC__) && (__CUDA_ARCH_SPECIFIC__ >= 1000))
#define HAS_TC 1
#else
#define HAS_TC 0
#endif

// ---------------- scratch ----------------------------------------------------
__device__ __half g_hin[(size_t)NC*Hdim];    // fallback staging only
__device__ __half g_PQ [(size_t)NC*HU];
__device__ __half g_Mf [(size_t)MAXE*Hdim];
__device__ __half g_Mr [(size_t)MAXE*Hdim];
__device__ float  g_h2 [(size_t)NC*Hdim];
__device__ __half g_hu [(size_t)NC*Hdim];
__device__ __half g_T1 [(size_t)NC*HU];      // fallback staging only
__device__ __half g_wabt[(size_t)HU*Hdim];
__device__ __half g_w2t [(size_t)Hdim*H2];
__device__ __half g_u1t [(size_t)HU*Hdim];
__device__ __half g_u2t [(size_t)Hdim*HU];
__device__ unsigned char g_valid[NC];
__device__ int g_vmode;
__device__ int g_ei[MAXE];
__device__ int g_ej[MAXE];
__device__ int g_posf[4*NC];
__device__ int g_posr[4*NC];
__device__ int g_bcount[2048];
__device__ int g_boffs[2048];
__device__ int g_E;

// fast GELU (fp32 tanh form, for fallback paths)
__device__ __forceinline__ float gelu_fast(float x) {
    float t = 0.7978845608028654f * fmaf(0.044715f * x, x * x, x);
    float th;
    asm("tanh.approx.f32 %0, %1;" : "=f"(th) : "f"(t));
    return 0.5f * x * (1.0f + th);
}
// packed-half2 GELU: sums stay fp32 upstream; rounding to fp16 happens here
// instead of one instruction later (output was stored fp16 anyway).
__device__ __forceinline__ __half2 gelu_h2(__half2 x) {
    __half2 x2 = __hmul2(x, x);
    __half2 inner = __hfma2(__hmul2(__float2half2_rn(0.044715f), x), x2, x);
    __half2 t = __hmul2(__float2half2_rn(0.7978845608f), inner);
    uint32_t thb;
    asm("tanh.approx.f16x2 %0, %1;" : "=r"(thb) : "r"(*(uint32_t*)&t));
    __half2 th = *(__half2*)&thb;
    __half2 halfx = __hmul2(__float2half2_rn(0.5f), x);
    return __hmul2(halfx, __hadd2(th, __float2half2_rn(1.0f)));
}
__device__ __forceinline__ void st4h(__half* p, const float* f) {
    uint2 u;
    *(__half2*)&u.x = __float22half2_rn(make_float2(f[0], f[1]));
    *(__half2*)&u.y = __float22half2_rn(make_float2(f[2], f[3]));
    *(uint2*)p = u;
}
__device__ __forceinline__ void ld8h(const __half* p, float* f) {
    uint4 u = *(const uint4*)p;
    float2 a = __half22float2(*(__half2*)&u.x);
    float2 b = __half22float2(*(__half2*)&u.y);
    float2 c = __half22float2(*(__half2*)&u.z);
    float2 d = __half22float2(*(__half2*)&u.w);
    f[0]=a.x; f[1]=a.y; f[2]=b.x; f[3]=b.y; f[4]=c.x; f[5]=c.y; f[6]=d.x; f[7]=d.y;
}
__device__ __forceinline__ void cvt8h(const uint4& u, float* f) {
    float2 a = __half22float2(*(__half2*)&u.x);
    float2 b = __half22float2(*(__half2*)&u.y);
    float2 c = __half22float2(*(__half2*)&u.z);
    float2 d = __half22float2(*(__half2*)&u.w);
    f[0]=a.x; f[1]=a.y; f[2]=b.x; f[3]=b.y; f[4]=c.x; f[5]=c.y; f[6]=d.x; f[7]=d.y;
}
__device__ __forceinline__ uint4 pack8h(const float* f) {
    uint4 u;
    *(__half2*)&u.x = __float22half2_rn(make_float2(f[0], f[1]));
    *(__half2*)&u.y = __float22half2_rn(make_float2(f[2], f[3]));
    *(__half2*)&u.z = __float22half2_rn(make_float2(f[4], f[5]));
    *(__half2*)&u.w = __float22half2_rn(make_float2(f[6], f[7]));
    return u;
}
// gelu over 8 fp32 sums -> packed uint4 of 8 halves
__device__ __forceinline__ uint4 gelu8_pack(const float* s) {
    uint4 u;
    __half2* h = (__half2*)&u;
    #pragma unroll
    for (int q = 0; q < 4; q++)
        h[q] = gelu_h2(__floats2half2_rn(s[2*q], s[2*q+1]));
    return u;
}

__device__ __forceinline__ void decode_edge(int g, int& i, int& j, int& oi) {
    int off, Ce, t;
    if (g < 130816)      { off = 1; Ce = 511; t = g;          oi = 0; }
    else if (g < 261376) { off = 2; Ce = 510; t = g - 130816; oi = 1; }
    else if (g < 391424) { off = 4; Ce = 508; t = g - 261376; oi = 2; }
    else                 { off = 8; Ce = 504; t = g - 391424; oi = 3; }
    int n = t / Ce, c = t - n * Ce;
    i = (n << 9) + c; j = i + off;
}

// ---------------- valid dtype detection + normalization ---------------------
__global__ void detect_vmode_kernel(const unsigned char* __restrict__ v) {
    int t = threadIdx.x;
    int nz1 = 0, nz23 = 0;
    #pragma unroll
    for (int k = 0; k < 16; k += 4) {
        int i = t * 16 + k;
        if (v[i+1]) nz1 = 1;
        if (v[i+2] | v[i+3]) nz23 = 1;
    }
    int a1 = __syncthreads_or(nz1);
    int a23 = __syncthreads_or(nz23);
    if (t == 0) g_vmode = a1 ? 0 : (a23 ? 2 : 1);
}
__global__ void conv_clear_kernel(const unsigned char* __restrict__ v) {
    int i = blockIdx.x * 256 + threadIdx.x;
    g_posf[i] = -1;
    g_posr[i] = -1;
    if (i < NC) {
        int mode = g_vmode;
        unsigned char r;
        if (mode == 0)      r = v[i] != 0;
        else if (mode == 1) r = ((const int*)v)[i] != 0;
        else                r = ((const unsigned int*)v)[i] != 0u;
        g_valid[i] = r;
    }
}

// ---------------- weight transposes (fp16), one launch -----------------------
__global__ void transpose_all_kernel(const float* __restrict__ w1,
                                     const float* __restrict__ w2,
                                     const float* __restrict__ u1,
                                     const float* __restrict__ u2) {
    int idx = blockIdx.x * 256 + threadIdx.x;
    if (idx < 262144) {
        int n = idx >> 8, k = idx & 255;
        float s = (n < 512) ? w1[(size_t)k * 512 + n]
                            : w1[(size_t)(k + 256) * 512 + (n - 512)];
        g_wabt[idx] = __float2half(s);
    } else if (idx < 393216) {
        int t = idx - 262144;
        int n = t >> 9, k = t & 511;
        g_w2t[t] = __float2half(w2[(size_t)k * 256 + n]);
    } else if (idx < 655360) {
        int t = idx - 393216;
        int n = t >> 8, k = t & 255;
        g_u1t[t] = __float2half(u1[(size_t)k * 1024 + n]);
    } else if (idx < 917504) {
        int t = idx - 655360;
        int n = t >> 10, k = t & 1023;
        g_u2t[t] = __float2half(u2[(size_t)k * 256 + n]);
    }
}

// ---------------- compaction: count / scan / scatter -------------------------
__global__ void count_kernel() {
    int g = blockIdx.x * 256 + threadIdx.x;
    int i, j, oi; decode_edge(g, i, j, oi);
    int pred = g_valid[i] & g_valid[j];
    unsigned bal = __ballot_sync(0xffffffffu, pred);
    __shared__ int wcnt[8];
    if ((threadIdx.x & 31) == 0) wcnt[threadIdx.x >> 5] = __popc(bal);
    __syncthreads();
    if (threadIdx.x == 0) {
        int s = 0;
        #pragma unroll
        for (int k = 0; k < 8; k++) s += wcnt[k];
        g_bcount[blockIdx.x] = s;
    }
}

__global__ void scan_kernel() {
    __shared__ int part[256];
    int t = threadIdx.x;
    int base = t * 8;
    int loc[8];
    int s = 0;
    #pragma unroll
    for (int k = 0; k < 8; k++) {
        int idx = base + k;
        int v = (idx < NB) ? g_bcount[idx] : 0;
        loc[k] = s; s += v;
    }
    part[t] = s;
    __syncthreads();
    for (int o = 1; o < 256; o <<= 1) {
        int v = part[t];
        int add = (t >= o) ? part[t - o] : 0;
        __syncthreads();
        part[t] = v + add;
        __syncthreads();
    }
    int excl = part[t] - s;
    #pragma unroll
    for (int k = 0; k < 8; k++) {
        int idx = base + k;
        if (idx < 2048) g_boffs[idx] = excl + loc[k];
    }
    __syncthreads();
    if (t == 0) g_E = part[255];
}

__global__ void scatter_kernel() {
    int g = blockIdx.x * 256 + threadIdx.x;
    int lane = threadIdx.x & 31, warp = threadIdx.x >> 5;
    int i, j, oi; decode_edge(g, i, j, oi);
    int pred = g_valid[i] & g_valid[j];
    unsigned bal = __ballot_sync(0xffffffffu, pred);
    __shared__ int wcnt[8], wbase[8];
    if (lane == 0) wcnt[warp] = __popc(bal);
    __syncthreads();
    if (threadIdx.x == 0) {
        int s = 0;
        #pragma unroll
        for (int k = 0; k < 8; k++) { wbase[k] = s; s += wcnt[k]; }
    }
    __syncthreads();
    if (pred) {
        int pos = g_boffs[blockIdx.x] + wbase[warp]
                + __popc(bal & ((1u << lane) - 1u));
        g_ei[pos] = i; g_ej[pos] = j;
        g_posf[oi * NC + i] = pos;
        g_posr[oi * NC + j] = pos;
    }
}

// ---------------- gather messages + h2 residual + LN -> hu -------------------
__global__ void gather_ln_kernel(const float* __restrict__ h,
                                 const float* __restrict__ b2,
                                 const float* __restrict__ w,
                                 const float* __restrict__ b) {
    int warp = threadIdx.x >> 5, lane = threadIdx.x & 31;
    int row = blockIdx.x * 8 + warp;

    int p = -1;
    if (lane < 4)      p = g_posf[lane * NC + row];
    else if (lane < 8) p = g_posr[(lane - 4) * NC + row];

    float acc[8] = {};
    int cnt = 0;
    #pragma unroll
    for (int s = 0; s < 8; s++) {
        int ps = __shfl_sync(0xffffffffu, p, s);
        if (ps >= 0) {
            cnt++;
            const __half* Mrow = (s < 4 ? g_Mf : g_Mr) + (size_t)ps * Hdim + lane * 8;
            float f[8];
            ld8h(Mrow, f);
            #pragma unroll
            for (int k = 0; k < 8; k++) acc[k] += f[k];
        }
    }
    float cf = (float)cnt;
    const float* hr = h + (size_t)row * Hdim + lane * 8;
    const float* b2p = b2 + lane * 8;
    float4 ha = *(const float4*)hr;
    float4 hc = *(const float4*)(hr + 4);
    float hv[8] = {ha.x, ha.y, ha.z, ha.w, hc.x, hc.y, hc.z, hc.w};
    float v[8];
    #pragma unroll
    for (int k = 0; k < 8; k++) v[k] = hv[k] + acc[k] + cf * b2p[k];

    float* h2r = g_h2 + (size_t)row * Hdim + lane * 8;
    float4 o;
    o.x = v[0]; o.y = v[1]; o.z = v[2]; o.w = v[3];
    *(float4*)h2r = o;
    o.x = v[4]; o.y = v[5]; o.z = v[6]; o.w = v[7];
    *(float4*)(h2r + 4) = o;

    float s1 = 0.f, s2 = 0.f;
    #pragma unroll
    for (int k = 0; k < 8; k++) { s1 += v[k]; s2 += v[k]*v[k]; }
    #pragma unroll
    for (int ofs = 16; ofs > 0; ofs >>= 1) {
        s1 += __shfl_xor_sync(0xffffffffu, s1, ofs);
        s2 += __shfl_xor_sync(0xffffffffu, s2, ofs);
    }
    float mu = s1 * (1.0f / Hdim);
    float inv = rsqrtf(fmaxf(s2 * (1.0f / Hdim) - mu * mu, 0.f) + 1e-5f);
    const float* wp = w + lane * 8;
    const float* bp = b + lane * 8;
    float o0[4], o1[4];
    #pragma unroll
    for (int k = 0; k < 4; k++) o0[k] = (v[k]   - mu) * inv * wp[k]   + bp[k];
    #pragma unroll
    for (int k = 0; k < 4; k++) o1[k] = (v[4+k] - mu) * inv * wp[4+k] + bp[4+k];
    __half* yr = g_hu + (size_t)row * Hdim + lane * 8;
    st4h(yr, o0); st4h(yr + 4, o1);
}

// ============================================================================
// common tcgen05 helpers
// ============================================================================
__device__ __forceinline__ uint32_t smem_u32(const void* p) {
    uint32_t a;
    asm("{ .reg .u64 t; cvta.to.shared.u64 t, %1; cvt.u32.u64 %0, t; }" : "=r"(a) : "l"(p));
    return a;
}
__device__ __forceinline__ void mbar_wait(uint32_t mbar, uint32_t parity) {
    asm volatile(
        "{\n\t.reg .pred P1;\n\t"
        "W_%=:\n\t"
        "mbarrier.try_wait.parity.acquire.cta.shared::cta.b64 P1, [%0], %1, 0x989680;\n\t"
        "@P1 bra.uni D_%=;\n\t"
        "bra.uni W_%=;\n\t"
        "D_%=:\n\t}"
        :: "r"(mbar), "r"(parity) : "memory");
}

#if HAS_TC
__device__ __forceinline__ void mma_f16_ss(uint32_t d_tmem, uint64_t a_desc,
                                           uint64_t b_desc, uint32_t idesc, bool acc) {
    uint32_t en = acc ? 1u : 0u;
    asm volatile(
        "{\n\t.reg .pred p;\n\t"
        "setp.ne.u32 p, %5, 0;\n\t"
        "tcgen05.mma.cta_group::1.kind::f16 [%0], %1, %2, %3, {%4, %4, %4, %4}, p;\n\t"
        "}"
        :: "r"(d_tmem), "l"(a_desc), "l"(b_desc), "r"(idesc), "r"(0u), "r"(en)
        : "memory");
}
#define LDTM_X32(r, addr) \
    asm volatile( \
        "tcgen05.ld.sync.aligned.32x32b.x32.b32 " \
        "{%0, %1, %2, %3, %4, %5, %6, %7, " \
        " %8, %9, %10, %11, %12, %13, %14, %15, " \
        " %16, %17, %18, %19, %20, %21, %22, %23, " \
        " %24, %25, %26, %27, %28, %29, %30, %31}, [%32];" \
        : "=r"((r)[0]),  "=r"((r)[1]),  "=r"((r)[2]),  "=r"((r)[3]), \
          "=r"((r)[4]),  "=r"((r)[5]),  "=r"((r)[6]),  "=r"((r)[7]), \
          "=r"((r)[8]),  "=r"((r)[9]),  "=r"((r)[10]), "=r"((r)[11]), \
          "=r"((r)[12]), "=r"((r)[13]), "=r"((r)[14]), "=r"((r)[15]), \
          "=r"((r)[16]), "=r"((r)[17]), "=r"((r)[18]), "=r"((r)[19]), \
          "=r"((r)[20]), "=r"((r)[21]), "=r"((r)[22]), "=r"((r)[23]), \
          "=r"((r)[24]), "=r"((r)[25]), "=r"((r)[26]), "=r"((r)[27]), \
          "=r"((r)[28]), "=r"((r)[29]), "=r"((r)[30]), "=r"((r)[31]) \
        : "r"(addr))
#endif

static constexpr unsigned long long DESC_BASE =
    (2ull << 61) | (1ull << 46) | (64ull << 32) | (1ull << 16);
#define MMA_IDESC ((1u<<4) | (32u<<17) | (8u<<24))
#define SMEM_EDGE (1024 + 131072 + 128 + 2048)
#define SMEM_MLP  (1024 + 196608 + 64)
#define SMEM_PQ   (1024 + 131072 + 64)

// ============================================================================
// fused LN1 + PQ GEMM, B register-prefetched.
// ============================================================================
__global__ void __launch_bounds__(256, 1)
fused_ln_pq(const float* __restrict__ h,
            const float* __restrict__ lnw,
            const float* __restrict__ lnb,
            const __half* __restrict__ wabt,
            __half* __restrict__ PQ) {
    extern __shared__ char dyn[];
    int tid = threadIdx.x;
    int m0 = blockIdx.x * 128;
    int warp = tid >> 5, lane = tid & 31;

#if HAS_TC
    uint32_t u0 = smem_u32(dyn);
    uint32_t pad = (1024u - (u0 & 1023u)) & 1023u;
    char* base = dyn + pad;
    uint32_t ub = u0 + pad;

    uint32_t ctrl  = ub + 131072;
    uint32_t mbar0 = ctrl + 8;

    if (tid == 0) {
        asm volatile("mbarrier.init.shared.b64 [%0], 1;" :: "r"(mbar0)     : "memory");
        asm volatile("mbarrier.init.shared.b64 [%0], 1;" :: "r"(mbar0 + 8) : "memory");
    }
    if (warp == 0) {
        asm volatile("tcgen05.alloc.cta_group::1.sync.aligned.shared::cta.b32 [%0], %1;"
                     :: "r"(ctrl), "r"(512u) : "memory");
        asm volatile("tcgen05.relinquish_alloc_permit.cta_group::1.sync.aligned;");
    }
    __syncthreads();
    uint32_t tmem;
    asm volatile("ld.shared.b32 %0, [%1];" : "=r"(tmem) : "r"(ctrl));

    int rB = tid >> 3, fB = tid & 7;

    uint4 rbB[8];
    {
        const __half* src = wabt + (size_t)rB * Hdim + fB * 8;
        #pragma unroll
        for (int i = 0; i < 8; i++)
            rbB[i] = *(const uint4*)(src + (size_t)(i * 32) * Hdim);
    }

    {
        const float* wp = lnw + lane * 8;
        const float* bp = lnb + lane * 8;
        float wv[8], bv2[8];
        #pragma unroll
        for (int k = 0; k < 8; k += 4) {
            *(float4*)(wv+k)  = *(const float4*)(wp+k);
            *(float4*)(bv2+k) = *(const float4*)(bp+k);
        }
        for (int it = 0; it < 16; it++) {
            int rl = it * 8 + warp;
            const float* xr = h + (size_t)(m0 + rl) * Hdim + lane * 8;
            float4 a = *(const float4*)xr;
            float4 c = *(const float4*)(xr + 4);
            float v[8] = {a.x, a.y, a.z, a.w, c.x, c.y, c.z, c.w};
            float s1 = 0.f, s2 = 0.f;
            #pragma unroll
            for (int k = 0; k < 8; k++) { s1 += v[k]; s2 += v[k]*v[k]; }
            #pragma unroll
            for (int o = 16; o > 0; o >>= 1) {
                s1 += __shfl_xor_sync(0xffffffffu, s1, o);
                s2 += __shfl_xor_sync(0xffffffffu, s2, o);
            }
            float mu = s1 * (1.0f / Hdim);
            float inv = rsqrtf(fmaxf(s2 * (1.0f / Hdim) - mu * mu, 0.f) + 1e-5f);
            float o8[8];
            #pragma unroll
            for (int k = 0; k < 8; k++) o8[k] = (v[k] - mu) * inv * wv[k] + bv2[k];
            uint32_t sob = (uint32_t)(rl * 128 + (lane & 7) * 16);
            sob ^= (sob >> 3) & 0x70u;
            *(uint4*)(base + (lane >> 3) * 16384 + sob) = pack8h(o8);
        }
    }
    __syncthreads();

    int trow = (warp & 3) * 32 + lane;
    int colhalf = (warp >> 2) * 128;

    int cidx = 0;
    for (int p = 0; p < 4; p++) {
        uint32_t D = tmem + (uint32_t)((p & 1) * 256);
        for (int c = 0; c < 4; c++) {
            int buf = cidx & 1;
            if (cidx >= 2) mbar_wait(mbar0 + 8u*buf, (uint32_t)(((cidx-2) >> 1) & 1));
            char* sB = base + 65536 + buf * 32768;
            #pragma unroll
            for (int i2 = 0; i2 < 8; i2++) {
                int rr = rB + i2 * 32;
                uint32_t sob = (uint32_t)(rr * 128 + fB * 16);
                sob ^= (sob >> 3) & 0x70u;
                *(uint4*)(sB + sob) = rbB[i2];
            }
            if (cidx + 1 < 16) {
                int nidx = cidx + 1;
                int np = nidx >> 2, nc = nidx & 3;
                const __half* src = wabt + (size_t)(np*256 + rB) * Hdim + nc*64 + fB*8;
                #pragma unroll
                for (int i = 0; i < 8; i++)
                    rbB[i] = *(const uint4*)(src + (size_t)(i * 32) * Hdim);
            }
            asm volatile("fence.proxy.async.shared::cta;" ::: "memory");
            __syncthreads();
            if (tid == 0) {
                uint32_t aaddr = ub + (uint32_t)(c * 16384);
                uint32_t baddr = ub + (uint32_t)(65536 + buf * 32768);
                uint64_t adesc = DESC_BASE | (uint64_t)((aaddr >> 4) & 0x3FFFu);
                uint64_t bdesc = DESC_BASE | (uint64_t)((baddr >> 4) & 0x3FFFu);
                #pragma unroll
                for (int s = 0; s < 4; s++)
                    mma_f16_ss(D, adesc + 2u*s, bdesc + 2u*s, MMA_IDESC, !(c == 0 && s == 0));
                asm volatile(
                    "tcgen05.commit.cta_group::1.mbarrier::arrive::one.shared::cluster.b64 [%0];"
                    :: "r"(mbar0 + 8u*buf) : "memory");
            }
            cidx++;
        }
        mbar_wait(mbar0 + 8u*((cidx-1)&1), (uint32_t)(((cidx-1) >> 1) & 1));
        mbar_wait(mbar0 + 8u*((cidx-2)&1), (uint32_t)(((cidx-2) >> 1) & 1));
        asm volatile("tcgen05.fence::after_thread_sync;" ::: "memory");

        {
            int m = m0 + trow;
            #pragma unroll
            for (int cc2 = 0; cc2 < 4; cc2++) {
                int col = colhalf + cc2 * 32;
                uint32_t r[32];
                LDTM_X32(r, D + (uint32_t)col);
                asm volatile("tcgen05.wait::ld.sync.aligned;" ::: "memory");
                #pragma unroll
                for (int q = 0; q < 32; q += 4) {
                    float o[4] = {__uint_as_float(r[q]),   __uint_as_float(r[q+1]),
                                  __uint_as_float(r[q+2]), __uint_as_float(r[q+3])};
                    st4h(PQ + (size_t)m * HU + p*256 + col + q, o);
                }
            }
        }
    }
    __syncthreads();
    if (warp == 0) {
        asm volatile("tcgen05.dealloc.cta_group::1.sync.aligned.b32 %0, %1;"
                     :: "r"(tmem), "r"(512u));
    }

#else  // -------- SIMT fallback: LN -> g_hin, then naive GEMM ------------------
    float* As = (float*)dyn;
    float* Bs = (float*)(dyn + 8192);

    for (int it = 0; it < 16; it++) {
        int rl = it * 8 + warp;
        int row = m0 + rl;
        const float* xr = h + (size_t)row * Hdim + lane * 8;
        float4 a = *(const float4*)xr;
        float4 c = *(const float4*)(xr + 4);
        float v[8] = {a.x, a.y, a.z, a.w, c.x, c.y, c.z, c.w};
        float s1 = 0.f, s2 = 0.f;
        #pragma unroll
        for (int k = 0; k < 8; k++) { s1 += v[k]; s2 += v[k]*v[k]; }
        #pragma unroll
        for (int o = 16; o > 0; o >>= 1) {
            s1 += __shfl_xor_sync(0xffffffffu, s1, o);
            s2 += __shfl_xor_sync(0xffffffffu, s2, o);
        }
        float mu = s1 * (1.0f / Hdim);
        float inv = rsqrtf(fmaxf(s2 * (1.0f / Hdim) - mu * mu, 0.f) + 1e-5f);
        float o8[8];
        #pragma unroll
        for (int k = 0; k < 8; k++)
            o8[k] = (v[k] - mu) * inv * lnw[lane*8+k] + lnb[lane*8+k];
        st4h(g_hin + (size_t)row * Hdim + lane * 8, o8);
        st4h(g_hin + (size_t)row * Hdim + lane * 8 + 4, o8 + 4);
    }
    __syncthreads();

    int tr = tid >> 4, tc = tid & 15;
    int lrow = tid >> 1;
    int lk   = (tid & 1) * 8;
    for (int half = 0; half < 8; half++) {
        int n0h = half * 128;
        float acc[8][8] = {};
        for (int k0 = 0; k0 < Hdim; k0 += 16) {
            #pragma unroll
            for (int e = 0; e < 8; e++) {
                As[(lk+e)*128 + lrow] = __half2float(g_hin[(size_t)(m0 + lrow) * Hdim + k0 + lk + e]);
                Bs[(lk+e)*128 + lrow] = __half2float(wabt[(size_t)(n0h + lrow) * Hdim + k0 + lk + e]);
            }
            __syncthreads();
            #pragma unroll
            for (int k = 0; k < 16; k++) {
                float a[8], b[8];
                #pragma unroll
                for (int i2 = 0; i2 < 8; i2++) a[i2] = As[k*128 + tr*8 + i2];
                #pragma unroll
                for (int j2 = 0; j2 < 8; j2++) b[j2] = Bs[k*128 + tc*8 + j2];
                #pragma unroll
                for (int i2 = 0; i2 < 8; i2++)
                    #pragma unroll
                    for (int j2 = 0; j2 < 8; j2++)
                        acc[i2][j2] += a[i2] * b[j2];
            }
            __syncthreads();
        }
        int col0 = n0h + tc * 8;
        #pragma unroll
        for (int i2 = 0; i2 < 8; i2++) {
            int m = m0 + tr * 8 + i2;
            for (int j2 = 0; j2 < 8; j2++)
                PQ[(size_t)m * HU + col0 + j2] = __float2half(acc[i2][j2]);
        }
        __syncthreads();
    }
#endif
}

// ============================================================================
// fused edge-message kernel (register-prefetched gathers, h2 gelu)
// ============================================================================
__global__ void __launch_bounds__(256, 1)
edge_msg_kernel(const float* __restrict__ xyz,
                const float* __restrict__ w1,
                const float* __restrict__ b1,
                const __half* __restrict__ w2t) {
    extern __shared__ char dyn[];
    int tid = threadIdx.x;
    int m0 = blockIdx.x * 128;
    if (m0 >= g_E) return;

#if HAS_TC
    uint32_t u0 = smem_u32(dyn);
    uint32_t pad = (1024u - (u0 & 1023u)) & 1023u;
    char* base = dyn + pad;
    uint32_t ub = u0 + pad;

    uint32_t ctrl  = ub + 131072;
    uint32_t mbar0 = ctrl + 8;
    float* ef = (float*)(base + 131072 + 128);

    int wid = tid >> 5;
    int lane = tid & 31;

    if (tid == 0) {
        asm volatile("mbarrier.init.shared.b64 [%0], 1;" :: "r"(mbar0)     : "memory");
        asm volatile("mbarrier.init.shared.b64 [%0], 1;" :: "r"(mbar0 + 8) : "memory");
    }
    if (wid == 0) {
        asm volatile("tcgen05.alloc.cta_group::1.sync.aligned.shared::cta.b32 [%0], %1;"
                     :: "r"(ctrl), "r"(512u) : "memory");
        asm volatile("tcgen05.relinquish_alloc_permit.cta_group::1.sync.aligned;");
    }
    __syncthreads();
    uint32_t tmem;
    asm volatile("ld.shared.b32 %0, [%1];" : "=r"(tmem) : "r"(ctrl));

    if (tid < 128) {
        int m = m0 + tid;
        int i = g_ei[m], j = g_ej[m];
        float dx = xyz[3*j+0] - xyz[3*i+0];
        float dy = xyz[3*j+1] - xyz[3*i+1];
        float dz = xyz[3*j+2] - xyz[3*i+2];
        float d = fmaxf(sqrtf(dx*dx + dy*dy + dz*dz), 1e-6f);
        float inv = 1.0f / d;
        ef[tid*4+0] = dx*inv; ef[tid*4+1] = dy*inv; ef[tid*4+2] = dz*inv; ef[tid*4+3] = d;
    }
    __syncthreads();

    int r0 = tid >> 3, oct = tid & 7;
    uint32_t so = (uint32_t)(r0 * 128 + oct * 16);
    so ^= (so >> 3) & 0x70u;

    int ei4[4], ej4[4];
    float efr[4][4];
    #pragma unroll
    for (int it = 0; it < 4; it++) {
        int r = r0 + it * 32;
        ei4[it] = g_ei[m0 + r];
        ej4[it] = g_ej[m0 + r];
        efr[it][0] = ef[r*4+0]; efr[it][1] = ef[r*4+1];
        efr[it][2] = ef[r*4+2]; efr[it][3] = ef[r*4+3];
    }

    uint4 gp[16];
    uint4 rbB[8];
    const int NCH = 8;

    {
        int col = oct * 8;
        #pragma unroll
        for (int it = 0; it < 4; it++) {
            gp[it*4+0] = *(const uint4*)(g_PQ + (size_t)ei4[it]*HU + col);
            gp[it*4+1] = *(const uint4*)(g_PQ + (size_t)ei4[it]*HU + 512 + col);
            gp[it*4+2] = *(const uint4*)(g_PQ + (size_t)ej4[it]*HU + col);
            gp[it*4+3] = *(const uint4*)(g_PQ + (size_t)ej4[it]*HU + 512 + col);
        }
        #pragma unroll
        for (int i2 = 0; i2 < 8; i2++) {
            int idx = tid + i2 * 256;
            int rB = idx >> 3, fB = idx & 7;
            rbB[i2] = *(const uint4*)(w2t + (size_t)rB * H2 + fB * 8);
        }
    }

    for (int c = 0; c < NCH; c++) {
        int buf = c & 1;
        if (c >= 2) mbar_wait(mbar0 + 8u * buf, (uint32_t)(((c - 2) >> 1) & 1));
        char* sAf = base + buf * 65536;
        char* sAr = sAf + 16384;
        char* sB  = sAf + 32768;
        int col = (c << 6) + oct * 8;

        #pragma unroll
        for (int i2 = 0; i2 < 8; i2++) {
            int idx = tid + i2 * 256;
            int rB = idx >> 3, fB = idx & 7;
            uint32_t sob = (uint32_t)(rB * 128 + fB * 16);
            sob ^= (sob >> 3) & 0x70u;
            *(uint4*)(sB + sob) = rbB[i2];
        }

        float w0v[8], w1v[8], w2v[8], w3v[8], bbv[8];
        {
            const float* wr0 = w1 + (size_t)(2*Hdim + 0)*H2 + col;
            const float* wr1 = w1 + (size_t)(2*Hdim + 1)*H2 + col;
            const float* wr2 = w1 + (size_t)(2*Hdim + 2)*H2 + col;
            const float* wr3 = w1 + (size_t)(2*Hdim + 3)*H2 + col;
            const float* bbr = b1 + col;
            #pragma unroll
            for (int q = 0; q < 8; q += 4) {
                *(float4*)(w0v+q) = *(const float4*)(wr0+q);
                *(float4*)(w1v+q) = *(const float4*)(wr1+q);
                *(float4*)(w2v+q) = *(const float4*)(wr2+q);
                *(float4*)(w3v+q) = *(const float4*)(wr3+q);
                *(float4*)(bbv+q) = *(const float4*)(bbr+q);
            }
        }

        #pragma unroll
        for (int it = 0; it < 4; it++) {
            float pi[8], qi[8], pj[8], qj[8];
            cvt8h(gp[it*4+0], pi);
            cvt8h(gp[it*4+1], qi);
            cvt8h(gp[it*4+2], pj);
            cvt8h(gp[it*4+3], qj);
            float e0 = efr[it][0], e1 = efr[it][1], e2 = efr[it][2], e3 = efr[it][3];
            float sf[8], sr[8];
            #pragma unroll
            for (int q = 0; q < 8; q++) {
                float eu = e0*w0v[q] + e1*w1v[q] + e2*w2v[q];
                float ed = e3*w3v[q] + bbv[q];
                sf[q] = pi[q] + qj[q] + eu + ed;
                sr[q] = pj[q] + qi[q] - eu + ed;
            }
            *(uint4*)(sAf + so + (uint32_t)(it * 4096)) = gelu8_pack(sf);
            *(uint4*)(sAr + so + (uint32_t)(it * 4096)) = gelu8_pack(sr);
        }

        if (c + 1 < NCH) {
            int coln = ((c + 1) << 6) + oct * 8;
            #pragma unroll
            for (int it = 0; it < 4; it++) {
                gp[it*4+0] = *(const uint4*)(g_PQ + (size_t)ei4[it]*HU + coln);
                gp[it*4+1] = *(const uint4*)(g_PQ + (size_t)ei4[it]*HU + 512 + coln);
                gp[it*4+2] = *(const uint4*)(g_PQ + (size_t)ej4[it]*HU + coln);
                gp[it*4+3] = *(const uint4*)(g_PQ + (size_t)ej4[it]*HU + 512 + coln);
            }
            int k0n = (c + 1) << 6;
            #pragma unroll
            for (int i2 = 0; i2 < 8; i2++) {
                int idx = tid + i2 * 256;
                int rB = idx >> 3, fB = idx & 7;
                rbB[i2] = *(const uint4*)(w2t + (size_t)rB * H2 + k0n + fB * 8);
            }
        }

        asm volatile("fence.proxy.async.shared::cta;" ::: "memory");
        __syncthreads();

        if (tid == 0) {
            uint32_t afaddr = ub + (uint32_t)(buf * 65536);
            uint32_t araddr = afaddr + 16384u;
            uint32_t baddr  = afaddr + 32768u;
            uint64_t adescF = DESC_BASE | (uint64_t)((afaddr >> 4) & 0x3FFFu);
            uint64_t adescR = DESC_BASE | (uint64_t)((araddr >> 4) & 0x3FFFu);
            uint64_t bdesc  = DESC_BASE | (uint64_t)((baddr  >> 4) & 0x3FFFu);
            #pragma unroll
            for (int s = 0; s < 4; s++) {
                bool acc = !(c == 0 && s == 0);
                mma_f16_ss(tmem,        adescF + 2u*s, bdesc + 2u*s, MMA_IDESC, acc);
                mma_f16_ss(tmem + 256u, adescR + 2u*s, bdesc + 2u*s, MMA_IDESC, acc);
            }
            asm volatile(
                "tcgen05.commit.cta_group::1.mbarrier::arrive::one.shared::cluster.b64 [%0];"
                :: "r"(mbar0 + 8u * buf) : "memory");
        }
    }
    mbar_wait(mbar0 + 8u * ((NCH - 2) & 1), (uint32_t)(((NCH - 2) >> 1) & 1));
    mbar_wait(mbar0 + 8u * ((NCH - 1) & 1), (uint32_t)(((NCH - 1) >> 1) & 1));
    asm volatile("tcgen05.fence::after_thread_sync;" ::: "memory");

    {
        int dir = wid >> 2;
        int wd  = wid & 3;
        int trow = wd * 32 + lane;
        int m = m0 + trow;
        __half* M = dir ? g_Mr : g_Mf;
        uint32_t dbase = tmem + (uint32_t)(dir * 256);
        #pragma unroll
        for (int cc = 0; cc < 256; cc += 32) {
            uint32_t r[32];
            LDTM_X32(r, dbase + (uint32_t)cc);
            asm volatile("tcgen05.wait::ld.sync.aligned;" ::: "memory");
            #pragma unroll
            for (int q = 0; q < 32; q += 4) {
                float o[4] = {__uint_as_float(r[q]),   __uint_as_float(r[q+1]),
                              __uint_as_float(r[q+2]), __uint_as_float(r[q+3])};
                st4h(M + (size_t)m * Hdim + cc + q, o);
            }
        }
    }
    __syncthreads();
    if (wid == 0) {
        asm volatile("tcgen05.dealloc.cta_group::1.sync.aligned.b32 %0, %1;"
                     :: "r"(tmem), "r"(512u));
    }

#else  // -------- SIMT fallback ------------------------------------------------
    float* As = (float*)dyn;
    float* Bs = (float*)(dyn + 8192);
    float* ef = (float*)(dyn + 16384);

    if (tid < 128) {
        int m = m0 + tid;
        int i = g_ei[m], j = g_ej[m];
        float dx = xyz[3*j+0] - xyz[3*i+0];
        float dy = xyz[3*j+1] - xyz[3*i+1];
        float dz = xyz[3*j+2] - xyz[3*i+2];
        float d = fmaxf(sqrtf(dx*dx + dy*dy + dz*dz), 1e-6f);
        float inv = 1.0f / d;
        ef[tid*4+0] = dx*inv; ef[tid*4+1] = dy*inv; ef[tid*4+2] = dz*inv; ef[tid*4+3] = d;
    }
    __syncthreads();

    int tr = tid >> 4, tc = tid & 15;
    for (int dir = 0; dir < 2; dir++) {
        for (int half = 0; half < 2; half++) {
            int n0h = half * 128;
            float acc[8][8] = {};
            for (int k0 = 0; k0 < H2; k0 += 16) {
                #pragma unroll
                for (int e = 0; e < 8; e++) {
                    int idx = tid * 8 + e;
                    int kk = idx >> 7, rr2 = idx & 127;
                    int m = m0 + rr2;
                    int i = g_ei[m], j = g_ej[m];
                    int colk = k0 + kk;
                    float e0 = ef[rr2*4], e1 = ef[rr2*4+1], e2 = ef[rr2*4+2], e3 = ef[rr2*4+3];
                    float eu = e0*w1[(size_t)(2*Hdim+0)*H2+colk]
                             + e1*w1[(size_t)(2*Hdim+1)*H2+colk]
                             + e2*w1[(size_t)(2*Hdim+2)*H2+colk];
                    float ed = e3*w1[(size_t)(2*Hdim+3)*H2+colk] + b1[colk];
                    float pv, qv;
                    if (dir == 0) {
                        pv = __half2float(g_PQ[(size_t)i*HU + colk]);
                        qv = __half2float(g_PQ[(size_t)j*HU + 512 + colk]);
                        As[kk*128 + rr2] = gelu_fast(pv + qv + eu + ed);
                    } else {
                        pv = __half2float(g_PQ[(size_t)j*HU + colk]);
                        qv = __half2float(g_PQ[(size_t)i*HU + 512 + colk]);
                        As[kk*128 + rr2] = gelu_fast(pv + qv - eu + ed);
                    }
                    Bs[kk*128 + rr2] = __half2float(w2t[(size_t)(n0h + rr2) * H2 + colk]);
                }
                __syncthreads();
                #pragma unroll
                for (int k = 0; k < 16; k++) {
                    float a[8], b[8];
                    #pragma unroll
                    for (int i2 = 0; i2 < 8; i2++) a[i2] = As[k*128 + tr*8 + i2];
                    #pragma unroll
                    for (int j2 = 0; j2 < 8; j2++) b[j2] = Bs[k*128 + tc*8 + j2];
                    #pragma unroll
                    for (int i2 = 0; i2 < 8; i2++)
                        #pragma unroll
                        for (int j2 = 0; j2 < 8; j2++)
                            acc[i2][j2] += a[i2] * b[j2];
                }
                __syncthreads();
            }
            __half* M = dir ? g_Mr : g_Mf;
            int col0 = n0h + tc * 8;
            #pragma unroll
            for (int i2 = 0; i2 < 8; i2++) {
                int m = m0 + tr * 8 + i2;
                for (int j2 = 0; j2 < 8; j2++)
                    M[(size_t)m * Hdim + col0 + j2] = __float2half(acc[i2][j2]);
            }
            __syncthreads();
        }
    }
#endif
}

// ============================================================================
// fused update-MLP, B register-prefetched, h2 gelu epilogue.
// ============================================================================
#if HAS_TC
__device__ __forceinline__ void mlp_prefetch_B(int idx, int rB, int fB,
                                               const __half* __restrict__ u1t,
                                               const __half* __restrict__ u2t,
                                               uint4* rb) {
    int p = idx >> 3, sub = idx & 7;
    if (sub < 4) {
        const __half* src = u1t + (size_t)(p*256 + rB) * Hdim + sub*64 + fB*8;
        #pragma unroll
        for (int i = 0; i < 8; i++)
            rb[i] = *(const uint4*)(src + (size_t)(i * 32) * Hdim);
    } else {
        const __half* src = u2t + (size_t)rB * HU + p*256 + (sub-4)*64 + fB*8;
        #pragma unroll
        for (int i = 0; i < 8; i++)
            rb[i] = *(const uint4*)(src + (size_t)(i * 32) * HU);
    }
}
#endif

__global__ void __launch_bounds__(256, 1)
fused_mlp_kernel(const __half* __restrict__ u1t,
                 const __half* __restrict__ u2t,
                 const float* __restrict__ bu1,
                 const float* __restrict__ bu2,
                 float* __restrict__ out) {
    extern __shared__ char dyn[];
    int tid = threadIdx.x;
    int m0 = blockIdx.x * 128;

#if HAS_TC
    uint32_t u0 = smem_u32(dyn);
    uint32_t pad = (1024u - (u0 & 1023u)) & 1023u;
    char* base = dyn + pad;
    uint32_t ub = u0 + pad;

    uint32_t ctrl  = ub + 196608;
    uint32_t mbar0 = ctrl + 8;

    int wid = tid >> 5;
    int lane = tid & 31;

    if (tid == 0) {
        asm volatile("mbarrier.init.shared.b64 [%0], 1;" :: "r"(mbar0)     : "memory");
        asm volatile("mbarrier.init.shared.b64 [%0], 1;" :: "r"(mbar0 + 8) : "memory");
    }
    if (wid == 0) {
        asm volatile("tcgen05.alloc.cta_group::1.sync.aligned.shared::cta.b32 [%0], %1;"
                     :: "r"(ctrl), "r"(512u) : "memory");
        asm volatile("tcgen05.relinquish_alloc_permit.cta_group::1.sync.aligned;");
    }
    __syncthreads();
    uint32_t tmem;
    asm volatile("ld.shared.b32 %0, [%1];" : "=r"(tmem) : "r"(ctrl));

    int rB = tid >> 3, fB = tid & 7;

    uint4 rbB[8];
    mlp_prefetch_B(0, rB, fB, u1t, u2t, rbB);

    #pragma unroll
    for (int i2 = 0; i2 < 16; i2++) {
        int g = tid + i2 * 256;
        int r = g >> 5;
        int f = g & 31;
        uint4 v = *(const uint4*)(g_hu + (size_t)(m0 + r) * Hdim + f * 8);
        uint32_t sob = (uint32_t)(r * 128 + (f & 7) * 16);
        sob ^= (sob >> 3) & 0x70u;
        *(uint4*)(base + (f >> 3) * 16384 + sob) = v;
    }

    int trow = (wid & 3) * 32 + lane;
    int colhalf = (wid >> 2) * 128;

    uint32_t D2 = tmem;
    uint32_t D1 = tmem + 256u;

    int cidx = 0;
    for (int p = 0; p < 4; p++) {
        for (int c = 0; c < 4; c++) {
            int buf = cidx & 1;
            if (cidx >= 2) mbar_wait(mbar0 + 8u*buf, (uint32_t)(((cidx-2) >> 1) & 1));
            char* sB = base + 131072 + buf * 32768;
            #pragma unroll
            for (int i2 = 0; i2 < 8; i2++) {
                int rr = rB + i2 * 32;
                uint32_t sob = (uint32_t)(rr * 128 + fB * 16);
                sob ^= (sob >> 3) & 0x70u;
                *(uint4*)(sB + sob) = rbB[i2];
            }
            if (cidx + 1 < 32)
                mlp_prefetch_B(cidx + 1, rB, fB, u1t, u2t, rbB);
            asm volatile("fence.proxy.async.shared::cta;" ::: "memory");
            __syncthreads();
            if (tid == 0) {
                uint32_t aaddr = ub + (uint32_t)(c * 16384);
                uint32_t baddr = ub + (uint32_t)(131072 + buf * 32768);
                uint64_t adesc = DESC_BASE | (uint64_t)((aaddr >> 4) & 0x3FFFu);
                uint64_t bdesc = DESC_BASE | (uint64_t)((baddr >> 4) & 0x3FFFu);
                #pragma unroll
                for (int s = 0; s < 4; s++)
                    mma_f16_ss(D1, adesc + 2u*s, bdesc + 2u*s, MMA_IDESC, !(c == 0 && s == 0));
                asm volatile(
                    "tcgen05.commit.cta_group::1.mbarrier::arrive::one.shared::cluster.b64 [%0];"
                    :: "r"(mbar0 + 8u*buf) : "memory");
            }
            cidx++;
        }
        mbar_wait(mbar0 + 8u*((cidx-1)&1), (uint32_t)(((cidx-1) >> 1) & 1));
        mbar_wait(mbar0 + 8u*((cidx-2)&1), (uint32_t)(((cidx-2) >> 1) & 1));
        asm volatile("tcgen05.fence::after_thread_sync;" ::: "memory");

        #pragma unroll
        for (int cc2 = 0; cc2 < 4; cc2++) {
            int col = colhalf + cc2 * 32;
            uint32_t r[32];
            LDTM_X32(r, D1 + (uint32_t)col);
            asm volatile("tcgen05.wait::ld.sync.aligned;" ::: "memory");
            #pragma unroll
            for (int q = 0; q < 32; q += 8) {
                int ck = col + q;
                float s[8];
                #pragma unroll
                for (int e = 0; e < 8; e++)
                    s[e] = __uint_as_float(r[q+e]) + __ldg(&bu1[p*256 + ck + e]);
                uint32_t sob = (uint32_t)(trow * 128 + ((ck >> 3) & 7) * 16);
                sob ^= (sob >> 3) & 0x70u;
                *(uint4*)(base + 65536 + (ck >> 6) * 16384 + sob) = gelu8_pack(s);
            }
        }

        for (int c = 0; c < 4; c++) {
            int buf = cidx & 1;
            mbar_wait(mbar0 + 8u*buf, (uint32_t)(((cidx-2) >> 1) & 1));
            char* sB = base + 131072 + buf * 32768;
            #pragma unroll
            for (int i2 = 0; i2 < 8; i2++) {
                int rr = rB + i2 * 32;
                uint32_t sob = (uint32_t)(rr * 128 + fB * 16);
                sob ^= (sob >> 3) & 0x70u;
                *(uint4*)(sB + sob) = rbB[i2];
            }
            if (cidx + 1 < 32)
                mlp_prefetch_B(cidx + 1, rB, fB, u1t, u2t, rbB);
            asm volatile("fence.proxy.async.shared::cta;" ::: "memory");
            __syncthreads();
            if (tid == 0) {
                uint32_t aaddr = ub + (uint32_t)(65536 + c * 16384);
                uint32_t baddr = ub + (uint32_t)(131072 + buf * 32768);
                uint64_t adesc = DESC_BASE | (uint64_t)((aaddr >> 4) & 0x3FFFu);
                uint64_t bdesc = DESC_BASE | (uint64_t)((baddr >> 4) & 0x3FFFu);
                #pragma unroll
                for (int s = 0; s < 4; s++)
                    mma_f16_ss(D2, adesc + 2u*s, bdesc + 2u*s, MMA_IDESC,
                               !(p == 0 && c == 0 && s == 0));
                asm volatile(
                    "tcgen05.commit.cta_group::1.mbarrier::arrive::one.shared::cluster.b64 [%0];"
                    :: "r"(mbar0 + 8u*buf) : "memory");
            }
            cidx++;
        }
    }
    mbar_wait(mbar0 + 8u*((cidx-1)&1), (uint32_t)(((cidx-1) >> 1) & 1));
    mbar_wait(mbar0 + 8u*((cidx-2)&1), (uint32_t)(((cidx-2) >> 1) & 1));
    asm volatile("tcgen05.fence::after_thread_sync;" ::: "memory");

    {
        int m = m0 + trow;
        float vf = g_valid[m] ? 1.0f : 0.0f;
        #pragma unroll
        for (int cc2 = 0; cc2 < 4; cc2++) {
            int col = colhalf + cc2 * 32;
            uint32_t r[32];
            LDTM_X32(r, D2 + (uint32_t)col);
            asm volatile("tcgen05.wait::ld.sync.aligned;" ::: "memory");
            const float* a2 = g_h2 + (size_t)m * Hdim + col;
            #pragma unroll
            for (int q = 0; q < 32; q += 4) {
                float4 av = *(const float4*)(a2 + q);
                float4 o;
                o.x = (av.x + __uint_as_float(r[q])   + __ldg(&bu2[col+q]))   * vf;
                o.y = (av.y + __uint_as_float(r[q+1]) + __ldg(&bu2[col+q+1])) * vf;
                o.z = (av.z + __uint_as_float(r[q+2]) + __ldg(&bu2[col+q+2])) * vf;
                o.w = (av.w + __uint_as_float(r[q+3]) + __ldg(&bu2[col+q+3])) * vf;
                *(float4*)(out + (size_t)m * Hdim + col + q) = o;
            }
        }
    }
    __syncthreads();
    if (wid == 0) {
        asm volatile("tcgen05.dealloc.cta_group::1.sync.aligned.b32 %0, %1;"
                     :: "r"(tmem), "r"(512u));
    }

#else  // -------- SIMT fallback: two naive GEMMs staged via g_T1 --------------
    float* As = (float*)dyn;
    float* Bs = (float*)(dyn + 8192);
    int tr = tid >> 4, tc = tid & 15;
    int lrow = tid >> 1;
    int lk   = (tid & 1) * 8;

    for (int half = 0; half < 8; half++) {
        int n0h = half * 128;
        float acc[8][8] = {};
        for (int k0 = 0; k0 < Hdim; k0 += 16) {
            #pragma unroll
            for (int e = 0; e < 8; e++) {
                As[(lk+e)*128 + lrow] = __half2float(g_hu[(size_t)(m0 + lrow) * Hdim + k0 + lk + e]);
                Bs[(lk+e)*128 + lrow] = __half2float(u1t[(size_t)(n0h + lrow) * Hdim + k0 + lk + e]);
            }
            __syncthreads();
            #pragma unroll
            for (int k = 0; k < 16; k++) {
                float a[8], b[8];
                #pragma unroll
                for (int i2 = 0; i2 < 8; i2++) a[i2] = As[k*128 + tr*8 + i2];
                #pragma unroll
                for (int j2 = 0; j2 < 8; j2++) b[j2] = Bs[k*128 + tc*8 + j2];
                #pragma unroll
                for (int i2 = 0; i2 < 8; i2++)
                    #pragma unroll
                    for (int j2 = 0; j2 < 8; j2++)
                        acc[i2][j2] += a[i2] * b[j2];
            }
            __syncthreads();
        }
        int col0 = n0h + tc * 8;
        #pragma unroll
        for (int i2 = 0; i2 < 8; i2++) {
            int m = m0 + tr * 8 + i2;
            for (int j2 = 0; j2 < 8; j2++)
                g_T1[(size_t)m * HU + col0 + j2] =
                    __float2half(gelu_fast(acc[i2][j2] + bu1[col0 + j2]));
        }
        __syncthreads();
    }

    for (int half = 0; half < 2; half++) {
        int n0h = half * 128;
        float acc[8][8] = {};
        for (int k0 = 0; k0 < HU; k0 += 16) {
            #pragma unroll
            for (int e = 0; e < 8; e++) {
                As[(lk+e)*128 + lrow] = __half2float(g_T1[(size_t)(m0 + lrow) * HU + k0 + lk + e]);
                Bs[(lk+e)*128 + lrow] = __half2float(u2t[(size_t)(n0h + lrow) * HU + k0 + lk + e]);
            }
            __syncthreads();
            #pragma unroll
            for (int k = 0; k < 16; k++) {
                float a[8], b[8];
                #pragma unroll
                for (int i2 = 0; i2 < 8; i2++) a[i2] = As[k*128 + tr*8 + i2];
                #pragma unroll
                for (int j2 = 0; j2 < 8; j2++) b[j2] = Bs[k*128 + tc*8 + j2];
                #pragma unroll
                for (int i2 = 0; i2 < 8; i2++)
                    #pragma unroll
                    for (int j2 = 0; j2 < 8; j2++)
                        acc[i2][j2] += a[i2] * b[j2];
            }
            __syncthreads();
        }
        int col0 = n0h + tc * 8;
        #pragma unroll
        for (int i2 = 0; i2 < 8; i2++) {
            int m = m0 + tr * 8 + i2;
            float vf = g_valid[m] ? 1.0f : 0.0f;
            for (int j2 = 0; j2 < 8; j2++)
                out[(size_t)m * Hdim + col0 + j2] =
                    (g_h2[(size_t)m * Hdim + col0 + j2] + acc[i2][j2] + bu2[col0 + j2]) * vf;
        }
        __syncthreads();
    }
#endif
}

// ---------------- launch -----------------------------------------------------
extern "C" void kernel_launch(void* const* d_in, const int* in_sizes, int n_in,
                              void* d_out, int out_size) {
    const float*         h      = (const float*)d_in[0];
    const float*         xyz    = (const float*)d_in[1];
    const unsigned char* validb = (const unsigned char*)d_in[2];
    const float*         ln_n_w = (const float*)d_in[3];
    const float*         ln_n_b = (const float*)d_in[4];
    const float*         w1     = (const float*)d_in[5];
    const float*         b1     = (const float*)d_in[6];
    const float*         w2     = (const float*)d_in[7];
    const float*         b2     = (const float*)d_in[8];
    const float*         ln_u_w = (const float*)d_in[9];
    const float*         ln_u_b = (const float*)d_in[10];
    const float*         u1     = (const float*)d_in[11];
    const float*         bu1    = (const float*)d_in[12];
    const float*         u2     = (const float*)d_in[13];
    const float*         bu2    = (const float*)d_in[14];
    float* out = (float*)d_out;

    __half *pPQ, *pWabt, *pW2t, *pU1t, *pU2t;
    cudaGetSymbolAddress((void**)&pPQ,  g_PQ);
    cudaGetSymbolAddress((void**)&pWabt, g_wabt);
    cudaGetSymbolAddress((void**)&pW2t,  g_w2t);
    cudaGetSymbolAddress((void**)&pU1t,  g_u1t);
    cudaGetSymbolAddress((void**)&pU2t,  g_u2t);

    cudaFuncSetAttribute(fused_ln_pq, cudaFuncAttributeMaxDynamicSharedMemorySize, SMEM_PQ);
    cudaFuncSetAttribute(edge_msg_kernel, cudaFuncAttributeMaxDynamicSharedMemorySize, SMEM_EDGE);
    cudaFuncSetAttribute(fused_mlp_kernel, cudaFuncAttributeMaxDynamicSharedMemorySize, SMEM_MLP);

    detect_vmode_kernel<<<1, 256>>>(validb);
    conv_clear_kernel<<<4*NC/256, 256>>>(validb);
    transpose_all_kernel<<<917504/256, 256>>>(w1, w2, u1, u2);
    count_kernel<<<NB, 256>>>();

    fused_ln_pq<<<NC/128, 256, SMEM_PQ>>>(h, ln_n_w, ln_n_b, pWabt, pPQ);

    scan_kernel<<<1, 256>>>();
    scatter_kernel<<<NB, 256>>>();

    edge_msg_kernel<<<MAXE/128, 256, SMEM_EDGE>>>(xyz, w1, b1, pW2t);

    gather_ln_kernel<<<NC/8, 256>>>(h, b2, ln_u_w, ln_u_b);

    fused_mlp_kernel<<<NC/128, 256, SMEM_MLP>>>(pU1t, pU2t, bu1, bu2, out);
    (void)in_sizes; (void)n_in; (void)out_size;
}